// round 1
// baseline (speedup 1.0000x reference)
#include <cuda_runtime.h>
#include <math.h>
#include <float.h>

#define Nn 2048
#define Dd 128
#define Vv 3
#define Hh 4
#define VDd 512
#define Kk 10
#define VH (Vv*Hh)
#define LRELU_ALPHA 0.2f

// ---------------- scratch (no allocations allowed) ----------------
__device__ float g_sq[Nn];
__device__ float g_dist[(size_t)Nn * Nn];
__device__ int   g_knn[Nn * Kk];
__device__ float g_Wh[(size_t)VH * Nn * Dd];
__device__ float g_f1[VH * Nn];
__device__ float g_f2[VH * Nn];
__device__ float g_meta[(size_t)Nn * VH * Dd];
__device__ float g_logits[Nn * Dd];

// ---------------- squared norms ----------------
__global__ void sq_kernel(const float* __restrict__ x) {
    int w = (blockIdx.x * blockDim.x + threadIdx.x) >> 5;
    int lane = threadIdx.x & 31;
    if (w >= Nn) return;
    float4 r = *(const float4*)(x + (size_t)w * Dd + lane * 4);
    float s = r.x * r.x + r.y * r.y + r.z * r.z + r.w * r.w;
    #pragma unroll
    for (int o = 16; o; o >>= 1) s += __shfl_xor_sync(0xffffffffu, s, o);
    if (lane == 0) g_sq[w] = s;
}

// ---------------- generic SGEMM  C = A(MxK) * B(KxN), 64x64x16 tiles ----------------
// MODE: 0 = plain, 1 = +bias[col], 2 = elu(+bias[col]), 3 = dist (sq[row]+sq[col]-2*acc)
// TRANSB: B stored row-major [N,K] (C[i][j] = dot(A_i, B_j))
template <int MODE, bool TRANSB>
__global__ __launch_bounds__(256) void sgemm_kernel(
    const float* __restrict__ A, const float* __restrict__ B, float* __restrict__ C,
    const float* __restrict__ bias,
    int M, int Ndim, int Kdim,
    long strideB, long strideC, long strideBias)
{
    const int BM = 64, BN = 64, BK = 16;
    __shared__ float As[BK][BM];
    __shared__ float Bs[BK][BN];

    const float* Bb = B + (size_t)blockIdx.z * strideB;
    float* Cb = C + (size_t)blockIdx.z * strideC;
    const float* biasb = bias ? bias + (size_t)blockIdx.z * strideBias : nullptr;

    int bm = blockIdx.y * BM;
    int bn = blockIdx.x * BN;
    int tid = threadIdx.x;
    int tx = tid & 15, ty = tid >> 4;

    float acc[4][4];
    #pragma unroll
    for (int u = 0; u < 4; u++)
        #pragma unroll
        for (int w = 0; w < 4; w++) acc[u][w] = 0.f;

    for (int k0 = 0; k0 < Kdim; k0 += BK) {
        {   // load A tile (transposed into smem)
            int idx = tid * 4;
            int m = idx / BK, k = idx % BK;
            float4 v = *(const float4*)(A + (size_t)(bm + m) * Kdim + k0 + k);
            As[k + 0][m] = v.x; As[k + 1][m] = v.y; As[k + 2][m] = v.z; As[k + 3][m] = v.w;
        }
        if (TRANSB) {
            int idx = tid * 4;
            int n = idx / BK, k = idx % BK;
            float4 v = *(const float4*)(Bb + (size_t)(bn + n) * Kdim + k0 + k);
            Bs[k + 0][n] = v.x; Bs[k + 1][n] = v.y; Bs[k + 2][n] = v.z; Bs[k + 3][n] = v.w;
        } else {
            int idx = tid * 4;
            int k = idx / BN, n = idx % BN;
            float4 v = *(const float4*)(Bb + (size_t)(k0 + k) * Ndim + bn + n);
            *(float4*)&Bs[k][n] = v;
        }
        __syncthreads();
        #pragma unroll
        for (int k = 0; k < BK; k++) {
            float a[4], b[4];
            #pragma unroll
            for (int u = 0; u < 4; u++) a[u] = As[k][ty * 4 + u];
            #pragma unroll
            for (int w = 0; w < 4; w++) b[w] = Bs[k][tx * 4 + w];
            #pragma unroll
            for (int u = 0; u < 4; u++)
                #pragma unroll
                for (int w = 0; w < 4; w++) acc[u][w] = fmaf(a[u], b[w], acc[u][w]);
        }
        __syncthreads();
    }

    #pragma unroll
    for (int u = 0; u < 4; u++) {
        int row = bm + ty * 4 + u;
        #pragma unroll
        for (int w = 0; w < 4; w++) {
            int col = bn + tx * 4 + w;
            float val = acc[u][w];
            if (MODE == 1) val += biasb[col];
            else if (MODE == 2) {
                val += biasb[col];
                val = (val > 0.f) ? val : expm1f(val);
            } else if (MODE == 3) {
                val = bias[row] + bias[col] - 2.f * val;
            }
            Cb[(size_t)row * Ndim + col] = val;
        }
    }
}

// ---------------- per-row top-K (smallest distance, lowest-index tie break) ----------------
__global__ __launch_bounds__(256) void knn_kernel() {
    __shared__ float sd[Nn];
    __shared__ float sval[256];
    __shared__ int   sidx[256];
    int row = blockIdx.x;
    int tid = threadIdx.x;

    const float* dr = g_dist + (size_t)row * Nn;
    #pragma unroll
    for (int t = 0; t < Nn / 256 / 4; t++) {
        int j = (tid + t * 256) * 4;
        *(float4*)&sd[j] = *(const float4*)(dr + j);
    }
    __syncthreads();

    for (int r = 0; r < Kk; r++) {
        float bv = FLT_MAX; int bi = Nn;
        #pragma unroll
        for (int t = 0; t < Nn / 256; t++) {
            int j = tid + t * 256;
            float v = sd[j];
            if (v < bv || (v == bv && j < bi)) { bv = v; bi = j; }
        }
        sval[tid] = bv; sidx[tid] = bi;
        __syncthreads();
        for (int s = 128; s > 0; s >>= 1) {
            if (tid < s) {
                float v = sval[tid + s]; int j2 = sidx[tid + s];
                if (v < sval[tid] || (v == sval[tid] && j2 < sidx[tid])) {
                    sval[tid] = v; sidx[tid] = j2;
                }
            }
            __syncthreads();
        }
        if (tid == 0) {
            g_knn[row * Kk + r] = sidx[0];
            sd[sidx[0]] = FLT_MAX;
        }
        __syncthreads();
    }
}

// ---------------- f1/f2: per-(v,h,n) dot of Wh row with attention vectors ----------------
__global__ void f12_kernel(const float* __restrict__ gat_a) {
    int w = (blockIdx.x * blockDim.x + threadIdx.x) >> 5;
    int lane = threadIdx.x & 31;
    if (w >= VH * Nn) return;
    int vh = w / Nn;
    const float* row = g_Wh + (size_t)w * Dd;
    const float* a1 = gat_a + (size_t)vh * 2 * Dd;
    const float* a2 = a1 + Dd;
    float4 r = *(const float4*)(row + lane * 4);
    float4 v1 = *(const float4*)(a1 + lane * 4);
    float4 v2 = *(const float4*)(a2 + lane * 4);
    float s1 = r.x * v1.x + r.y * v1.y + r.z * v1.z + r.w * v1.w;
    float s2 = r.x * v2.x + r.y * v2.y + r.z * v2.z + r.w * v2.w;
    #pragma unroll
    for (int o = 16; o; o >>= 1) {
        s1 += __shfl_xor_sync(0xffffffffu, s1, o);
        s2 += __shfl_xor_sync(0xffffffffu, s2, o);
    }
    if (lane == 0) { g_f1[w] = s1; g_f2[w] = s2; }
}

// ---------------- sparse GAT attention: one warp per (v,h,node) ----------------
__global__ void attn_kernel(const float* __restrict__ fm) {
    int w = (blockIdx.x * blockDim.x + threadIdx.x) >> 5;
    int lane = threadIdx.x & 31;
    if (w >= VH * Nn) return;
    int i = w % Nn;
    int vh = w / Nn;
    int v = vh / Hh;

    int nb = -1;
    bool valid = false;
    if (lane < Kk) {
        nb = g_knn[i * Kk + lane];
        valid = (nb == i) || (fm[(size_t)i * Vv + v] > 0.f && fm[(size_t)nb * Vv + v] > 0.f);
    }
    // ensure self-edge present (eye term in adj)
    unsigned hasSelf = __ballot_sync(0xffffffffu, lane < Kk && nb == i);
    if (hasSelf == 0 && lane == Kk) { nb = i; valid = true; }

    float e = -FLT_MAX;
    if (valid) {
        float x = g_f1[vh * Nn + i] + g_f2[vh * Nn + nb];
        e = (x >= 0.f) ? x : LRELU_ALPHA * x;
    }
    float m = e;
    #pragma unroll
    for (int o = 16; o; o >>= 1) m = fmaxf(m, __shfl_xor_sync(0xffffffffu, m, o));
    float wt = valid ? expf(e - m) : 0.f;
    float s = wt;
    #pragma unroll
    for (int o = 16; o; o >>= 1) s += __shfl_xor_sync(0xffffffffu, s, o);
    float att = wt / s;

    const float* base = g_Wh + (size_t)vh * Nn * Dd;
    float4 acc = make_float4(0.f, 0.f, 0.f, 0.f);
    #pragma unroll
    for (int j = 0; j <= Kk; j++) {
        float a = __shfl_sync(0xffffffffu, att, j);
        int nj = __shfl_sync(0xffffffffu, nb, j);
        if (a != 0.f) {
            float4 wv = *(const float4*)(base + (size_t)nj * Dd + lane * 4);
            acc.x = fmaf(a, wv.x, acc.x);
            acc.y = fmaf(a, wv.y, acc.y);
            acc.z = fmaf(a, wv.z, acc.z);
            acc.w = fmaf(a, wv.w, acc.w);
        }
    }
    // meta layout: [N, V*H*D] with (v,h,d) fastest-order matching hp.transpose(2,0,1,3)
    float* dst = g_meta + (size_t)i * (VH * Dd) + (size_t)vh * Dd + lane * 4;
    *(float4*)dst = acc;
}

// ---------------- row log_softmax over D=128 ----------------
__global__ __launch_bounds__(128) void logsoftmax_kernel(float* __restrict__ outp) {
    __shared__ float red[128];
    int row = blockIdx.x;
    int t = threadIdx.x;
    float x = g_logits[row * Dd + t];
    red[t] = x;
    __syncthreads();
    for (int s = 64; s > 0; s >>= 1) {
        if (t < s) red[t] = fmaxf(red[t], red[t + s]);
        __syncthreads();
    }
    float m = red[0];
    __syncthreads();
    red[t] = expf(x - m);
    __syncthreads();
    for (int s = 64; s > 0; s >>= 1) {
        if (t < s) red[t] += red[t + s];
        __syncthreads();
    }
    float lse = m + logf(red[0]);
    outp[row * Dd + t] = x - lse;
}

// ---------------- launch ----------------
extern "C" void kernel_launch(void* const* d_in, const int* in_sizes, int n_in,
                              void* d_out, int out_size) {
    const float* fm     = (const float*)d_in[0];
    const float* latent = (const float*)d_in[1];
    const float* enc_W  = (const float*)d_in[2];
    const float* enc_b  = (const float*)d_in[3];
    const float* gat_W  = (const float*)d_in[4];
    const float* gat_a  = (const float*)d_in[5];
    const float* agg_W  = (const float*)d_in[6];
    const float* agg_b  = (const float*)d_in[7];
    const float* cls_W  = (const float*)d_in[8];
    const float* cls_b  = (const float*)d_in[9];

    float* out  = (float*)d_out;
    float* rec  = out;                                   // [V,N,VD]
    float* outp = out + (size_t)Vv * Nn * VDd;           // [N,D]
    float* sem  = outp + (size_t)Nn * Dd;                // [N,D]

    float *p_sq, *p_dist, *p_Wh, *p_meta, *p_logits;
    cudaGetSymbolAddress((void**)&p_sq, g_sq);
    cudaGetSymbolAddress((void**)&p_dist, g_dist);
    cudaGetSymbolAddress((void**)&p_Wh, g_Wh);
    cudaGetSymbolAddress((void**)&p_meta, g_meta);
    cudaGetSymbolAddress((void**)&p_logits, g_logits);

    // 1. squared norms
    sq_kernel<<<Nn / 8, 256>>>(latent);
    // 2. pairwise distances: dist = sq_i + sq_j - 2 * latent @ latent^T
    sgemm_kernel<3, true><<<dim3(Nn / 64, Nn / 64, 1), 256>>>(
        latent, latent, p_dist, p_sq, Nn, Nn, Dd, 0, 0, 0);
    // 3. top-K neighbors per row
    knn_kernel<<<Nn, 256>>>();
    // 4. Wh[v,h] = latent @ gat_W[v,h]   (12 batched GEMMs)
    sgemm_kernel<0, false><<<dim3(Dd / 64, Nn / 64, VH), 256>>>(
        latent, gat_W, p_Wh, nullptr, Nn, Dd, Dd,
        (long)Dd * Dd, (long)Nn * Dd, 0);
    // 5. f1/f2 attention projections
    f12_kernel<<<VH * Nn / 8, 256>>>(gat_a);
    // 6. sparse masked softmax attention + gather -> meta [N, V*H*D]
    attn_kernel<<<VH * Nn / 8, 256>>>(fm);
    // 7. rec[v] = latent @ enc_W[v] + enc_b[v]  (3 batched GEMMs, direct to output)
    sgemm_kernel<1, false><<<dim3(VDd / 64, Nn / 64, Vv), 256>>>(
        latent, enc_W, rec, enc_b, Nn, VDd, Dd,
        (long)Dd * VDd, (long)Nn * VDd, (long)VDd);
    // 8. semantic = meta @ agg_W + agg_b (direct to output)
    sgemm_kernel<1, false><<<dim3(Dd / 64, Nn / 64, 1), 256>>>(
        p_meta, agg_W, sem, agg_b, Nn, Dd, VH * Dd, 0, 0, 0);
    // 9. logits = elu(semantic @ cls_W + cls_b)
    sgemm_kernel<2, false><<<dim3(Dd / 64, Nn / 64, 1), 256>>>(
        sem, cls_W, p_logits, cls_b, Nn, Dd, Dd, 0, 0, 0);
    // 10. output = log_softmax(logits)
    logsoftmax_kernel<<<Nn, 128>>>(outp);
}

// round 2
// speedup vs baseline: 1.4936x; 1.4936x over previous
#include <cuda_runtime.h>
#include <math.h>
#include <float.h>

#define Nn 2048
#define Dd 128
#define Vv 3
#define Hh 4
#define VDd 512
#define Kk 10
#define VH (Vv*Hh)
#define LRELU_ALPHA 0.2f
#define AGG_SPLITS 8
#define AGG_KCHUNK ((VH*Dd)/AGG_SPLITS)   // 192

// ---------------- scratch (no allocations allowed) ----------------
__device__ float g_sq[Nn];
__device__ float g_dist[(size_t)Nn * Nn];
__device__ int   g_knn[Nn * Kk];
__device__ float g_Wh[(size_t)VH * Nn * Dd];
__device__ float g_f1[VH * Nn];
__device__ float g_f2[VH * Nn];
__device__ float g_meta[(size_t)Nn * VH * Dd];
__device__ float g_logits[Nn * Dd];
__device__ float g_part[(size_t)AGG_SPLITS * Nn * Dd];

// ---------------- squared norms ----------------
__global__ void sq_kernel(const float* __restrict__ x) {
    int w = (blockIdx.x * blockDim.x + threadIdx.x) >> 5;
    int lane = threadIdx.x & 31;
    if (w >= Nn) return;
    float4 r = *(const float4*)(x + (size_t)w * Dd + lane * 4);
    float s = r.x * r.x + r.y * r.y + r.z * r.z + r.w * r.w;
    #pragma unroll
    for (int o = 16; o; o >>= 1) s += __shfl_xor_sync(0xffffffffu, s, o);
    if (lane == 0) g_sq[w] = s;
}

// =====================================================================
// 128x128x16 double-buffered SGEMM, 8x8 microtile, 256 threads.
// MODE: 0 = plain, 1 = +bias[col], 2 = elu(+bias[col]), 3 = dist epilogue
// TRANSB: B stored row-major [N,K]
// Per blockIdx.z: A += zA, B += zB, C += zC, bias += zBias (element offsets)
// =====================================================================
template <int MODE, bool TRANSB>
__global__ __launch_bounds__(256) void sgemm128(
    const float* __restrict__ A, const float* __restrict__ B, float* __restrict__ C,
    const float* __restrict__ bias,
    int Kdim, int lda, int ldb, int ldc,
    long zA, long zB, long zC, long zBias)
{
    __shared__ float As[2][16][128];
    __shared__ float Bs[2][16][128];

    const float* Ab = A + (size_t)blockIdx.z * zA;
    const float* Bb = B + (size_t)blockIdx.z * zB;
    float* Cb = C + (size_t)blockIdx.z * zC;
    const float* biasb = bias ? bias + (size_t)blockIdx.z * zBias : nullptr;

    const int bm = blockIdx.y * 128;
    const int bn = blockIdx.x * 128;
    const int tid = threadIdx.x;
    const int tx = tid & 15, ty = tid >> 4;

    // load indices (two float4s each for A and B)
    const int fa0 = tid, fa1 = tid + 256;
    const int ar0 = fa0 >> 2, ac0 = (fa0 & 3) * 4;
    const int ar1 = fa1 >> 2, ac1 = (fa1 & 3) * 4;
    // B non-trans: k = f>>5, n = (f&31)*4 ; B trans: n = f>>2, c = (f&3)*4
    const int bk0 = TRANSB ? (fa0 >> 2) : (fa0 >> 5);
    const int bc0 = TRANSB ? ((fa0 & 3) * 4) : ((fa0 & 31) * 4);
    const int bk1 = TRANSB ? (fa1 >> 2) : (fa1 >> 5);
    const int bc1 = TRANSB ? ((fa1 & 3) * 4) : ((fa1 & 31) * 4);

    float acc[8][8];
    #pragma unroll
    for (int i = 0; i < 8; i++)
        #pragma unroll
        for (int j = 0; j < 8; j++) acc[i][j] = 0.f;

    const int T = Kdim >> 4;

    // ---- load stage 0 ----
    {
        float4 a0 = *(const float4*)(Ab + (size_t)(bm + ar0) * lda + ac0);
        float4 a1 = *(const float4*)(Ab + (size_t)(bm + ar1) * lda + ac1);
        As[0][ac0 + 0][ar0] = a0.x; As[0][ac0 + 1][ar0] = a0.y;
        As[0][ac0 + 2][ar0] = a0.z; As[0][ac0 + 3][ar0] = a0.w;
        As[0][ac1 + 0][ar1] = a1.x; As[0][ac1 + 1][ar1] = a1.y;
        As[0][ac1 + 2][ar1] = a1.z; As[0][ac1 + 3][ar1] = a1.w;
        if (TRANSB) {
            float4 b0 = *(const float4*)(Bb + (size_t)(bn + bk0) * ldb + bc0);
            float4 b1 = *(const float4*)(Bb + (size_t)(bn + bk1) * ldb + bc1);
            Bs[0][bc0 + 0][bk0] = b0.x; Bs[0][bc0 + 1][bk0] = b0.y;
            Bs[0][bc0 + 2][bk0] = b0.z; Bs[0][bc0 + 3][bk0] = b0.w;
            Bs[0][bc1 + 0][bk1] = b1.x; Bs[0][bc1 + 1][bk1] = b1.y;
            Bs[0][bc1 + 2][bk1] = b1.z; Bs[0][bc1 + 3][bk1] = b1.w;
        } else {
            float4 b0 = *(const float4*)(Bb + (size_t)bk0 * ldb + bn + bc0);
            float4 b1 = *(const float4*)(Bb + (size_t)bk1 * ldb + bn + bc1);
            *(float4*)&Bs[0][bk0][bc0] = b0;
            *(float4*)&Bs[0][bk1][bc1] = b1;
        }
    }
    __syncthreads();

    int cur = 0;
    for (int t = 0; t < T; t++) {
        float4 pa0, pa1, pb0, pb1;
        const bool has = (t + 1 < T);
        if (has) {
            int k0 = (t + 1) << 4;
            pa0 = *(const float4*)(Ab + (size_t)(bm + ar0) * lda + k0 + ac0);
            pa1 = *(const float4*)(Ab + (size_t)(bm + ar1) * lda + k0 + ac1);
            if (TRANSB) {
                pb0 = *(const float4*)(Bb + (size_t)(bn + bk0) * ldb + k0 + bc0);
                pb1 = *(const float4*)(Bb + (size_t)(bn + bk1) * ldb + k0 + bc1);
            } else {
                pb0 = *(const float4*)(Bb + (size_t)(k0 + bk0) * ldb + bn + bc0);
                pb1 = *(const float4*)(Bb + (size_t)(k0 + bk1) * ldb + bn + bc1);
            }
        }

        #pragma unroll
        for (int k = 0; k < 16; k++) {
            float a[8], b[8];
            *(float4*)&a[0] = *(const float4*)&As[cur][k][ty * 4];
            *(float4*)&a[4] = *(const float4*)&As[cur][k][64 + ty * 4];
            *(float4*)&b[0] = *(const float4*)&Bs[cur][k][tx * 4];
            *(float4*)&b[4] = *(const float4*)&Bs[cur][k][64 + tx * 4];
            #pragma unroll
            for (int i = 0; i < 8; i++)
                #pragma unroll
                for (int j = 0; j < 8; j++)
                    acc[i][j] = fmaf(a[i], b[j], acc[i][j]);
        }

        if (has) {
            int nxt = cur ^ 1;
            As[nxt][ac0 + 0][ar0] = pa0.x; As[nxt][ac0 + 1][ar0] = pa0.y;
            As[nxt][ac0 + 2][ar0] = pa0.z; As[nxt][ac0 + 3][ar0] = pa0.w;
            As[nxt][ac1 + 0][ar1] = pa1.x; As[nxt][ac1 + 1][ar1] = pa1.y;
            As[nxt][ac1 + 2][ar1] = pa1.z; As[nxt][ac1 + 3][ar1] = pa1.w;
            if (TRANSB) {
                Bs[nxt][bc0 + 0][bk0] = pb0.x; Bs[nxt][bc0 + 1][bk0] = pb0.y;
                Bs[nxt][bc0 + 2][bk0] = pb0.z; Bs[nxt][bc0 + 3][bk0] = pb0.w;
                Bs[nxt][bc1 + 0][bk1] = pb1.x; Bs[nxt][bc1 + 1][bk1] = pb1.y;
                Bs[nxt][bc1 + 2][bk1] = pb1.z; Bs[nxt][bc1 + 3][bk1] = pb1.w;
            } else {
                *(float4*)&Bs[nxt][bk0][bc0] = pb0;
                *(float4*)&Bs[nxt][bk1][bc1] = pb1;
            }
        }
        __syncthreads();
        cur ^= 1;
    }

    // ---- epilogue ----
    #pragma unroll
    for (int ih = 0; ih < 2; ih++) {
        #pragma unroll
        for (int u = 0; u < 4; u++) {
            int row = bm + ih * 64 + ty * 4 + u;
            #pragma unroll
            for (int jh = 0; jh < 2; jh++) {
                int col = bn + jh * 64 + tx * 4;
                float4 v;
                v.x = acc[ih * 4 + u][jh * 4 + 0];
                v.y = acc[ih * 4 + u][jh * 4 + 1];
                v.z = acc[ih * 4 + u][jh * 4 + 2];
                v.w = acc[ih * 4 + u][jh * 4 + 3];
                if (MODE == 1 || MODE == 2) {
                    float4 b4 = *(const float4*)(biasb + col);
                    v.x += b4.x; v.y += b4.y; v.z += b4.z; v.w += b4.w;
                    if (MODE == 2) {
                        v.x = (v.x > 0.f) ? v.x : expm1f(v.x);
                        v.y = (v.y > 0.f) ? v.y : expm1f(v.y);
                        v.z = (v.z > 0.f) ? v.z : expm1f(v.z);
                        v.w = (v.w > 0.f) ? v.w : expm1f(v.w);
                    }
                } else if (MODE == 3) {
                    float sr = bias[row];
                    float4 sc = *(const float4*)(bias + col);
                    v.x = sr + sc.x - 2.f * v.x;
                    v.y = sr + sc.y - 2.f * v.y;
                    v.z = sr + sc.z - 2.f * v.z;
                    v.w = sr + sc.w - 2.f * v.w;
                }
                *(float4*)(Cb + (size_t)row * ldc + col) = v;
            }
        }
    }
}

// ---------------- old 64x64 SGEMM kept for small cls GEMM ----------------
template <int MODE>
__global__ __launch_bounds__(256) void sgemm64(
    const float* __restrict__ A, const float* __restrict__ B, float* __restrict__ C,
    const float* __restrict__ bias, int Ndim, int Kdim)
{
    const int BM = 64, BN = 64, BK = 16;
    __shared__ float As[BK][BM];
    __shared__ float Bs[BK][BN];

    int bm = blockIdx.y * BM;
    int bn = blockIdx.x * BN;
    int tid = threadIdx.x;
    int tx = tid & 15, ty = tid >> 4;

    float acc[4][4];
    #pragma unroll
    for (int u = 0; u < 4; u++)
        #pragma unroll
        for (int w = 0; w < 4; w++) acc[u][w] = 0.f;

    for (int k0 = 0; k0 < Kdim; k0 += BK) {
        {
            int idx = tid * 4;
            int m = idx / BK, k = idx % BK;
            float4 v = *(const float4*)(A + (size_t)(bm + m) * Kdim + k0 + k);
            As[k + 0][m] = v.x; As[k + 1][m] = v.y; As[k + 2][m] = v.z; As[k + 3][m] = v.w;
        }
        {
            int idx = tid * 4;
            int k = idx / BN, n = idx % BN;
            float4 v = *(const float4*)(B + (size_t)(k0 + k) * Ndim + bn + n);
            *(float4*)&Bs[k][n] = v;
        }
        __syncthreads();
        #pragma unroll
        for (int k = 0; k < BK; k++) {
            float a[4], b[4];
            #pragma unroll
            for (int u = 0; u < 4; u++) a[u] = As[k][ty * 4 + u];
            #pragma unroll
            for (int w = 0; w < 4; w++) b[w] = Bs[k][tx * 4 + w];
            #pragma unroll
            for (int u = 0; u < 4; u++)
                #pragma unroll
                for (int w = 0; w < 4; w++) acc[u][w] = fmaf(a[u], b[w], acc[u][w]);
        }
        __syncthreads();
    }

    #pragma unroll
    for (int u = 0; u < 4; u++) {
        int row = bm + ty * 4 + u;
        #pragma unroll
        for (int w = 0; w < 4; w++) {
            int col = bn + tx * 4 + w;
            float val = acc[u][w] + bias[col];
            if (MODE == 2) val = (val > 0.f) ? val : expm1f(val);
            C[(size_t)row * Ndim + col] = val;
        }
    }
}

// ---------------- per-row top-K: one warp per row, register top-10 ----------------
__global__ void knn_kernel() {
    int w = (blockIdx.x * blockDim.x + threadIdx.x) >> 5;
    int lane = threadIdx.x & 31;
    if (w >= Nn) return;
    const float* dr = g_dist + (size_t)w * Nn;

    float val[Kk];
    int   idx[Kk];
    #pragma unroll
    for (int p = 0; p < Kk; p++) { val[p] = FLT_MAX; idx[p] = 0x7fffffff; }

    for (int t = 0; t < Nn / 32; t++) {
        int j = lane + t * 32;
        float d = dr[j];
        if (d < val[Kk - 1]) {
            #pragma unroll
            for (int p = Kk - 1; p >= 1; p--) {
                if (d < val[p]) {
                    bool sh = d < val[p - 1];
                    val[p] = sh ? val[p - 1] : d;
                    idx[p] = sh ? idx[p - 1] : j;
                }
            }
            if (d < val[0]) { val[0] = d; idx[0] = j; }
        }
    }

    // 32-way merge: pop global min K times
    #pragma unroll 1
    for (int r = 0; r < Kk; r++) {
        float bv = val[0]; int bi = idx[0];
        #pragma unroll
        for (int o = 16; o; o >>= 1) {
            float ov = __shfl_xor_sync(0xffffffffu, bv, o);
            int   oi = __shfl_xor_sync(0xffffffffu, bi, o);
            if (ov < bv || (ov == bv && oi < bi)) { bv = ov; bi = oi; }
        }
        if (lane == 0) g_knn[w * Kk + r] = bi;
        if (val[0] == bv && idx[0] == bi) {
            #pragma unroll
            for (int p = 0; p < Kk - 1; p++) { val[p] = val[p + 1]; idx[p] = idx[p + 1]; }
            val[Kk - 1] = FLT_MAX; idx[Kk - 1] = 0x7fffffff;
        }
    }
}

// ---------------- f1/f2 projections ----------------
__global__ void f12_kernel(const float* __restrict__ gat_a) {
    int w = (blockIdx.x * blockDim.x + threadIdx.x) >> 5;
    int lane = threadIdx.x & 31;
    if (w >= VH * Nn) return;
    int vh = w / Nn;
    const float* row = g_Wh + (size_t)w * Dd;
    const float* a1 = gat_a + (size_t)vh * 2 * Dd;
    const float* a2 = a1 + Dd;
    float4 r = *(const float4*)(row + lane * 4);
    float4 v1 = *(const float4*)(a1 + lane * 4);
    float4 v2 = *(const float4*)(a2 + lane * 4);
    float s1 = r.x * v1.x + r.y * v1.y + r.z * v1.z + r.w * v1.w;
    float s2 = r.x * v2.x + r.y * v2.y + r.z * v2.z + r.w * v2.w;
    #pragma unroll
    for (int o = 16; o; o >>= 1) {
        s1 += __shfl_xor_sync(0xffffffffu, s1, o);
        s2 += __shfl_xor_sync(0xffffffffu, s2, o);
    }
    if (lane == 0) { g_f1[w] = s1; g_f2[w] = s2; }
}

// ---------------- sparse GAT attention: one warp per (v,h,node) ----------------
__global__ void attn_kernel(const float* __restrict__ fm) {
    int w = (blockIdx.x * blockDim.x + threadIdx.x) >> 5;
    int lane = threadIdx.x & 31;
    if (w >= VH * Nn) return;
    int i = w % Nn;
    int vh = w / Nn;
    int v = vh / Hh;

    int nb = -1;
    bool valid = false;
    if (lane < Kk) {
        nb = g_knn[i * Kk + lane];
        valid = (nb == i) || (fm[(size_t)i * Vv + v] > 0.f && fm[(size_t)nb * Vv + v] > 0.f);
    }
    unsigned hasSelf = __ballot_sync(0xffffffffu, lane < Kk && nb == i);
    if (hasSelf == 0 && lane == Kk) { nb = i; valid = true; }

    float e = -FLT_MAX;
    if (valid) {
        float x = g_f1[vh * Nn + i] + g_f2[vh * Nn + nb];
        e = (x >= 0.f) ? x : LRELU_ALPHA * x;
    }
    float m = e;
    #pragma unroll
    for (int o = 16; o; o >>= 1) m = fmaxf(m, __shfl_xor_sync(0xffffffffu, m, o));
    float wt = valid ? expf(e - m) : 0.f;
    float s = wt;
    #pragma unroll
    for (int o = 16; o; o >>= 1) s += __shfl_xor_sync(0xffffffffu, s, o);
    float att = wt / s;

    const float* base = g_Wh + (size_t)vh * Nn * Dd;
    float4 acc = make_float4(0.f, 0.f, 0.f, 0.f);
    #pragma unroll
    for (int j = 0; j <= Kk; j++) {
        float a = __shfl_sync(0xffffffffu, att, j);
        int nj = __shfl_sync(0xffffffffu, nb, j);
        if (a != 0.f) {
            float4 wv = *(const float4*)(base + (size_t)nj * Dd + lane * 4);
            acc.x = fmaf(a, wv.x, acc.x);
            acc.y = fmaf(a, wv.y, acc.y);
            acc.z = fmaf(a, wv.z, acc.z);
            acc.w = fmaf(a, wv.w, acc.w);
        }
    }
    float* dst = g_meta + (size_t)i * (VH * Dd) + (size_t)vh * Dd + lane * 4;
    *(float4*)dst = acc;
}

// ---------------- split-K reduce for agg + bias ----------------
__global__ void agg_reduce_kernel(const float* __restrict__ bias, float* __restrict__ sem) {
    int i = blockIdx.x * blockDim.x + threadIdx.x;
    if (i >= Nn * Dd) return;
    float s = 0.f;
    #pragma unroll
    for (int p = 0; p < AGG_SPLITS; p++) s += g_part[(size_t)p * Nn * Dd + i];
    sem[i] = s + bias[i & (Dd - 1)];
}

// ---------------- row log_softmax over D=128 ----------------
__global__ __launch_bounds__(128) void logsoftmax_kernel(float* __restrict__ outp) {
    __shared__ float red[128];
    int row = blockIdx.x;
    int t = threadIdx.x;
    float x = g_logits[row * Dd + t];
    red[t] = x;
    __syncthreads();
    for (int s = 64; s > 0; s >>= 1) {
        if (t < s) red[t] = fmaxf(red[t], red[t + s]);
        __syncthreads();
    }
    float m = red[0];
    __syncthreads();
    red[t] = expf(x - m);
    __syncthreads();
    for (int s = 64; s > 0; s >>= 1) {
        if (t < s) red[t] += red[t + s];
        __syncthreads();
    }
    float lse = m + logf(red[0]);
    outp[row * Dd + t] = x - lse;
}

// ---------------- launch ----------------
extern "C" void kernel_launch(void* const* d_in, const int* in_sizes, int n_in,
                              void* d_out, int out_size) {
    const float* fm     = (const float*)d_in[0];
    const float* latent = (const float*)d_in[1];
    const float* enc_W  = (const float*)d_in[2];
    const float* enc_b  = (const float*)d_in[3];
    const float* gat_W  = (const float*)d_in[4];
    const float* gat_a  = (const float*)d_in[5];
    const float* agg_W  = (const float*)d_in[6];
    const float* agg_b  = (const float*)d_in[7];
    const float* cls_W  = (const float*)d_in[8];
    const float* cls_b  = (const float*)d_in[9];

    float* out  = (float*)d_out;
    float* rec  = out;                                   // [V,N,VD]
    float* outp = out + (size_t)Vv * Nn * VDd;           // [N,D]
    float* sem  = outp + (size_t)Nn * Dd;                // [N,D]

    float *p_sq, *p_dist, *p_Wh, *p_meta, *p_logits, *p_part;
    cudaGetSymbolAddress((void**)&p_sq, g_sq);
    cudaGetSymbolAddress((void**)&p_dist, g_dist);
    cudaGetSymbolAddress((void**)&p_Wh, g_Wh);
    cudaGetSymbolAddress((void**)&p_meta, g_meta);
    cudaGetSymbolAddress((void**)&p_logits, g_logits);
    cudaGetSymbolAddress((void**)&p_part, g_part);

    // 1. squared norms
    sq_kernel<<<Nn / 8, 256>>>(latent);
    // 2. dist = sq_i + sq_j - 2 * latent @ latent^T
    sgemm128<3, true><<<dim3(Nn / 128, Nn / 128, 1), 256>>>(
        latent, latent, p_dist, p_sq, Dd, Dd, Dd, Nn, 0, 0, 0, 0);
    // 3. top-K neighbors per row (warp per row)
    knn_kernel<<<Nn / 8, 256>>>();
    // 4. Wh[v,h] = latent @ gat_W[v,h]
    sgemm128<0, false><<<dim3(1, Nn / 128, VH), 256>>>(
        latent, gat_W, p_Wh, nullptr, Dd, Dd, Dd, Dd,
        0, (long)Dd * Dd, (long)Nn * Dd, 0);
    // 5. f1/f2 attention projections
    f12_kernel<<<VH * Nn / 8, 256>>>(gat_a);
    // 6. sparse masked softmax attention + gather -> meta [N, V*H*D]
    attn_kernel<<<VH * Nn / 8, 256>>>(fm);
    // 7. rec[v] = latent @ enc_W[v] + enc_b[v]
    sgemm128<1, false><<<dim3(VDd / 128, Nn / 128, Vv), 256>>>(
        latent, enc_W, rec, enc_b, Dd, Dd, VDd, VDd,
        0, (long)Dd * VDd, (long)Nn * VDd, (long)VDd);
    // 8. semantic partials = meta @ agg_W (split-K)
    sgemm128<0, false><<<dim3(1, Nn / 128, AGG_SPLITS), 256>>>(
        p_meta, agg_W, p_part, nullptr, AGG_KCHUNK, VH * Dd, Dd, Dd,
        (long)AGG_KCHUNK, (long)AGG_KCHUNK * Dd, (long)Nn * Dd, 0);
    // 9. reduce partials + bias -> semantic (output)
    agg_reduce_kernel<<<(Nn * Dd) / 256, 256>>>(agg_b, sem);
    // 10. logits = elu(semantic @ cls_W + cls_b)
    sgemm64<2><<<dim3(Dd / 64, Nn / 64, 1), 256>>>(
        sem, cls_W, p_logits, cls_b, Dd, Dd);
    // 11. output = log_softmax(logits)
    logsoftmax_kernel<<<Nn, 128>>>(outp);
}

// round 4
// speedup vs baseline: 1.5873x; 1.0627x over previous
#include <cuda_runtime.h>
#include <cuda_bf16.h>
#include <cstdint>
#include <math.h>
#include <float.h>

#define Nn 2048
#define Dd 128
#define Vv 3
#define Hh 4
#define VDd 512
#define Kk 10
#define VH (Vv*Hh)
#define LRELU_ALPHA 0.2f
#define AGG_SPLITS 8
#define AGG_KCHUNK ((VH*Dd)/AGG_SPLITS)   // 192

// ---------------- scratch (no allocations allowed) ----------------
__device__ float g_sq[Nn];
__device__ float g_dist[(size_t)Nn * Nn];
__device__ int   g_knn[Nn * Kk];
__device__ float g_Wh[(size_t)VH * Nn * Dd];
__device__ float g_f1[VH * Nn];
__device__ float g_f2[VH * Nn];
__device__ float g_meta[(size_t)Nn * VH * Dd];
__device__ float g_logits[Nn * Dd];
__device__ float g_part[(size_t)AGG_SPLITS * Nn * Dd];

// bf16 split operands
__device__ __nv_bfloat16 g_lat_h[Nn * Dd],  g_lat_l[Nn * Dd];
__device__ __nv_bfloat16 g_gwT_h[VH * Dd * Dd], g_gwT_l[VH * Dd * Dd];
__device__ __nv_bfloat16 g_encT_h[Vv * VDd * Dd], g_encT_l[Vv * VDd * Dd];
__device__ __nv_bfloat16 g_aggT_h[Dd * VH * Dd], g_aggT_l[Dd * VH * Dd];
__device__ __nv_bfloat16 g_clsT_h[Dd * Dd], g_clsT_l[Dd * Dd];
__device__ __nv_bfloat16 g_meta_h[(size_t)Nn * VH * Dd], g_meta_l[(size_t)Nn * VH * Dd];
__device__ __nv_bfloat16 g_sem_h[Nn * Dd], g_sem_l[Nn * Dd];

// ---------------- split fp32 -> (hi, lo) bf16 ----------------
__global__ void split_kernel(const float* __restrict__ src,
                             __nv_bfloat16* __restrict__ hi,
                             __nv_bfloat16* __restrict__ lo, int n) {
    int i = blockIdx.x * 256 + threadIdx.x;
    if (i >= n) return;
    float x = src[i];
    __nv_bfloat16 h = __float2bfloat16(x);
    hi[i] = h;
    lo[i] = __float2bfloat16(x - __bfloat162float(h));
}

// split + transpose: in [z][R][C] -> out [z][C][R]
__global__ void split_trans_kernel(const float* __restrict__ src,
                                   __nv_bfloat16* __restrict__ hi,
                                   __nv_bfloat16* __restrict__ lo, int R, int C) {
    int i = blockIdx.x * 256 + threadIdx.x;
    size_t zb = (size_t)blockIdx.z * R * C;
    int r = i / C, c = i % C;
    float x = src[zb + i];
    __nv_bfloat16 h = __float2bfloat16(x);
    size_t o = zb + (size_t)c * R + r;
    hi[o] = h;
    lo[o] = __float2bfloat16(x - __bfloat162float(h));
}

// ---------------- squared norms ----------------
__global__ void sq_kernel(const float* __restrict__ x) {
    int w = (blockIdx.x * blockDim.x + threadIdx.x) >> 5;
    int lane = threadIdx.x & 31;
    if (w >= Nn) return;
    float4 r = *(const float4*)(x + (size_t)w * Dd + lane * 4);
    float s = r.x * r.x + r.y * r.y + r.z * r.z + r.w * r.w;
    #pragma unroll
    for (int o = 16; o; o >>= 1) s += __shfl_xor_sync(0xffffffffu, s, o);
    if (lane == 0) g_sq[w] = s;
}

#define MMA_BF16(c, a0, a1, a2, a3, b0, b1) \
    asm volatile("mma.sync.aligned.m16n8k16.row.col.f32.bf16.bf16.f32 " \
                 "{%0,%1,%2,%3}, {%4,%5,%6,%7}, {%8,%9}, {%0,%1,%2,%3};" \
                 : "+f"((c)[0]), "+f"((c)[1]), "+f"((c)[2]), "+f"((c)[3]) \
                 : "r"(a0), "r"(a1), "r"(a2), "r"(a3), "r"(b0), "r"(b1))

// =====================================================================
// bf16 split-compensated tensor-core GEMM.
// C[M,N] = (Ah+Al)[M,K] @ (Bh+Bl)^T where B stored [N,K] row-major.
// 128x128x32 CTA tile, 8 warps (2x4), each warp 64x32 via m16n8k16.
// MODE: 0 plain, 1 +bias[col], 2 elu(+bias[col]), 3 dist epilogue
// =====================================================================
template <int MODE>
__global__ __launch_bounds__(256) void bmma_kernel(
    const __nv_bfloat16* __restrict__ Ah, const __nv_bfloat16* __restrict__ Al,
    const __nv_bfloat16* __restrict__ Bh, const __nv_bfloat16* __restrict__ Bl,
    float* __restrict__ C, const float* __restrict__ bias,
    int Kdim, int lda, int ldb, int ldc,
    long zA, long zB, long zC, long zBias)
{
    __shared__ __nv_bfloat16 Ash[128][40];
    __shared__ __nv_bfloat16 Asl[128][40];
    __shared__ __nv_bfloat16 Bsh[128][40];
    __shared__ __nv_bfloat16 Bsl[128][40];

    const __nv_bfloat16* Ahb = Ah + (size_t)blockIdx.z * zA;
    const __nv_bfloat16* Alb = Al + (size_t)blockIdx.z * zA;
    const __nv_bfloat16* Bhb = Bh + (size_t)blockIdx.z * zB;
    const __nv_bfloat16* Blb = Bl + (size_t)blockIdx.z * zB;
    float* Cb = C + (size_t)blockIdx.z * zC;
    const float* biasb = bias ? bias + (size_t)blockIdx.z * zBias : nullptr;

    const int bm = blockIdx.y * 128, bn = blockIdx.x * 128;
    const int tid = threadIdx.x;
    const int wid = tid >> 5, lane = tid & 31;
    const int wm = wid >> 2, wn = wid & 3;       // 2 x 4 warp grid
    const int gr = lane >> 2, ct = lane & 3;

    // gmem->smem loader: each thread 1 uint4 (8 bf16) per row-half per array
    const int r0 = tid >> 2;            // 0..63
    const int cv = (tid & 3) * 8;       // 0,8,16,24

    float acc[4][4][4];
    #pragma unroll
    for (int mt = 0; mt < 4; mt++)
        #pragma unroll
        for (int nt = 0; nt < 4; nt++)
            #pragma unroll
            for (int q = 0; q < 4; q++) acc[mt][nt][q] = 0.f;

    const int T = Kdim >> 5;
    for (int t = 0; t < T; t++) {
        const int k0 = t * 32;
        uint4 gah0 = *(const uint4*)(Ahb + (size_t)(bm + r0) * lda + k0 + cv);
        uint4 gah1 = *(const uint4*)(Ahb + (size_t)(bm + r0 + 64) * lda + k0 + cv);
        uint4 gal0 = *(const uint4*)(Alb + (size_t)(bm + r0) * lda + k0 + cv);
        uint4 gal1 = *(const uint4*)(Alb + (size_t)(bm + r0 + 64) * lda + k0 + cv);
        uint4 gbh0 = *(const uint4*)(Bhb + (size_t)(bn + r0) * ldb + k0 + cv);
        uint4 gbh1 = *(const uint4*)(Bhb + (size_t)(bn + r0 + 64) * ldb + k0 + cv);
        uint4 gbl0 = *(const uint4*)(Blb + (size_t)(bn + r0) * ldb + k0 + cv);
        uint4 gbl1 = *(const uint4*)(Blb + (size_t)(bn + r0 + 64) * ldb + k0 + cv);

        __syncthreads();   // previous tile's compute done
        *(uint4*)&Ash[r0][cv] = gah0;  *(uint4*)&Ash[r0 + 64][cv] = gah1;
        *(uint4*)&Asl[r0][cv] = gal0;  *(uint4*)&Asl[r0 + 64][cv] = gal1;
        *(uint4*)&Bsh[r0][cv] = gbh0;  *(uint4*)&Bsh[r0 + 64][cv] = gbh1;
        *(uint4*)&Bsl[r0][cv] = gbl0;  *(uint4*)&Bsl[r0 + 64][cv] = gbl1;
        __syncthreads();

        #pragma unroll
        for (int kk = 0; kk < 32; kk += 16) {
            uint32_t bh[4][2], bl[4][2];
            #pragma unroll
            for (int nt = 0; nt < 4; nt++) {
                int n = wn * 32 + nt * 8 + gr;
                bh[nt][0] = *(const uint32_t*)&Bsh[n][kk + ct * 2];
                bh[nt][1] = *(const uint32_t*)&Bsh[n][kk + ct * 2 + 8];
                bl[nt][0] = *(const uint32_t*)&Bsl[n][kk + ct * 2];
                bl[nt][1] = *(const uint32_t*)&Bsl[n][kk + ct * 2 + 8];
            }
            #pragma unroll
            for (int mt = 0; mt < 4; mt++) {
                int rA = wm * 64 + mt * 16 + gr;
                uint32_t ah0 = *(const uint32_t*)&Ash[rA][kk + ct * 2];
                uint32_t ah1 = *(const uint32_t*)&Ash[rA + 8][kk + ct * 2];
                uint32_t ah2 = *(const uint32_t*)&Ash[rA][kk + ct * 2 + 8];
                uint32_t ah3 = *(const uint32_t*)&Ash[rA + 8][kk + ct * 2 + 8];
                uint32_t al0 = *(const uint32_t*)&Asl[rA][kk + ct * 2];
                uint32_t al1 = *(const uint32_t*)&Asl[rA + 8][kk + ct * 2];
                uint32_t al2 = *(const uint32_t*)&Asl[rA][kk + ct * 2 + 8];
                uint32_t al3 = *(const uint32_t*)&Asl[rA + 8][kk + ct * 2 + 8];
                #pragma unroll
                for (int nt = 0; nt < 4; nt++) {
                    MMA_BF16(acc[mt][nt], ah0, ah1, ah2, ah3, bh[nt][0], bh[nt][1]);
                    MMA_BF16(acc[mt][nt], ah0, ah1, ah2, ah3, bl[nt][0], bl[nt][1]);
                    MMA_BF16(acc[mt][nt], al0, al1, al2, al3, bh[nt][0], bh[nt][1]);
                }
            }
        }
    }

    // epilogue
    #pragma unroll
    for (int mt = 0; mt < 4; mt++) {
        int row = bm + wm * 64 + mt * 16 + gr;
        #pragma unroll
        for (int nt = 0; nt < 4; nt++) {
            int col = bn + wn * 32 + nt * 8 + ct * 2;
            float v0 = acc[mt][nt][0], v1 = acc[mt][nt][1];
            float v2 = acc[mt][nt][2], v3 = acc[mt][nt][3];
            if (MODE == 1 || MODE == 2) {
                float b0 = biasb[col], b1 = biasb[col + 1];
                v0 += b0; v1 += b1; v2 += b0; v3 += b1;
                if (MODE == 2) {
                    v0 = (v0 > 0.f) ? v0 : expm1f(v0);
                    v1 = (v1 > 0.f) ? v1 : expm1f(v1);
                    v2 = (v2 > 0.f) ? v2 : expm1f(v2);
                    v3 = (v3 > 0.f) ? v3 : expm1f(v3);
                }
            } else if (MODE == 3) {
                float sr0 = bias[row], sr1 = bias[row + 8];
                float sc0 = bias[col], sc1 = bias[col + 1];
                v0 = sr0 + sc0 - 2.f * v0;
                v1 = sr0 + sc1 - 2.f * v1;
                v2 = sr1 + sc0 - 2.f * v2;
                v3 = sr1 + sc1 - 2.f * v3;
            }
            *(float2*)(Cb + (size_t)row * ldc + col) = make_float2(v0, v1);
            *(float2*)(Cb + (size_t)(row + 8) * ldc + col) = make_float2(v2, v3);
        }
    }
}

// ---------------- per-row top-K: one warp per row, register top-10 ----------------
__global__ void knn_kernel() {
    int w = (blockIdx.x * blockDim.x + threadIdx.x) >> 5;
    int lane = threadIdx.x & 31;
    if (w >= Nn) return;
    const float* dr = g_dist + (size_t)w * Nn;

    float val[Kk];
    int   idx[Kk];
    #pragma unroll
    for (int p = 0; p < Kk; p++) { val[p] = FLT_MAX; idx[p] = 0x7fffffff; }

    for (int t = 0; t < Nn / 32; t++) {
        int j = lane + t * 32;
        float d = dr[j];
        if (d < val[Kk - 1]) {
            #pragma unroll
            for (int p = Kk - 1; p >= 1; p--) {
                if (d < val[p]) {
                    bool sh = d < val[p - 1];
                    val[p] = sh ? val[p - 1] : d;
                    idx[p] = sh ? idx[p - 1] : j;
                }
            }
            if (d < val[0]) { val[0] = d; idx[0] = j; }
        }
    }

    #pragma unroll 1
    for (int r = 0; r < Kk; r++) {
        float bv = val[0]; int bi = idx[0];
        #pragma unroll
        for (int o = 16; o; o >>= 1) {
            float ov = __shfl_xor_sync(0xffffffffu, bv, o);
            int   oi = __shfl_xor_sync(0xffffffffu, bi, o);
            if (ov < bv || (ov == bv && oi < bi)) { bv = ov; bi = oi; }
        }
        if (lane == 0) g_knn[w * Kk + r] = bi;
        if (val[0] == bv && idx[0] == bi) {
            #pragma unroll
            for (int p = 0; p < Kk - 1; p++) { val[p] = val[p + 1]; idx[p] = idx[p + 1]; }
            val[Kk - 1] = FLT_MAX; idx[Kk - 1] = 0x7fffffff;
        }
    }
}

// ---------------- f1/f2 projections ----------------
__global__ void f12_kernel(const float* __restrict__ gat_a) {
    int w = (blockIdx.x * blockDim.x + threadIdx.x) >> 5;
    int lane = threadIdx.x & 31;
    if (w >= VH * Nn) return;
    int vh = w / Nn;
    const float* row = g_Wh + (size_t)w * Dd;
    const float* a1 = gat_a + (size_t)vh * 2 * Dd;
    const float* a2 = a1 + Dd;
    float4 r = *(const float4*)(row + lane * 4);
    float4 v1 = *(const float4*)(a1 + lane * 4);
    float4 v2 = *(const float4*)(a2 + lane * 4);
    float s1 = r.x * v1.x + r.y * v1.y + r.z * v1.z + r.w * v1.w;
    float s2 = r.x * v2.x + r.y * v2.y + r.z * v2.z + r.w * v2.w;
    #pragma unroll
    for (int o = 16; o; o >>= 1) {
        s1 += __shfl_xor_sync(0xffffffffu, s1, o);
        s2 += __shfl_xor_sync(0xffffffffu, s2, o);
    }
    if (lane == 0) { g_f1[w] = s1; g_f2[w] = s2; }
}

// ---------------- sparse GAT attention: one warp per (v,h,node) ----------------
__global__ void attn_kernel(const float* __restrict__ fm) {
    int w = (blockIdx.x * blockDim.x + threadIdx.x) >> 5;
    int lane = threadIdx.x & 31;
    if (w >= VH * Nn) return;
    int i = w % Nn;
    int vh = w / Nn;
    int v = vh / Hh;

    int nb = -1;
    bool valid = false;
    if (lane < Kk) {
        nb = g_knn[i * Kk + lane];
        valid = (nb == i) || (fm[(size_t)i * Vv + v] > 0.f && fm[(size_t)nb * Vv + v] > 0.f);
    }
    unsigned hasSelf = __ballot_sync(0xffffffffu, lane < Kk && nb == i);
    if (hasSelf == 0 && lane == Kk) { nb = i; valid = true; }

    float e = -FLT_MAX;
    if (valid) {
        float x = g_f1[vh * Nn + i] + g_f2[vh * Nn + nb];
        e = (x >= 0.f) ? x : LRELU_ALPHA * x;
    }
    float m = e;
    #pragma unroll
    for (int o = 16; o; o >>= 1) m = fmaxf(m, __shfl_xor_sync(0xffffffffu, m, o));
    float wt = valid ? expf(e - m) : 0.f;
    float s = wt;
    #pragma unroll
    for (int o = 16; o; o >>= 1) s += __shfl_xor_sync(0xffffffffu, s, o);
    float att = wt / s;

    const float* base = g_Wh + (size_t)vh * Nn * Dd;
    float4 acc = make_float4(0.f, 0.f, 0.f, 0.f);
    #pragma unroll
    for (int j = 0; j <= Kk; j++) {
        float a = __shfl_sync(0xffffffffu, att, j);
        int nj = __shfl_sync(0xffffffffu, nb, j);
        if (a != 0.f) {
            float4 wv = *(const float4*)(base + (size_t)nj * Dd + lane * 4);
            acc.x = fmaf(a, wv.x, acc.x);
            acc.y = fmaf(a, wv.y, acc.y);
            acc.z = fmaf(a, wv.z, acc.z);
            acc.w = fmaf(a, wv.w, acc.w);
        }
    }
    float* dst = g_meta + (size_t)i * (VH * Dd) + (size_t)vh * Dd + lane * 4;
    *(float4*)dst = acc;
}

// ---------------- split-K reduce for agg + bias ----------------
__global__ void agg_reduce_kernel(const float* __restrict__ bias, float* __restrict__ sem) {
    int i = blockIdx.x * blockDim.x + threadIdx.x;
    if (i >= Nn * Dd) return;
    float s = 0.f;
    #pragma unroll
    for (int p = 0; p < AGG_SPLITS; p++) s += g_part[(size_t)p * Nn * Dd + i];
    sem[i] = s + bias[i & (Dd - 1)];
}

// ---------------- row log_softmax over D=128 ----------------
__global__ __launch_bounds__(128) void logsoftmax_kernel(float* __restrict__ outp) {
    __shared__ float red[128];
    int row = blockIdx.x;
    int t = threadIdx.x;
    float x = g_logits[row * Dd + t];
    red[t] = x;
    __syncthreads();
    for (int s = 64; s > 0; s >>= 1) {
        if (t < s) red[t] = fmaxf(red[t], red[t + s]);
        __syncthreads();
    }
    float m = red[0];
    __syncthreads();
    red[t] = expf(x - m);
    __syncthreads();
    for (int s = 64; s > 0; s >>= 1) {
        if (t < s) red[t] += red[t + s];
        __syncthreads();
    }
    float lse = m + logf(red[0]);
    outp[row * Dd + t] = x - lse;
}

// ---------------- launch ----------------
extern "C" void kernel_launch(void* const* d_in, const int* in_sizes, int n_in,
                              void* d_out, int out_size) {
    const float* fm     = (const float*)d_in[0];
    const float* latent = (const float*)d_in[1];
    const float* enc_W  = (const float*)d_in[2];
    const float* enc_b  = (const float*)d_in[3];
    const float* gat_W  = (const float*)d_in[4];
    const float* gat_a  = (const float*)d_in[5];
    const float* agg_W  = (const float*)d_in[6];
    const float* agg_b  = (const float*)d_in[7];
    const float* cls_W  = (const float*)d_in[8];
    const float* cls_b  = (const float*)d_in[9];

    float* out  = (float*)d_out;
    float* rec  = out;                                   // [V,N,VD]
    float* outp = out + (size_t)Vv * Nn * VDd;           // [N,D]
    float* sem  = outp + (size_t)Nn * Dd;                // [N,D]

    float *p_sq, *p_dist, *p_Wh, *p_meta, *p_logits, *p_part;
    cudaGetSymbolAddress((void**)&p_sq, g_sq);
    cudaGetSymbolAddress((void**)&p_dist, g_dist);
    cudaGetSymbolAddress((void**)&p_Wh, g_Wh);
    cudaGetSymbolAddress((void**)&p_meta, g_meta);
    cudaGetSymbolAddress((void**)&p_logits, g_logits);
    cudaGetSymbolAddress((void**)&p_part, g_part);

    __nv_bfloat16 *lat_h, *lat_l, *gwT_h, *gwT_l, *encT_h, *encT_l;
    __nv_bfloat16 *aggT_h, *aggT_l, *clsT_h, *clsT_l, *meta_h, *meta_l, *sem_h, *sem_l;
    cudaGetSymbolAddress((void**)&lat_h, g_lat_h);   cudaGetSymbolAddress((void**)&lat_l, g_lat_l);
    cudaGetSymbolAddress((void**)&gwT_h, g_gwT_h);   cudaGetSymbolAddress((void**)&gwT_l, g_gwT_l);
    cudaGetSymbolAddress((void**)&encT_h, g_encT_h); cudaGetSymbolAddress((void**)&encT_l, g_encT_l);
    cudaGetSymbolAddress((void**)&aggT_h, g_aggT_h); cudaGetSymbolAddress((void**)&aggT_l, g_aggT_l);
    cudaGetSymbolAddress((void**)&clsT_h, g_clsT_h); cudaGetSymbolAddress((void**)&clsT_l, g_clsT_l);
    cudaGetSymbolAddress((void**)&meta_h, g_meta_h); cudaGetSymbolAddress((void**)&meta_l, g_meta_l);
    cudaGetSymbolAddress((void**)&sem_h, g_sem_h);   cudaGetSymbolAddress((void**)&sem_l, g_sem_l);

    // 0. split operands (weights independent of data flow; do up front)
    split_kernel<<<(Nn * Dd) / 256, 256>>>(latent, lat_h, lat_l, Nn * Dd);
    split_trans_kernel<<<dim3((Dd * Dd) / 256, 1, VH), 256>>>(gat_W, gwT_h, gwT_l, Dd, Dd);
    split_trans_kernel<<<dim3((Dd * VDd) / 256, 1, Vv), 256>>>(enc_W, encT_h, encT_l, Dd, VDd);
    split_trans_kernel<<<dim3((VH * Dd * Dd) / 256, 1, 1), 256>>>(agg_W, aggT_h, aggT_l, VH * Dd, Dd);
    split_trans_kernel<<<dim3((Dd * Dd) / 256, 1, 1), 256>>>(cls_W, clsT_h, clsT_l, Dd, Dd);
    // 1. squared norms
    sq_kernel<<<Nn / 8, 256>>>(latent);
    // 2. dist = sq_i + sq_j - 2 * latent @ latent^T  (B-trans == latent itself)
    bmma_kernel<3><<<dim3(Nn / 128, Nn / 128, 1), 256>>>(
        lat_h, lat_l, lat_h, lat_l, p_dist, p_sq, Dd, Dd, Dd, Nn, 0, 0, 0, 0);
    // 3. top-K neighbors per row
    knn_kernel<<<Nn / 8, 256>>>();
    // 4. Wh[v,h] = latent @ gat_W[v,h]
    bmma_kernel<0><<<dim3(1, Nn / 128, VH), 256>>>(
        lat_h, lat_l, gwT_h, gwT_l, p_Wh, nullptr, Dd, Dd, Dd, Dd,
        0, (long)Dd * Dd, (long)Nn * Dd, 0);
    // 5. f1/f2 projections
    f12_kernel<<<VH * Nn / 8, 256>>>(gat_a);
    // 6. sparse attention -> meta
    attn_kernel<<<VH * Nn / 8, 256>>>(fm);
    // 7. rec[v] = latent @ enc_W[v] + enc_b[v]
    bmma_kernel<1><<<dim3(VDd / 128, Nn / 128, Vv), 256>>>(
        lat_h, lat_l, encT_h, encT_l, rec, enc_b, Dd, Dd, Dd, VDd,
        0, (long)VDd * Dd, (long)Nn * VDd, (long)VDd);
    // 8. split meta, then semantic partials = meta @ agg_W (split-K)
    split_kernel<<<(Nn * VH * Dd) / 256, 256>>>(p_meta, meta_h, meta_l, Nn * VH * Dd);
    bmma_kernel<0><<<dim3(1, Nn / 128, AGG_SPLITS), 256>>>(
        meta_h, meta_l, aggT_h, aggT_l, p_part, nullptr,
        AGG_KCHUNK, VH * Dd, VH * Dd, Dd,
        (long)AGG_KCHUNK, (long)AGG_KCHUNK, (long)Nn * Dd, 0);
    // 9. reduce partials + bias -> semantic (output)
    agg_reduce_kernel<<<(Nn * Dd) / 256, 256>>>(agg_b, sem);
    // 10. logits = elu(semantic @ cls_W + cls_b)
    split_kernel<<<(Nn * Dd) / 256, 256>>>(sem, sem_h, sem_l, Nn * Dd);
    bmma_kernel<2><<<dim3(1, Nn / 128, 1), 256>>>(
        sem_h, sem_l, clsT_h, clsT_l, p_logits, cls_b, Dd, Dd, Dd, Dd, 0, 0, 0, 0);
    // 11. output = log_softmax(logits)
    logsoftmax_kernel<<<Nn, 128>>>(outp);
}

// round 5
// speedup vs baseline: 2.0427x; 1.2869x over previous
#include <cuda_runtime.h>
#include <cuda_bf16.h>
#include <cstdint>
#include <math.h>
#include <float.h>

#define Nn 2048
#define Dd 128
#define Vv 3
#define Hh 4
#define VDd 512
#define Kk 10
#define VH (Vv*Hh)
#define LRELU_ALPHA 0.2f
#define AGG_SPLITS 8
#define AGG_KCHUNK ((VH*Dd)/AGG_SPLITS)   // 192

// ---------------- scratch (no allocations allowed) ----------------
__device__ float g_sq[Nn];
__device__ float g_dist[(size_t)Nn * Nn];
__device__ int   g_knn[Nn * Kk];
__device__ float g_Wh[(size_t)VH * Nn * Dd];
__device__ float g_f1[VH * Nn];
__device__ float g_f2[VH * Nn];
__device__ float g_part[(size_t)AGG_SPLITS * Nn * Dd];

// bf16 split operands
__device__ __nv_bfloat16 g_lat_h[Nn * Dd],  g_lat_l[Nn * Dd];
__device__ __nv_bfloat16 g_gwT_h[VH * Dd * Dd], g_gwT_l[VH * Dd * Dd];
__device__ __nv_bfloat16 g_encT_h[Vv * VDd * Dd], g_encT_l[Vv * VDd * Dd];
__device__ __nv_bfloat16 g_aggT_h[Dd * VH * Dd], g_aggT_l[Dd * VH * Dd];
__device__ __nv_bfloat16 g_clsT_h[Dd * Dd], g_clsT_l[Dd * Dd];
__device__ __nv_bfloat16 g_meta_h[(size_t)Nn * VH * Dd], g_meta_l[(size_t)Nn * VH * Dd];
__device__ __nv_bfloat16 g_sem_h[Nn * Dd], g_sem_l[Nn * Dd];

// ---------------- coalesced transpose + split (32x32 tiles) ----------------
__device__ __forceinline__ void trans_tile(
    const float* __restrict__ src, int R, int C,
    __nv_bfloat16* __restrict__ dh, __nv_bfloat16* __restrict__ dl,
    int tr, int tc, int tid)
{
    __shared__ float tile[32][33];
    int tx = tid & 31, ty = tid >> 5;   // ty 0..7
    int r0 = tr * 32, c0 = tc * 32;
    #pragma unroll
    for (int p = 0; p < 4; p++)
        tile[ty + p * 8][tx] = src[(size_t)(r0 + ty + p * 8) * C + c0 + tx];
    __syncthreads();
    #pragma unroll
    for (int p = 0; p < 4; p++) {
        int j = ty + p * 8;
        float x = tile[tx][j];
        __nv_bfloat16 h = __float2bfloat16(x);
        size_t o = (size_t)(c0 + j) * R + r0 + tx;
        dh[o] = h;
        dl[o] = __float2bfloat16(x - __bfloat162float(h));
    }
}

__global__ __launch_bounds__(256) void prep_weights(
    const float* __restrict__ gw, const float* __restrict__ ew,
    const float* __restrict__ aw, const float* __restrict__ cw)
{
    int b = blockIdx.x, tid = threadIdx.x;
    if (b < 192) {                       // gat_W: VH x [128,128]
        int z = b >> 4, t = b & 15;
        trans_tile(gw + (size_t)z * Dd * Dd, Dd, Dd,
                   g_gwT_h + (size_t)z * Dd * Dd, g_gwT_l + (size_t)z * Dd * Dd,
                   t >> 2, t & 3, tid);
    } else if (b < 384) {                // enc_W: 3 x [128,512]
        int bb = b - 192; int z = bb >> 6, t = bb & 63;
        trans_tile(ew + (size_t)z * Dd * VDd, Dd, VDd,
                   g_encT_h + (size_t)z * VDd * Dd, g_encT_l + (size_t)z * VDd * Dd,
                   t >> 4, t & 15, tid);
    } else if (b < 576) {                // agg_W: [1536,128]
        int t = b - 384;
        trans_tile(aw, VH * Dd, Dd, g_aggT_h, g_aggT_l, t >> 2, t & 3, tid);
    } else {                             // cls_W: [128,128]
        int t = b - 576;
        trans_tile(cw, Dd, Dd, g_clsT_h, g_clsT_l, t >> 2, t & 3, tid);
    }
}

// ---------------- latent: split + squared norms ----------------
__global__ void prep_latent(const float* __restrict__ x) {
    int w = (blockIdx.x * blockDim.x + threadIdx.x) >> 5;
    int lane = threadIdx.x & 31;
    if (w >= Nn) return;
    float4 r = *(const float4*)(x + (size_t)w * Dd + lane * 4);
    union { __nv_bfloat16 b[4]; uint2 u; } H, L;
    float c[4] = {r.x, r.y, r.z, r.w};
    #pragma unroll
    for (int q = 0; q < 4; q++) {
        H.b[q] = __float2bfloat16(c[q]);
        L.b[q] = __float2bfloat16(c[q] - __bfloat162float(H.b[q]));
    }
    *(uint2*)(g_lat_h + (size_t)w * Dd + lane * 4) = H.u;
    *(uint2*)(g_lat_l + (size_t)w * Dd + lane * 4) = L.u;
    float s = c[0]*c[0] + c[1]*c[1] + c[2]*c[2] + c[3]*c[3];
    #pragma unroll
    for (int o = 16; o; o >>= 1) s += __shfl_xor_sync(0xffffffffu, s, o);
    if (lane == 0) g_sq[w] = s;
}

#define MMA_BF16(c, a0, a1, a2, a3, b0, b1) \
    asm volatile("mma.sync.aligned.m16n8k16.row.col.f32.bf16.bf16.f32 " \
                 "{%0,%1,%2,%3}, {%4,%5,%6,%7}, {%8,%9}, {%0,%1,%2,%3};" \
                 : "+f"((c)[0]), "+f"((c)[1]), "+f"((c)[2]), "+f"((c)[3]) \
                 : "r"(a0), "r"(a1), "r"(a2), "r"(a3), "r"(b0), "r"(b1))

// =====================================================================
// bf16 split-compensated tensor-core GEMM.
// MODE: 0 plain, 1 +bias[col], 3 dist epilogue,
//       4 plain + fused f1/f2 row-dots (bias = gat_a[z]),
//       5 +bias, elu, row log_softmax fused (writes final output)
// =====================================================================
template <int MODE>
__global__ __launch_bounds__(256) void bmma_kernel(
    const __nv_bfloat16* __restrict__ Ah, const __nv_bfloat16* __restrict__ Al,
    const __nv_bfloat16* __restrict__ Bh, const __nv_bfloat16* __restrict__ Bl,
    float* __restrict__ C, const float* __restrict__ bias,
    int Kdim, int lda, int ldb, int ldc,
    long zA, long zB, long zC, long zBias)
{
    __shared__ __nv_bfloat16 Ash[128][40];
    __shared__ __nv_bfloat16 Asl[128][40];
    __shared__ __nv_bfloat16 Bsh[128][40];
    __shared__ __nv_bfloat16 Bsl[128][40];

    const __nv_bfloat16* Ahb = Ah + (size_t)blockIdx.z * zA;
    const __nv_bfloat16* Alb = Al + (size_t)blockIdx.z * zA;
    const __nv_bfloat16* Bhb = Bh + (size_t)blockIdx.z * zB;
    const __nv_bfloat16* Blb = Bl + (size_t)blockIdx.z * zB;
    float* Cb = C + (size_t)blockIdx.z * zC;
    const float* biasb = bias ? bias + (size_t)blockIdx.z * zBias : nullptr;

    const int bm = blockIdx.y * 128, bn = blockIdx.x * 128;
    const int tid = threadIdx.x;
    const int wid = tid >> 5, lane = tid & 31;
    const int wm = wid >> 2, wn = wid & 3;       // 2 x 4 warp grid
    const int gr = lane >> 2, ct = lane & 3;

    const int r0 = tid >> 2;            // 0..63
    const int cv = (tid & 3) * 8;       // 0,8,16,24

    float acc[4][4][4];
    #pragma unroll
    for (int mt = 0; mt < 4; mt++)
        #pragma unroll
        for (int nt = 0; nt < 4; nt++)
            #pragma unroll
            for (int q = 0; q < 4; q++) acc[mt][nt][q] = 0.f;

    const int T = Kdim >> 5;
    for (int t = 0; t < T; t++) {
        const int k0 = t * 32;
        uint4 gah0 = *(const uint4*)(Ahb + (size_t)(bm + r0) * lda + k0 + cv);
        uint4 gah1 = *(const uint4*)(Ahb + (size_t)(bm + r0 + 64) * lda + k0 + cv);
        uint4 gal0 = *(const uint4*)(Alb + (size_t)(bm + r0) * lda + k0 + cv);
        uint4 gal1 = *(const uint4*)(Alb + (size_t)(bm + r0 + 64) * lda + k0 + cv);
        uint4 gbh0 = *(const uint4*)(Bhb + (size_t)(bn + r0) * ldb + k0 + cv);
        uint4 gbh1 = *(const uint4*)(Bhb + (size_t)(bn + r0 + 64) * ldb + k0 + cv);
        uint4 gbl0 = *(const uint4*)(Blb + (size_t)(bn + r0) * ldb + k0 + cv);
        uint4 gbl1 = *(const uint4*)(Blb + (size_t)(bn + r0 + 64) * ldb + k0 + cv);

        __syncthreads();
        *(uint4*)&Ash[r0][cv] = gah0;  *(uint4*)&Ash[r0 + 64][cv] = gah1;
        *(uint4*)&Asl[r0][cv] = gal0;  *(uint4*)&Asl[r0 + 64][cv] = gal1;
        *(uint4*)&Bsh[r0][cv] = gbh0;  *(uint4*)&Bsh[r0 + 64][cv] = gbh1;
        *(uint4*)&Bsl[r0][cv] = gbl0;  *(uint4*)&Bsl[r0 + 64][cv] = gbl1;
        __syncthreads();

        #pragma unroll
        for (int kk = 0; kk < 32; kk += 16) {
            uint32_t bh[4][2], bl[4][2];
            #pragma unroll
            for (int nt = 0; nt < 4; nt++) {
                int n = wn * 32 + nt * 8 + gr;
                bh[nt][0] = *(const uint32_t*)&Bsh[n][kk + ct * 2];
                bh[nt][1] = *(const uint32_t*)&Bsh[n][kk + ct * 2 + 8];
                bl[nt][0] = *(const uint32_t*)&Bsl[n][kk + ct * 2];
                bl[nt][1] = *(const uint32_t*)&Bsl[n][kk + ct * 2 + 8];
            }
            #pragma unroll
            for (int mt = 0; mt < 4; mt++) {
                int rA = wm * 64 + mt * 16 + gr;
                uint32_t ah0 = *(const uint32_t*)&Ash[rA][kk + ct * 2];
                uint32_t ah1 = *(const uint32_t*)&Ash[rA + 8][kk + ct * 2];
                uint32_t ah2 = *(const uint32_t*)&Ash[rA][kk + ct * 2 + 8];
                uint32_t ah3 = *(const uint32_t*)&Ash[rA + 8][kk + ct * 2 + 8];
                uint32_t al0 = *(const uint32_t*)&Asl[rA][kk + ct * 2];
                uint32_t al1 = *(const uint32_t*)&Asl[rA + 8][kk + ct * 2];
                uint32_t al2 = *(const uint32_t*)&Asl[rA][kk + ct * 2 + 8];
                uint32_t al3 = *(const uint32_t*)&Asl[rA + 8][kk + ct * 2 + 8];
                #pragma unroll
                for (int nt = 0; nt < 4; nt++) {
                    MMA_BF16(acc[mt][nt], ah0, ah1, ah2, ah3, bh[nt][0], bh[nt][1]);
                    MMA_BF16(acc[mt][nt], ah0, ah1, ah2, ah3, bl[nt][0], bl[nt][1]);
                    MMA_BF16(acc[mt][nt], al0, al1, al2, al3, bh[nt][0], bh[nt][1]);
                }
            }
        }
    }

    // ---- standard store (all modes except 5) ----
    if (MODE != 5) {
        #pragma unroll
        for (int mt = 0; mt < 4; mt++) {
            int row = bm + wm * 64 + mt * 16 + gr;
            #pragma unroll
            for (int nt = 0; nt < 4; nt++) {
                int col = bn + wn * 32 + nt * 8 + ct * 2;
                float v0 = acc[mt][nt][0], v1 = acc[mt][nt][1];
                float v2 = acc[mt][nt][2], v3 = acc[mt][nt][3];
                if (MODE == 1) {
                    float b0 = biasb[col], b1 = biasb[col + 1];
                    v0 += b0; v1 += b1; v2 += b0; v3 += b1;
                } else if (MODE == 3) {
                    float sr0 = bias[row], sr1 = bias[row + 8];
                    float sc0 = bias[col], sc1 = bias[col + 1];
                    v0 = sr0 + sc0 - 2.f * v0;
                    v1 = sr0 + sc1 - 2.f * v1;
                    v2 = sr1 + sc0 - 2.f * v2;
                    v3 = sr1 + sc1 - 2.f * v3;
                }
                *(float2*)(Cb + (size_t)row * ldc + col) = make_float2(v0, v1);
                *(float2*)(Cb + (size_t)(row + 8) * ldc + col) = make_float2(v2, v3);
            }
        }
    }

    // ---- MODE 4: fused f1/f2 row-dots (requires grid.x == 1, ldc == Dd) ----
    if (MODE == 4) {
        __shared__ float sf1[4][128];
        __shared__ float sf2[4][128];
        float a1c[4][2], a2c[4][2];
        #pragma unroll
        for (int nt = 0; nt < 4; nt++) {
            int col = bn + wn * 32 + nt * 8 + ct * 2;
            a1c[nt][0] = biasb[col];      a1c[nt][1] = biasb[col + 1];
            a2c[nt][0] = biasb[Dd + col]; a2c[nt][1] = biasb[Dd + col + 1];
        }
        float p1[8], p2[8];
        #pragma unroll
        for (int ri = 0; ri < 8; ri++) {
            int mt = ri >> 1, h2 = ri & 1;
            float s1 = 0.f, s2 = 0.f;
            #pragma unroll
            for (int nt = 0; nt < 4; nt++) {
                float v0 = acc[mt][nt][h2 * 2 + 0], v1 = acc[mt][nt][h2 * 2 + 1];
                s1 += v0 * a1c[nt][0] + v1 * a1c[nt][1];
                s2 += v0 * a2c[nt][0] + v1 * a2c[nt][1];
            }
            p1[ri] = s1; p2[ri] = s2;
        }
        #pragma unroll
        for (int ri = 0; ri < 8; ri++) {
            p1[ri] += __shfl_xor_sync(0xffffffffu, p1[ri], 1);
            p1[ri] += __shfl_xor_sync(0xffffffffu, p1[ri], 2);
            p2[ri] += __shfl_xor_sync(0xffffffffu, p2[ri], 1);
            p2[ri] += __shfl_xor_sync(0xffffffffu, p2[ri], 2);
        }
        if (ct == 0) {
            #pragma unroll
            for (int ri = 0; ri < 8; ri++) {
                int rl = wm * 64 + (ri >> 1) * 16 + gr + (ri & 1) * 8;
                sf1[wn][rl] = p1[ri];
                sf2[wn][rl] = p2[ri];
            }
        }
        __syncthreads();
        if (tid < 128) {
            float f1 = sf1[0][tid] + sf1[1][tid] + sf1[2][tid] + sf1[3][tid];
            float f2 = sf2[0][tid] + sf2[1][tid] + sf2[2][tid] + sf2[3][tid];
            g_f1[(size_t)blockIdx.z * Nn + bm + tid] = f1;
            g_f2[(size_t)blockIdx.z * Nn + bm + tid] = f2;
        }
    }

    // ---- MODE 5: bias + elu + row log_softmax, final store ----
    if (MODE == 5) {
        __shared__ float sred[4][128];
        __shared__ float srow[128];
        #pragma unroll
        for (int mt = 0; mt < 4; mt++)
            #pragma unroll
            for (int nt = 0; nt < 4; nt++) {
                int col = bn + wn * 32 + nt * 8 + ct * 2;
                float b0 = biasb[col], b1 = biasb[col + 1];
                acc[mt][nt][0] += b0; acc[mt][nt][1] += b1;
                acc[mt][nt][2] += b0; acc[mt][nt][3] += b1;
                #pragma unroll
                for (int q = 0; q < 4; q++) {
                    float v = acc[mt][nt][q];
                    acc[mt][nt][q] = (v > 0.f) ? v : expm1f(v);
                }
            }
        // row max
        float rm[8];
        #pragma unroll
        for (int ri = 0; ri < 8; ri++) {
            int mt = ri >> 1, h2 = ri & 1;
            float m = -FLT_MAX;
            #pragma unroll
            for (int nt = 0; nt < 4; nt++)
                m = fmaxf(m, fmaxf(acc[mt][nt][h2 * 2], acc[mt][nt][h2 * 2 + 1]));
            rm[ri] = m;
        }
        #pragma unroll
        for (int ri = 0; ri < 8; ri++) {
            rm[ri] = fmaxf(rm[ri], __shfl_xor_sync(0xffffffffu, rm[ri], 1));
            rm[ri] = fmaxf(rm[ri], __shfl_xor_sync(0xffffffffu, rm[ri], 2));
        }
        if (ct == 0)
            #pragma unroll
            for (int ri = 0; ri < 8; ri++)
                sred[wn][wm * 64 + (ri >> 1) * 16 + gr + (ri & 1) * 8] = rm[ri];
        __syncthreads();
        if (tid < 128)
            srow[tid] = fmaxf(fmaxf(sred[0][tid], sred[1][tid]),
                              fmaxf(sred[2][tid], sred[3][tid]));
        __syncthreads();
        // sum exp
        float se[8];
        #pragma unroll
        for (int ri = 0; ri < 8; ri++) {
            int mt = ri >> 1, h2 = ri & 1;
            int rl = wm * 64 + mt * 16 + gr + h2 * 8;
            float m = srow[rl];
            float s = 0.f;
            #pragma unroll
            for (int nt = 0; nt < 4; nt++)
                s += expf(acc[mt][nt][h2 * 2] - m) + expf(acc[mt][nt][h2 * 2 + 1] - m);
            se[ri] = s;
        }
        #pragma unroll
        for (int ri = 0; ri < 8; ri++) {
            se[ri] += __shfl_xor_sync(0xffffffffu, se[ri], 1);
            se[ri] += __shfl_xor_sync(0xffffffffu, se[ri], 2);
        }
        __syncthreads();
        if (ct == 0)
            #pragma unroll
            for (int ri = 0; ri < 8; ri++)
                sred[wn][wm * 64 + (ri >> 1) * 16 + gr + (ri & 1) * 8] = se[ri];
        __syncthreads();
        if (tid < 128)
            srow[tid] += logf(sred[0][tid] + sred[1][tid] + sred[2][tid] + sred[3][tid]);
        __syncthreads();
        #pragma unroll
        for (int mt = 0; mt < 4; mt++) {
            #pragma unroll
            for (int nt = 0; nt < 4; nt++) {
                int col = bn + wn * 32 + nt * 8 + ct * 2;
                int rl0 = wm * 64 + mt * 16 + gr;
                float l0 = srow[rl0], l1 = srow[rl0 + 8];
                *(float2*)(Cb + (size_t)(bm + rl0) * ldc + col) =
                    make_float2(acc[mt][nt][0] - l0, acc[mt][nt][1] - l0);
                *(float2*)(Cb + (size_t)(bm + rl0 + 8) * ldc + col) =
                    make_float2(acc[mt][nt][2] - l1, acc[mt][nt][3] - l1);
            }
        }
    }
}

// ---------------- per-row top-K: one warp per row, register top-10 ----------------
__global__ void knn_kernel() {
    int w = (blockIdx.x * blockDim.x + threadIdx.x) >> 5;
    int lane = threadIdx.x & 31;
    if (w >= Nn) return;
    const float* dr = g_dist + (size_t)w * Nn;

    float val[Kk];
    int   idx[Kk];
    #pragma unroll
    for (int p = 0; p < Kk; p++) { val[p] = FLT_MAX; idx[p] = 0x7fffffff; }

    for (int t = 0; t < Nn / 32; t++) {
        int j = lane + t * 32;
        float d = dr[j];
        if (d < val[Kk - 1]) {
            #pragma unroll
            for (int p = Kk - 1; p >= 1; p--) {
                if (d < val[p]) {
                    bool sh = d < val[p - 1];
                    val[p] = sh ? val[p - 1] : d;
                    idx[p] = sh ? idx[p - 1] : j;
                }
            }
            if (d < val[0]) { val[0] = d; idx[0] = j; }
        }
    }

    #pragma unroll 1
    for (int r = 0; r < Kk; r++) {
        float bv = val[0]; int bi = idx[0];
        #pragma unroll
        for (int o = 16; o; o >>= 1) {
            float ov = __shfl_xor_sync(0xffffffffu, bv, o);
            int   oi = __shfl_xor_sync(0xffffffffu, bi, o);
            if (ov < bv || (ov == bv && oi < bi)) { bv = ov; bi = oi; }
        }
        if (lane == 0) g_knn[w * Kk + r] = bi;
        if (val[0] == bv && idx[0] == bi) {
            #pragma unroll
            for (int p = 0; p < Kk - 1; p++) { val[p] = val[p + 1]; idx[p] = idx[p + 1]; }
            val[Kk - 1] = FLT_MAX; idx[Kk - 1] = 0x7fffffff;
        }
    }
}

// ---------------- sparse GAT attention -> split bf16 meta ----------------
__global__ void attn_kernel(const float* __restrict__ fm) {
    int w = (blockIdx.x * blockDim.x + threadIdx.x) >> 5;
    int lane = threadIdx.x & 31;
    if (w >= VH * Nn) return;
    int i = w % Nn;
    int vh = w / Nn;
    int v = vh / Hh;

    int nb = -1;
    bool valid = false;
    if (lane < Kk) {
        nb = g_knn[i * Kk + lane];
        valid = (nb == i) || (fm[(size_t)i * Vv + v] > 0.f && fm[(size_t)nb * Vv + v] > 0.f);
    }
    unsigned hasSelf = __ballot_sync(0xffffffffu, lane < Kk && nb == i);
    if (hasSelf == 0 && lane == Kk) { nb = i; valid = true; }

    float e = -FLT_MAX;
    if (valid) {
        float x = g_f1[vh * Nn + i] + g_f2[vh * Nn + nb];
        e = (x >= 0.f) ? x : LRELU_ALPHA * x;
    }
    float m = e;
    #pragma unroll
    for (int o = 16; o; o >>= 1) m = fmaxf(m, __shfl_xor_sync(0xffffffffu, m, o));
    float wt = valid ? expf(e - m) : 0.f;
    float s = wt;
    #pragma unroll
    for (int o = 16; o; o >>= 1) s += __shfl_xor_sync(0xffffffffu, s, o);
    float att = wt / s;

    const float* base = g_Wh + (size_t)vh * Nn * Dd;
    float acc[4] = {0.f, 0.f, 0.f, 0.f};
    #pragma unroll
    for (int j = 0; j <= Kk; j++) {
        float a = __shfl_sync(0xffffffffu, att, j);
        int nj = __shfl_sync(0xffffffffu, nb, j);
        if (a != 0.f) {
            float4 wv = *(const float4*)(base + (size_t)nj * Dd + lane * 4);
            acc[0] = fmaf(a, wv.x, acc[0]);
            acc[1] = fmaf(a, wv.y, acc[1]);
            acc[2] = fmaf(a, wv.z, acc[2]);
            acc[3] = fmaf(a, wv.w, acc[3]);
        }
    }
    union { __nv_bfloat16 b[4]; uint2 u; } H, L;
    #pragma unroll
    for (int q = 0; q < 4; q++) {
        H.b[q] = __float2bfloat16(acc[q]);
        L.b[q] = __float2bfloat16(acc[q] - __bfloat162float(H.b[q]));
    }
    size_t dst = (size_t)i * (VH * Dd) + (size_t)vh * Dd + lane * 4;
    *(uint2*)(g_meta_h + dst) = H.u;
    *(uint2*)(g_meta_l + dst) = L.u;
}

// ---------------- split-K reduce for agg + bias -> sem fp32 + bf16 split ----------------
__global__ void agg_reduce_kernel(const float* __restrict__ bias, float* __restrict__ sem) {
    int i = blockIdx.x * blockDim.x + threadIdx.x;
    if (i >= Nn * Dd) return;
    float s = 0.f;
    #pragma unroll
    for (int p = 0; p < AGG_SPLITS; p++) s += g_part[(size_t)p * Nn * Dd + i];
    s += bias[i & (Dd - 1)];
    sem[i] = s;
    __nv_bfloat16 h = __float2bfloat16(s);
    g_sem_h[i] = h;
    g_sem_l[i] = __float2bfloat16(s - __bfloat162float(h));
}

// ---------------- launch ----------------
extern "C" void kernel_launch(void* const* d_in, const int* in_sizes, int n_in,
                              void* d_out, int out_size) {
    const float* fm     = (const float*)d_in[0];
    const float* latent = (const float*)d_in[1];
    const float* enc_W  = (const float*)d_in[2];
    const float* enc_b  = (const float*)d_in[3];
    const float* gat_W  = (const float*)d_in[4];
    const float* gat_a  = (const float*)d_in[5];
    const float* agg_W  = (const float*)d_in[6];
    const float* agg_b  = (const float*)d_in[7];
    const float* cls_W  = (const float*)d_in[8];
    const float* cls_b  = (const float*)d_in[9];

    float* out  = (float*)d_out;
    float* rec  = out;                                   // [V,N,VD]
    float* outp = out + (size_t)Vv * Nn * VDd;           // [N,D]
    float* sem  = outp + (size_t)Nn * Dd;                // [N,D]

    float *p_sq, *p_dist, *p_Wh, *p_part;
    cudaGetSymbolAddress((void**)&p_sq, g_sq);
    cudaGetSymbolAddress((void**)&p_dist, g_dist);
    cudaGetSymbolAddress((void**)&p_Wh, g_Wh);
    cudaGetSymbolAddress((void**)&p_part, g_part);

    __nv_bfloat16 *lat_h, *lat_l, *gwT_h, *gwT_l, *encT_h, *encT_l;
    __nv_bfloat16 *aggT_h, *aggT_l, *clsT_h, *clsT_l, *meta_h, *meta_l, *sem_h, *sem_l;
    cudaGetSymbolAddress((void**)&lat_h, g_lat_h);   cudaGetSymbolAddress((void**)&lat_l, g_lat_l);
    cudaGetSymbolAddress((void**)&gwT_h, g_gwT_h);   cudaGetSymbolAddress((void**)&gwT_l, g_gwT_l);
    cudaGetSymbolAddress((void**)&encT_h, g_encT_h); cudaGetSymbolAddress((void**)&encT_l, g_encT_l);
    cudaGetSymbolAddress((void**)&aggT_h, g_aggT_h); cudaGetSymbolAddress((void**)&aggT_l, g_aggT_l);
    cudaGetSymbolAddress((void**)&clsT_h, g_clsT_h); cudaGetSymbolAddress((void**)&clsT_l, g_clsT_l);
    cudaGetSymbolAddress((void**)&meta_h, g_meta_h); cudaGetSymbolAddress((void**)&meta_l, g_meta_l);
    cudaGetSymbolAddress((void**)&sem_h, g_sem_h);   cudaGetSymbolAddress((void**)&sem_l, g_sem_l);

    // 1. prep: weight transposes+splits (one kernel), latent split+sq
    prep_weights<<<592, 256>>>(gat_W, enc_W, agg_W, cls_W);
    prep_latent<<<Nn / 8, 256>>>(latent);
    // 2. dist = sq_i + sq_j - 2 * latent @ latent^T
    bmma_kernel<3><<<dim3(Nn / 128, Nn / 128, 1), 256>>>(
        lat_h, lat_l, lat_h, lat_l, p_dist, p_sq, Dd, Dd, Dd, Nn, 0, 0, 0, 0);
    // 3. top-K neighbors per row
    knn_kernel<<<Nn / 8, 256>>>();
    // 4. Wh[v,h] = latent @ gat_W[v,h]  (+ fused f1/f2)
    bmma_kernel<4><<<dim3(1, Nn / 128, VH), 256>>>(
        lat_h, lat_l, gwT_h, gwT_l, p_Wh, gat_a, Dd, Dd, Dd, Dd,
        0, (long)Dd * Dd, (long)Nn * Dd, (long)2 * Dd);
    // 5. sparse attention -> split bf16 meta
    attn_kernel<<<VH * Nn / 8, 256>>>(fm);
    // 6. rec[v] = latent @ enc_W[v] + enc_b[v]
    bmma_kernel<1><<<dim3(VDd / 128, Nn / 128, Vv), 256>>>(
        lat_h, lat_l, encT_h, encT_l, rec, enc_b, Dd, Dd, Dd, VDd,
        0, (long)VDd * Dd, (long)Nn * VDd, (long)VDd);
    // 7. semantic partials = meta @ agg_W (split-K)
    bmma_kernel<0><<<dim3(1, Nn / 128, AGG_SPLITS), 256>>>(
        meta_h, meta_l, aggT_h, aggT_l, p_part, nullptr,
        AGG_KCHUNK, VH * Dd, VH * Dd, Dd,
        (long)AGG_KCHUNK, (long)AGG_KCHUNK, (long)Nn * Dd, 0);
    // 8. reduce partials + bias -> semantic (fp32 out + bf16 split)
    agg_reduce_kernel<<<(Nn * Dd) / 256, 256>>>(agg_b, sem);
    // 9. output = log_softmax(elu(sem @ cls_W + cls_b))  (fully fused)
    bmma_kernel<5><<<dim3(1, Nn / 128, 1), 256>>>(
        sem_h, sem_l, clsT_h, clsT_l, outp, cls_b, Dd, Dd, Dd, Dd, 0, 0, 0, 0);
}

// round 6
// speedup vs baseline: 2.1222x; 1.0389x over previous
#include <cuda_runtime.h>
#include <cuda_bf16.h>
#include <cstdint>
#include <math.h>
#include <float.h>

#define Nn 2048
#define Dd 128
#define Vv 3
#define Hh 4
#define VDd 512
#define Kk 10
#define VH (Vv*Hh)
#define LRELU_ALPHA 0.2f
#define AGG_SPLITS 8
#define AGG_KCHUNK ((VH*Dd)/AGG_SPLITS)   // 192

// ---------------- scratch (no allocations allowed) ----------------
__device__ float g_sq[Nn];
__device__ float g_dist[(size_t)Nn * Nn];
__device__ int   g_knn[Nn * Kk];
__device__ float g_Wh[(size_t)VH * Nn * Dd];
__device__ float g_f1[VH * Nn];
__device__ float g_f2[VH * Nn];
__device__ float g_part[(size_t)AGG_SPLITS * Nn * Dd];

// bf16 split operands
__device__ __nv_bfloat16 g_lat_h[Nn * Dd],  g_lat_l[Nn * Dd];
__device__ __nv_bfloat16 g_gwT_h[VH * Dd * Dd], g_gwT_l[VH * Dd * Dd];
__device__ __nv_bfloat16 g_encT_h[Vv * VDd * Dd], g_encT_l[Vv * VDd * Dd];
__device__ __nv_bfloat16 g_aggT_h[Dd * VH * Dd], g_aggT_l[Dd * VH * Dd];
__device__ __nv_bfloat16 g_clsT_h[Dd * Dd], g_clsT_l[Dd * Dd];
__device__ __nv_bfloat16 g_meta_h[(size_t)Nn * VH * Dd], g_meta_l[(size_t)Nn * VH * Dd];
__device__ __nv_bfloat16 g_sem_h[Nn * Dd], g_sem_l[Nn * Dd];

// ---------------- coalesced transpose + split (32x32 tiles) ----------------
__device__ __forceinline__ void trans_tile(
    const float* __restrict__ src, int R, int C,
    __nv_bfloat16* __restrict__ dh, __nv_bfloat16* __restrict__ dl,
    int tr, int tc, int tid)
{
    __shared__ float tile[32][33];
    int tx = tid & 31, ty = tid >> 5;   // ty 0..7
    int r0 = tr * 32, c0 = tc * 32;
    #pragma unroll
    for (int p = 0; p < 4; p++)
        tile[ty + p * 8][tx] = src[(size_t)(r0 + ty + p * 8) * C + c0 + tx];
    __syncthreads();
    #pragma unroll
    for (int p = 0; p < 4; p++) {
        int j = ty + p * 8;
        float x = tile[tx][j];
        __nv_bfloat16 h = __float2bfloat16(x);
        size_t o = (size_t)(c0 + j) * R + r0 + tx;
        dh[o] = h;
        dl[o] = __float2bfloat16(x - __bfloat162float(h));
    }
}

__global__ __launch_bounds__(256) void prep_weights(
    const float* __restrict__ gw, const float* __restrict__ ew,
    const float* __restrict__ aw, const float* __restrict__ cw)
{
    int b = blockIdx.x, tid = threadIdx.x;
    if (b < 192) {                       // gat_W: VH x [128,128]
        int z = b >> 4, t = b & 15;
        trans_tile(gw + (size_t)z * Dd * Dd, Dd, Dd,
                   g_gwT_h + (size_t)z * Dd * Dd, g_gwT_l + (size_t)z * Dd * Dd,
                   t >> 2, t & 3, tid);
    } else if (b < 384) {                // enc_W: 3 x [128,512]
        int bb = b - 192; int z = bb >> 6, t = bb & 63;
        trans_tile(ew + (size_t)z * Dd * VDd, Dd, VDd,
                   g_encT_h + (size_t)z * VDd * Dd, g_encT_l + (size_t)z * VDd * Dd,
                   t >> 4, t & 15, tid);
    } else if (b < 576) {                // agg_W: [1536,128]
        int t = b - 384;
        trans_tile(aw, VH * Dd, Dd, g_aggT_h, g_aggT_l, t >> 2, t & 3, tid);
    } else {                             // cls_W: [128,128]
        int t = b - 576;
        trans_tile(cw, Dd, Dd, g_clsT_h, g_clsT_l, t >> 2, t & 3, tid);
    }
}

// ---------------- latent: split + squared norms ----------------
__global__ void prep_latent(const float* __restrict__ x) {
    int w = (blockIdx.x * blockDim.x + threadIdx.x) >> 5;
    int lane = threadIdx.x & 31;
    if (w >= Nn) return;
    float4 r = *(const float4*)(x + (size_t)w * Dd + lane * 4);
    union { __nv_bfloat16 b[4]; uint2 u; } H, L;
    float c[4] = {r.x, r.y, r.z, r.w};
    #pragma unroll
    for (int q = 0; q < 4; q++) {
        H.b[q] = __float2bfloat16(c[q]);
        L.b[q] = __float2bfloat16(c[q] - __bfloat162float(H.b[q]));
    }
    *(uint2*)(g_lat_h + (size_t)w * Dd + lane * 4) = H.u;
    *(uint2*)(g_lat_l + (size_t)w * Dd + lane * 4) = L.u;
    float s = c[0]*c[0] + c[1]*c[1] + c[2]*c[2] + c[3]*c[3];
    #pragma unroll
    for (int o = 16; o; o >>= 1) s += __shfl_xor_sync(0xffffffffu, s, o);
    if (lane == 0) g_sq[w] = s;
}

#define MMA_BF16(c, a0, a1, a2, a3, b0, b1) \
    asm volatile("mma.sync.aligned.m16n8k16.row.col.f32.bf16.bf16.f32 " \
                 "{%0,%1,%2,%3}, {%4,%5,%6,%7}, {%8,%9}, {%0,%1,%2,%3};" \
                 : "+f"((c)[0]), "+f"((c)[1]), "+f"((c)[2]), "+f"((c)[3]) \
                 : "r"(a0), "r"(a1), "r"(a2), "r"(a3), "r"(b0), "r"(b1))

// =====================================================================
// bf16 split-compensated tensor-core GEMM.
// MODE: 0 plain, 1 +bias[col], 3 dist epilogue,
//       4 plain + fused f1/f2 row-dots (bias = gat_a[z]),
//       5 +bias, elu, row log_softmax fused (writes final output)
// =====================================================================
template <int MODE>
__global__ __launch_bounds__(256) void bmma_kernel(
    const __nv_bfloat16* __restrict__ Ah, const __nv_bfloat16* __restrict__ Al,
    const __nv_bfloat16* __restrict__ Bh, const __nv_bfloat16* __restrict__ Bl,
    float* __restrict__ C, const float* __restrict__ bias,
    int Kdim, int lda, int ldb, int ldc,
    long zA, long zB, long zC, long zBias)
{
    __shared__ __nv_bfloat16 Ash[128][40];
    __shared__ __nv_bfloat16 Asl[128][40];
    __shared__ __nv_bfloat16 Bsh[128][40];
    __shared__ __nv_bfloat16 Bsl[128][40];

    const __nv_bfloat16* Ahb = Ah + (size_t)blockIdx.z * zA;
    const __nv_bfloat16* Alb = Al + (size_t)blockIdx.z * zA;
    const __nv_bfloat16* Bhb = Bh + (size_t)blockIdx.z * zB;
    const __nv_bfloat16* Blb = Bl + (size_t)blockIdx.z * zB;
    float* Cb = C + (size_t)blockIdx.z * zC;
    const float* biasb = bias ? bias + (size_t)blockIdx.z * zBias : nullptr;

    const int bm = blockIdx.y * 128, bn = blockIdx.x * 128;
    const int tid = threadIdx.x;
    const int wid = tid >> 5, lane = tid & 31;
    const int wm = wid >> 2, wn = wid & 3;       // 2 x 4 warp grid
    const int gr = lane >> 2, ct = lane & 3;

    const int r0 = tid >> 2;            // 0..63
    const int cv = (tid & 3) * 8;       // 0,8,16,24

    float acc[4][4][4];
    #pragma unroll
    for (int mt = 0; mt < 4; mt++)
        #pragma unroll
        for (int nt = 0; nt < 4; nt++)
            #pragma unroll
            for (int q = 0; q < 4; q++) acc[mt][nt][q] = 0.f;

    const int T = Kdim >> 5;
    for (int t = 0; t < T; t++) {
        const int k0 = t * 32;
        uint4 gah0 = *(const uint4*)(Ahb + (size_t)(bm + r0) * lda + k0 + cv);
        uint4 gah1 = *(const uint4*)(Ahb + (size_t)(bm + r0 + 64) * lda + k0 + cv);
        uint4 gal0 = *(const uint4*)(Alb + (size_t)(bm + r0) * lda + k0 + cv);
        uint4 gal1 = *(const uint4*)(Alb + (size_t)(bm + r0 + 64) * lda + k0 + cv);
        uint4 gbh0 = *(const uint4*)(Bhb + (size_t)(bn + r0) * ldb + k0 + cv);
        uint4 gbh1 = *(const uint4*)(Bhb + (size_t)(bn + r0 + 64) * ldb + k0 + cv);
        uint4 gbl0 = *(const uint4*)(Blb + (size_t)(bn + r0) * ldb + k0 + cv);
        uint4 gbl1 = *(const uint4*)(Blb + (size_t)(bn + r0 + 64) * ldb + k0 + cv);

        __syncthreads();
        *(uint4*)&Ash[r0][cv] = gah0;  *(uint4*)&Ash[r0 + 64][cv] = gah1;
        *(uint4*)&Asl[r0][cv] = gal0;  *(uint4*)&Asl[r0 + 64][cv] = gal1;
        *(uint4*)&Bsh[r0][cv] = gbh0;  *(uint4*)&Bsh[r0 + 64][cv] = gbh1;
        *(uint4*)&Bsl[r0][cv] = gbl0;  *(uint4*)&Bsl[r0 + 64][cv] = gbl1;
        __syncthreads();

        #pragma unroll
        for (int kk = 0; kk < 32; kk += 16) {
            uint32_t bh[4][2], bl[4][2];
            #pragma unroll
            for (int nt = 0; nt < 4; nt++) {
                int n = wn * 32 + nt * 8 + gr;
                bh[nt][0] = *(const uint32_t*)&Bsh[n][kk + ct * 2];
                bh[nt][1] = *(const uint32_t*)&Bsh[n][kk + ct * 2 + 8];
                bl[nt][0] = *(const uint32_t*)&Bsl[n][kk + ct * 2];
                bl[nt][1] = *(const uint32_t*)&Bsl[n][kk + ct * 2 + 8];
            }
            #pragma unroll
            for (int mt = 0; mt < 4; mt++) {
                int rA = wm * 64 + mt * 16 + gr;
                uint32_t ah0 = *(const uint32_t*)&Ash[rA][kk + ct * 2];
                uint32_t ah1 = *(const uint32_t*)&Ash[rA + 8][kk + ct * 2];
                uint32_t ah2 = *(const uint32_t*)&Ash[rA][kk + ct * 2 + 8];
                uint32_t ah3 = *(const uint32_t*)&Ash[rA + 8][kk + ct * 2 + 8];
                uint32_t al0 = *(const uint32_t*)&Asl[rA][kk + ct * 2];
                uint32_t al1 = *(const uint32_t*)&Asl[rA + 8][kk + ct * 2];
                uint32_t al2 = *(const uint32_t*)&Asl[rA][kk + ct * 2 + 8];
                uint32_t al3 = *(const uint32_t*)&Asl[rA + 8][kk + ct * 2 + 8];
                #pragma unroll
                for (int nt = 0; nt < 4; nt++) {
                    MMA_BF16(acc[mt][nt], ah0, ah1, ah2, ah3, bh[nt][0], bh[nt][1]);
                    MMA_BF16(acc[mt][nt], ah0, ah1, ah2, ah3, bl[nt][0], bl[nt][1]);
                    MMA_BF16(acc[mt][nt], al0, al1, al2, al3, bh[nt][0], bh[nt][1]);
                }
            }
        }
    }

    // ---- standard store (all modes except 5) ----
    if (MODE != 5) {
        #pragma unroll
        for (int mt = 0; mt < 4; mt++) {
            int row = bm + wm * 64 + mt * 16 + gr;
            #pragma unroll
            for (int nt = 0; nt < 4; nt++) {
                int col = bn + wn * 32 + nt * 8 + ct * 2;
                float v0 = acc[mt][nt][0], v1 = acc[mt][nt][1];
                float v2 = acc[mt][nt][2], v3 = acc[mt][nt][3];
                if (MODE == 1) {
                    float b0 = biasb[col], b1 = biasb[col + 1];
                    v0 += b0; v1 += b1; v2 += b0; v3 += b1;
                } else if (MODE == 3) {
                    float sr0 = bias[row], sr1 = bias[row + 8];
                    float sc0 = bias[col], sc1 = bias[col + 1];
                    v0 = sr0 + sc0 - 2.f * v0;
                    v1 = sr0 + sc1 - 2.f * v1;
                    v2 = sr1 + sc0 - 2.f * v2;
                    v3 = sr1 + sc1 - 2.f * v3;
                }
                *(float2*)(Cb + (size_t)row * ldc + col) = make_float2(v0, v1);
                *(float2*)(Cb + (size_t)(row + 8) * ldc + col) = make_float2(v2, v3);
            }
        }
    }

    // ---- MODE 4: fused f1/f2 row-dots (requires grid.x == 1, ldc == Dd) ----
    if (MODE == 4) {
        __shared__ float sf1[4][128];
        __shared__ float sf2[4][128];
        float a1c[4][2], a2c[4][2];
        #pragma unroll
        for (int nt = 0; nt < 4; nt++) {
            int col = bn + wn * 32 + nt * 8 + ct * 2;
            a1c[nt][0] = biasb[col];      a1c[nt][1] = biasb[col + 1];
            a2c[nt][0] = biasb[Dd + col]; a2c[nt][1] = biasb[Dd + col + 1];
        }
        float p1[8], p2[8];
        #pragma unroll
        for (int ri = 0; ri < 8; ri++) {
            int mt = ri >> 1, h2 = ri & 1;
            float s1 = 0.f, s2 = 0.f;
            #pragma unroll
            for (int nt = 0; nt < 4; nt++) {
                float v0 = acc[mt][nt][h2 * 2 + 0], v1 = acc[mt][nt][h2 * 2 + 1];
                s1 += v0 * a1c[nt][0] + v1 * a1c[nt][1];
                s2 += v0 * a2c[nt][0] + v1 * a2c[nt][1];
            }
            p1[ri] = s1; p2[ri] = s2;
        }
        #pragma unroll
        for (int ri = 0; ri < 8; ri++) {
            p1[ri] += __shfl_xor_sync(0xffffffffu, p1[ri], 1);
            p1[ri] += __shfl_xor_sync(0xffffffffu, p1[ri], 2);
            p2[ri] += __shfl_xor_sync(0xffffffffu, p2[ri], 1);
            p2[ri] += __shfl_xor_sync(0xffffffffu, p2[ri], 2);
        }
        if (ct == 0) {
            #pragma unroll
            for (int ri = 0; ri < 8; ri++) {
                int rl = wm * 64 + (ri >> 1) * 16 + gr + (ri & 1) * 8;
                sf1[wn][rl] = p1[ri];
                sf2[wn][rl] = p2[ri];
            }
        }
        __syncthreads();
        if (tid < 128) {
            float f1 = sf1[0][tid] + sf1[1][tid] + sf1[2][tid] + sf1[3][tid];
            float f2 = sf2[0][tid] + sf2[1][tid] + sf2[2][tid] + sf2[3][tid];
            g_f1[(size_t)blockIdx.z * Nn + bm + tid] = f1;
            g_f2[(size_t)blockIdx.z * Nn + bm + tid] = f2;
        }
    }

    // ---- MODE 5: bias + elu + row log_softmax, final store ----
    if (MODE == 5) {
        __shared__ float sred[4][128];
        __shared__ float srow[128];
        #pragma unroll
        for (int mt = 0; mt < 4; mt++)
            #pragma unroll
            for (int nt = 0; nt < 4; nt++) {
                int col = bn + wn * 32 + nt * 8 + ct * 2;
                float b0 = biasb[col], b1 = biasb[col + 1];
                acc[mt][nt][0] += b0; acc[mt][nt][1] += b1;
                acc[mt][nt][2] += b0; acc[mt][nt][3] += b1;
                #pragma unroll
                for (int q = 0; q < 4; q++) {
                    float v = acc[mt][nt][q];
                    acc[mt][nt][q] = (v > 0.f) ? v : expm1f(v);
                }
            }
        // row max
        float rm[8];
        #pragma unroll
        for (int ri = 0; ri < 8; ri++) {
            int mt = ri >> 1, h2 = ri & 1;
            float m = -FLT_MAX;
            #pragma unroll
            for (int nt = 0; nt < 4; nt++)
                m = fmaxf(m, fmaxf(acc[mt][nt][h2 * 2], acc[mt][nt][h2 * 2 + 1]));
            rm[ri] = m;
        }
        #pragma unroll
        for (int ri = 0; ri < 8; ri++) {
            rm[ri] = fmaxf(rm[ri], __shfl_xor_sync(0xffffffffu, rm[ri], 1));
            rm[ri] = fmaxf(rm[ri], __shfl_xor_sync(0xffffffffu, rm[ri], 2));
        }
        if (ct == 0)
            #pragma unroll
            for (int ri = 0; ri < 8; ri++)
                sred[wn][wm * 64 + (ri >> 1) * 16 + gr + (ri & 1) * 8] = rm[ri];
        __syncthreads();
        if (tid < 128)
            srow[tid] = fmaxf(fmaxf(sred[0][tid], sred[1][tid]),
                              fmaxf(sred[2][tid], sred[3][tid]));
        __syncthreads();
        // sum exp
        float se[8];
        #pragma unroll
        for (int ri = 0; ri < 8; ri++) {
            int mt = ri >> 1, h2 = ri & 1;
            int rl = wm * 64 + mt * 16 + gr + h2 * 8;
            float m = srow[rl];
            float s = 0.f;
            #pragma unroll
            for (int nt = 0; nt < 4; nt++)
                s += expf(acc[mt][nt][h2 * 2] - m) + expf(acc[mt][nt][h2 * 2 + 1] - m);
            se[ri] = s;
        }
        #pragma unroll
        for (int ri = 0; ri < 8; ri++) {
            se[ri] += __shfl_xor_sync(0xffffffffu, se[ri], 1);
            se[ri] += __shfl_xor_sync(0xffffffffu, se[ri], 2);
        }
        __syncthreads();
        if (ct == 0)
            #pragma unroll
            for (int ri = 0; ri < 8; ri++)
                sred[wn][wm * 64 + (ri >> 1) * 16 + gr + (ri & 1) * 8] = se[ri];
        __syncthreads();
        if (tid < 128)
            srow[tid] += logf(sred[0][tid] + sred[1][tid] + sred[2][tid] + sred[3][tid]);
        __syncthreads();
        #pragma unroll
        for (int mt = 0; mt < 4; mt++) {
            #pragma unroll
            for (int nt = 0; nt < 4; nt++) {
                int col = bn + wn * 32 + nt * 8 + ct * 2;
                int rl0 = wm * 64 + mt * 16 + gr;
                float l0 = srow[rl0], l1 = srow[rl0 + 8];
                *(float2*)(Cb + (size_t)(bm + rl0) * ldc + col) =
                    make_float2(acc[mt][nt][0] - l0, acc[mt][nt][1] - l0);
                *(float2*)(Cb + (size_t)(bm + rl0 + 8) * ldc + col) =
                    make_float2(acc[mt][nt][2] - l1, acc[mt][nt][3] - l1);
            }
        }
    }
}

// ---------------- per-row top-K: 4 warps per row + merge ----------------
// Block of 256 threads handles 2 rows. Each warp scans a 512-elem quarter
// keeping a register top-10 (strict-less insertion preserves lowest-index on
// ties), pops it sorted into smem, then one warp per row merges 40 candidates.
__global__ __launch_bounds__(256) void knn_kernel() {
    __shared__ float sval[8][Kk];
    __shared__ int   sidx[8][Kk];
    int tid = threadIdx.x;
    int wid = tid >> 5, lane = tid & 31;
    int row = blockIdx.x * 2 + (wid >> 2);
    int quarter = wid & 3;
    const float* dr = g_dist + (size_t)row * Nn + quarter * 512;

    float val[Kk];
    int   idx[Kk];
    #pragma unroll
    for (int p = 0; p < Kk; p++) { val[p] = FLT_MAX; idx[p] = 0x7fffffff; }

    #pragma unroll 4
    for (int t = 0; t < 16; t++) {
        int j = lane + t * 32;
        float d = dr[j];
        if (d < val[Kk - 1]) {
            int gj = quarter * 512 + j;
            #pragma unroll
            for (int p = Kk - 1; p >= 1; p--) {
                if (d < val[p]) {
                    bool sh = d < val[p - 1];
                    val[p] = sh ? val[p - 1] : d;
                    idx[p] = sh ? idx[p - 1] : gj;
                }
            }
            if (d < val[0]) { val[0] = d; idx[0] = gj; }
        }
    }

    // warp pop-10 -> sorted candidates in smem
    #pragma unroll 1
    for (int r = 0; r < Kk; r++) {
        float bv = val[0]; int bi = idx[0];
        #pragma unroll
        for (int o = 16; o; o >>= 1) {
            float ov = __shfl_xor_sync(0xffffffffu, bv, o);
            int   oi = __shfl_xor_sync(0xffffffffu, bi, o);
            if (ov < bv || (ov == bv && oi < bi)) { bv = ov; bi = oi; }
        }
        if (lane == 0) { sval[wid][r] = bv; sidx[wid][r] = bi; }
        if (val[0] == bv && idx[0] == bi) {
            #pragma unroll
            for (int p = 0; p < Kk - 1; p++) { val[p] = val[p + 1]; idx[p] = idx[p + 1]; }
            val[Kk - 1] = FLT_MAX; idx[Kk - 1] = 0x7fffffff;
        }
    }
    __syncthreads();

    // merge 4 x 10 candidates: warps 0 (row A) and 4 (row B)
    if ((wid & 3) == 0) {
        int wbase = wid;              // 0 or 4
        float a = FLT_MAX; int ai = 0x7fffffff;
        float b = FLT_MAX; int bi = 0x7fffffff;
        if (lane < 40) { a = sval[wbase + lane / Kk][lane % Kk]; ai = sidx[wbase + lane / Kk][lane % Kk]; }
        int l2 = lane + 32;
        if (l2 < 40) { b = sval[wbase + l2 / Kk][l2 % Kk]; bi = sidx[wbase + l2 / Kk][l2 % Kk]; }
        #pragma unroll 1
        for (int r = 0; r < Kk; r++) {
            bool useB = (b < a) || (b == a && bi < ai);
            float cv = useB ? b : a;
            int   ci = useB ? bi : ai;
            float mv = cv; int mi = ci;
            #pragma unroll
            for (int o = 16; o; o >>= 1) {
                float ov = __shfl_xor_sync(0xffffffffu, mv, o);
                int   oi = __shfl_xor_sync(0xffffffffu, mi, o);
                if (ov < mv || (ov == mv && oi < mi)) { mv = ov; mi = oi; }
            }
            if (lane == 0) g_knn[row * Kk + r] = mi;
            if (cv == mv && ci == mi) {
                if (useB) { b = FLT_MAX; bi = 0x7fffffff; }
                else      { a = FLT_MAX; ai = 0x7fffffff; }
            }
        }
    }
}

// ---------------- sparse GAT attention -> split bf16 meta ----------------
__global__ void attn_kernel(const float* __restrict__ fm) {
    int w = (blockIdx.x * blockDim.x + threadIdx.x) >> 5;
    int lane = threadIdx.x & 31;
    if (w >= VH * Nn) return;
    int i = w % Nn;
    int vh = w / Nn;
    int v = vh / Hh;

    int nb = -1;
    bool valid = false;
    if (lane < Kk) {
        nb = g_knn[i * Kk + lane];
        valid = (nb == i) || (fm[(size_t)i * Vv + v] > 0.f && fm[(size_t)nb * Vv + v] > 0.f);
    }
    unsigned hasSelf = __ballot_sync(0xffffffffu, lane < Kk && nb == i);
    if (hasSelf == 0 && lane == Kk) { nb = i; valid = true; }

    float e = -FLT_MAX;
    if (valid) {
        float x = g_f1[vh * Nn + i] + g_f2[vh * Nn + nb];
        e = (x >= 0.f) ? x : LRELU_ALPHA * x;
    }
    float m = e;
    #pragma unroll
    for (int o = 16; o; o >>= 1) m = fmaxf(m, __shfl_xor_sync(0xffffffffu, m, o));
    float wt = valid ? expf(e - m) : 0.f;
    float s = wt;
    #pragma unroll
    for (int o = 16; o; o >>= 1) s += __shfl_xor_sync(0xffffffffu, s, o);
    float att = wt / s;

    const float* base = g_Wh + (size_t)vh * Nn * Dd;
    float acc[4] = {0.f, 0.f, 0.f, 0.f};
    #pragma unroll
    for (int j = 0; j <= Kk; j++) {
        float a = __shfl_sync(0xffffffffu, att, j);
        int nj = __shfl_sync(0xffffffffu, nb, j);
        if (a != 0.f) {
            float4 wv = *(const float4*)(base + (size_t)nj * Dd + lane * 4);
            acc[0] = fmaf(a, wv.x, acc[0]);
            acc[1] = fmaf(a, wv.y, acc[1]);
            acc[2] = fmaf(a, wv.z, acc[2]);
            acc[3] = fmaf(a, wv.w, acc[3]);
        }
    }
    union { __nv_bfloat16 b[4]; uint2 u; } H, L;
    #pragma unroll
    for (int q = 0; q < 4; q++) {
        H.b[q] = __float2bfloat16(acc[q]);
        L.b[q] = __float2bfloat16(acc[q] - __bfloat162float(H.b[q]));
    }
    size_t dst = (size_t)i * (VH * Dd) + (size_t)vh * Dd + lane * 4;
    *(uint2*)(g_meta_h + dst) = H.u;
    *(uint2*)(g_meta_l + dst) = L.u;
}

// ---------------- split-K reduce for agg + bias -> sem fp32 + bf16 split ----------------
__global__ void agg_reduce_kernel(const float* __restrict__ bias, float* __restrict__ sem) {
    int i = blockIdx.x * blockDim.x + threadIdx.x;
    if (i >= Nn * Dd) return;
    float s = 0.f;
    #pragma unroll
    for (int p = 0; p < AGG_SPLITS; p++) s += g_part[(size_t)p * Nn * Dd + i];
    s += bias[i & (Dd - 1)];
    sem[i] = s;
    __nv_bfloat16 h = __float2bfloat16(s);
    g_sem_h[i] = h;
    g_sem_l[i] = __float2bfloat16(s - __bfloat162float(h));
}

// ---------------- launch ----------------
extern "C" void kernel_launch(void* const* d_in, const int* in_sizes, int n_in,
                              void* d_out, int out_size) {
    const float* fm     = (const float*)d_in[0];
    const float* latent = (const float*)d_in[1];
    const float* enc_W  = (const float*)d_in[2];
    const float* enc_b  = (const float*)d_in[3];
    const float* gat_W  = (const float*)d_in[4];
    const float* gat_a  = (const float*)d_in[5];
    const float* agg_W  = (const float*)d_in[6];
    const float* agg_b  = (const float*)d_in[7];
    const float* cls_W  = (const float*)d_in[8];
    const float* cls_b  = (const float*)d_in[9];

    float* out  = (float*)d_out;
    float* rec  = out;                                   // [V,N,VD]
    float* outp = out + (size_t)Vv * Nn * VDd;           // [N,D]
    float* sem  = outp + (size_t)Nn * Dd;                // [N,D]

    float *p_sq, *p_dist, *p_Wh, *p_part;
    cudaGetSymbolAddress((void**)&p_sq, g_sq);
    cudaGetSymbolAddress((void**)&p_dist, g_dist);
    cudaGetSymbolAddress((void**)&p_Wh, g_Wh);
    cudaGetSymbolAddress((void**)&p_part, g_part);

    __nv_bfloat16 *lat_h, *lat_l, *gwT_h, *gwT_l, *encT_h, *encT_l;
    __nv_bfloat16 *aggT_h, *aggT_l, *clsT_h, *clsT_l, *meta_h, *meta_l, *sem_h, *sem_l;
    cudaGetSymbolAddress((void**)&lat_h, g_lat_h);   cudaGetSymbolAddress((void**)&lat_l, g_lat_l);
    cudaGetSymbolAddress((void**)&gwT_h, g_gwT_h);   cudaGetSymbolAddress((void**)&gwT_l, g_gwT_l);
    cudaGetSymbolAddress((void**)&encT_h, g_encT_h); cudaGetSymbolAddress((void**)&encT_l, g_encT_l);
    cudaGetSymbolAddress((void**)&aggT_h, g_aggT_h); cudaGetSymbolAddress((void**)&aggT_l, g_aggT_l);
    cudaGetSymbolAddress((void**)&clsT_h, g_clsT_h); cudaGetSymbolAddress((void**)&clsT_l, g_clsT_l);
    cudaGetSymbolAddress((void**)&meta_h, g_meta_h); cudaGetSymbolAddress((void**)&meta_l, g_meta_l);
    cudaGetSymbolAddress((void**)&sem_h, g_sem_h);   cudaGetSymbolAddress((void**)&sem_l, g_sem_l);

    // 1. prep: weight transposes+splits (one kernel), latent split+sq
    prep_weights<<<592, 256>>>(gat_W, enc_W, agg_W, cls_W);
    prep_latent<<<Nn / 8, 256>>>(latent);
    // 2. dist = sq_i + sq_j - 2 * latent @ latent^T
    bmma_kernel<3><<<dim3(Nn / 128, Nn / 128, 1), 256>>>(
        lat_h, lat_l, lat_h, lat_l, p_dist, p_sq, Dd, Dd, Dd, Nn, 0, 0, 0, 0);
    // 3. top-K neighbors per row (4 warps/row + merge)
    knn_kernel<<<Nn / 2, 256>>>();
    // 4. Wh[v,h] = latent @ gat_W[v,h]  (+ fused f1/f2)
    bmma_kernel<4><<<dim3(1, Nn / 128, VH), 256>>>(
        lat_h, lat_l, gwT_h, gwT_l, p_Wh, gat_a, Dd, Dd, Dd, Dd,
        0, (long)Dd * Dd, (long)Nn * Dd, (long)2 * Dd);
    // 5. sparse attention -> split bf16 meta
    attn_kernel<<<VH * Nn / 8, 256>>>(fm);
    // 6. rec[v] = latent @ enc_W[v] + enc_b[v]
    bmma_kernel<1><<<dim3(VDd / 128, Nn / 128, Vv), 256>>>(
        lat_h, lat_l, encT_h, encT_l, rec, enc_b, Dd, Dd, Dd, VDd,
        0, (long)VDd * Dd, (long)Nn * VDd, (long)VDd);
    // 7. semantic partials = meta @ agg_W (split-K)
    bmma_kernel<0><<<dim3(1, Nn / 128, AGG_SPLITS), 256>>>(
        meta_h, meta_l, aggT_h, aggT_l, p_part, nullptr,
        AGG_KCHUNK, VH * Dd, VH * Dd, Dd,
        (long)AGG_KCHUNK, (long)AGG_KCHUNK, (long)Nn * Dd, 0);
    // 8. reduce partials + bias -> semantic (fp32 out + bf16 split)
    agg_reduce_kernel<<<(Nn * Dd) / 256, 256>>>(agg_b, sem);
    // 9. output = log_softmax(elu(sem @ cls_W + cls_b))  (fully fused)
    bmma_kernel<5><<<dim3(1, Nn / 128, 1), 256>>>(
        sem_h, sem_l, clsT_h, clsT_l, outp, cls_b, Dd, Dd, Dd, Dd, 0, 0, 0, 0);
}

// round 8
// speedup vs baseline: 2.1869x; 1.0305x over previous
#include <cuda_runtime.h>
#include <cuda_bf16.h>
#include <cstdint>
#include <math.h>
#include <float.h>

#define Nn 2048
#define Dd 128
#define Vv 3
#define Hh 4
#define VDd 512
#define Kk 10
#define VH (Vv*Hh)
#define LRELU_ALPHA 0.2f
#define AGG_SPLITS 8
#define AGG_KCHUNK ((VH*Dd)/AGG_SPLITS)   // 192

// ---------------- scratch (no allocations allowed) ----------------
__device__ float g_sq[Nn];
__device__ float g_dist[(size_t)Nn * Nn];
__device__ int   g_knn[Nn * Kk];
__device__ float g_Wh[(size_t)VH * Nn * Dd];
__device__ float g_f1[VH * Nn];
__device__ float g_f2[VH * Nn];
__device__ float g_part[(size_t)AGG_SPLITS * Nn * Dd];

// bf16 split operands
__device__ __nv_bfloat16 g_lat_h[Nn * Dd],  g_lat_l[Nn * Dd];
__device__ __nv_bfloat16 g_gwT_h[VH * Dd * Dd], g_gwT_l[VH * Dd * Dd];
__device__ __nv_bfloat16 g_encT_h[Vv * VDd * Dd], g_encT_l[Vv * VDd * Dd];
__device__ __nv_bfloat16 g_aggT_h[Dd * VH * Dd], g_aggT_l[Dd * VH * Dd];
__device__ __nv_bfloat16 g_clsT_h[Dd * Dd], g_clsT_l[Dd * Dd];
__device__ __nv_bfloat16 g_meta_h[(size_t)Nn * VH * Dd], g_meta_l[(size_t)Nn * VH * Dd];
__device__ __nv_bfloat16 g_sem_h[Nn * Dd], g_sem_l[Nn * Dd];

// ---------------- coalesced transpose + split (32x32 tiles) ----------------
__device__ __forceinline__ void trans_tile(
    const float* __restrict__ src, int R, int C,
    __nv_bfloat16* __restrict__ dh, __nv_bfloat16* __restrict__ dl,
    int tr, int tc, int tid)
{
    __shared__ float tile[32][33];
    int tx = tid & 31, ty = tid >> 5;   // ty 0..7
    int r0 = tr * 32, c0 = tc * 32;
    #pragma unroll
    for (int p = 0; p < 4; p++)
        tile[ty + p * 8][tx] = src[(size_t)(r0 + ty + p * 8) * C + c0 + tx];
    __syncthreads();
    #pragma unroll
    for (int p = 0; p < 4; p++) {
        int j = ty + p * 8;
        float x = tile[tx][j];
        __nv_bfloat16 h = __float2bfloat16(x);
        size_t o = (size_t)(c0 + j) * R + r0 + tx;
        dh[o] = h;
        dl[o] = __float2bfloat16(x - __bfloat162float(h));
    }
}

// combined prep: weights (blocks 0..591) + latent split/sq (blocks 592..847)
__global__ __launch_bounds__(256) void prep_all(
    const float* __restrict__ gw, const float* __restrict__ ew,
    const float* __restrict__ aw, const float* __restrict__ cw,
    const float* __restrict__ lat)
{
    int b = blockIdx.x, tid = threadIdx.x;
    if (b < 192) {                       // gat_W: VH x [128,128] -> 16 tiles each
        int z = b >> 4, t = b & 15;
        trans_tile(gw + (size_t)z * Dd * Dd, Dd, Dd,
                   g_gwT_h + (size_t)z * Dd * Dd, g_gwT_l + (size_t)z * Dd * Dd,
                   t >> 2, t & 3, tid);
    } else if (b < 384) {                // enc_W: 3 x [128,512] -> 64 tiles each
        int bb = b - 192; int z = bb >> 6, t = bb & 63;
        trans_tile(ew + (size_t)z * Dd * VDd, Dd, VDd,
                   g_encT_h + (size_t)z * VDd * Dd, g_encT_l + (size_t)z * VDd * Dd,
                   t >> 4, t & 15, tid);
    } else if (b < 576) {                // agg_W: [1536,128] -> 192 tiles
        int t = b - 384;
        trans_tile(aw, VH * Dd, Dd, g_aggT_h, g_aggT_l, t >> 2, t & 3, tid);
    } else if (b < 592) {                // cls_W: [128,128] -> 16 tiles
        int t = b - 576;
        trans_tile(cw, Dd, Dd, g_clsT_h, g_clsT_l, t >> 2, t & 3, tid);
    } else {                             // latent split + sq: blocks 592..847, 8 rows each
        int w = (b - 592) * 8 + (tid >> 5);
        int lane = tid & 31;
        float4 r = *(const float4*)(lat + (size_t)w * Dd + lane * 4);
        union { __nv_bfloat16 bb[4]; uint2 u; } H, L;
        float c[4] = {r.x, r.y, r.z, r.w};
        #pragma unroll
        for (int q = 0; q < 4; q++) {
            H.bb[q] = __float2bfloat16(c[q]);
            L.bb[q] = __float2bfloat16(c[q] - __bfloat162float(H.bb[q]));
        }
        *(uint2*)(g_lat_h + (size_t)w * Dd + lane * 4) = H.u;
        *(uint2*)(g_lat_l + (size_t)w * Dd + lane * 4) = L.u;
        float s = c[0]*c[0] + c[1]*c[1] + c[2]*c[2] + c[3]*c[3];
        #pragma unroll
        for (int o = 16; o; o >>= 1) s += __shfl_xor_sync(0xffffffffu, s, o);
        if (lane == 0) g_sq[w] = s;
    }
}

#define MMA_BF16(c, a0, a1, a2, a3, b0, b1) \
    asm volatile("mma.sync.aligned.m16n8k16.row.col.f32.bf16.bf16.f32 " \
                 "{%0,%1,%2,%3}, {%4,%5,%6,%7}, {%8,%9}, {%0,%1,%2,%3};" \
                 : "+f"((c)[0]), "+f"((c)[1]), "+f"((c)[2]), "+f"((c)[3]) \
                 : "r"(a0), "r"(a1), "r"(a2), "r"(a3), "r"(b0), "r"(b1))

// =====================================================================
// bf16 split-compensated tensor-core GEMM.
// MODE: 0 plain, 1 +bias[col], 3 dist epilogue,
//       4 plain + fused f1/f2 row-dots (bias = gat_a[z]),
//       5 +bias, elu, row log_softmax fused (writes final output)
// =====================================================================
template <int MODE>
__global__ __launch_bounds__(256) void bmma_kernel(
    const __nv_bfloat16* __restrict__ Ah, const __nv_bfloat16* __restrict__ Al,
    const __nv_bfloat16* __restrict__ Bh, const __nv_bfloat16* __restrict__ Bl,
    float* __restrict__ C, const float* __restrict__ bias,
    int Kdim, int lda, int ldb, int ldc,
    long zA, long zB, long zC, long zBias)
{
    __shared__ __nv_bfloat16 Ash[128][40];
    __shared__ __nv_bfloat16 Asl[128][40];
    __shared__ __nv_bfloat16 Bsh[128][40];
    __shared__ __nv_bfloat16 Bsl[128][40];

    const __nv_bfloat16* Ahb = Ah + (size_t)blockIdx.z * zA;
    const __nv_bfloat16* Alb = Al + (size_t)blockIdx.z * zA;
    const __nv_bfloat16* Bhb = Bh + (size_t)blockIdx.z * zB;
    const __nv_bfloat16* Blb = Bl + (size_t)blockIdx.z * zB;
    float* Cb = C + (size_t)blockIdx.z * zC;
    const float* biasb = bias ? bias + (size_t)blockIdx.z * zBias : nullptr;

    const int bm = blockIdx.y * 128, bn = blockIdx.x * 128;
    const int tid = threadIdx.x;
    const int wid = tid >> 5, lane = tid & 31;
    const int wm = wid >> 2, wn = wid & 3;       // 2 x 4 warp grid
    const int gr = lane >> 2, ct = lane & 3;

    const int r0 = tid >> 2;            // 0..63
    const int cv = (tid & 3) * 8;       // 0,8,16,24

    float acc[4][4][4];
    #pragma unroll
    for (int mt = 0; mt < 4; mt++)
        #pragma unroll
        for (int nt = 0; nt < 4; nt++)
            #pragma unroll
            for (int q = 0; q < 4; q++) acc[mt][nt][q] = 0.f;

    const int T = Kdim >> 5;
    for (int t = 0; t < T; t++) {
        const int k0 = t * 32;
        uint4 gah0 = *(const uint4*)(Ahb + (size_t)(bm + r0) * lda + k0 + cv);
        uint4 gah1 = *(const uint4*)(Ahb + (size_t)(bm + r0 + 64) * lda + k0 + cv);
        uint4 gal0 = *(const uint4*)(Alb + (size_t)(bm + r0) * lda + k0 + cv);
        uint4 gal1 = *(const uint4*)(Alb + (size_t)(bm + r0 + 64) * lda + k0 + cv);
        uint4 gbh0 = *(const uint4*)(Bhb + (size_t)(bn + r0) * ldb + k0 + cv);
        uint4 gbh1 = *(const uint4*)(Bhb + (size_t)(bn + r0 + 64) * ldb + k0 + cv);
        uint4 gbl0 = *(const uint4*)(Blb + (size_t)(bn + r0) * ldb + k0 + cv);
        uint4 gbl1 = *(const uint4*)(Blb + (size_t)(bn + r0 + 64) * ldb + k0 + cv);

        __syncthreads();
        *(uint4*)&Ash[r0][cv] = gah0;  *(uint4*)&Ash[r0 + 64][cv] = gah1;
        *(uint4*)&Asl[r0][cv] = gal0;  *(uint4*)&Asl[r0 + 64][cv] = gal1;
        *(uint4*)&Bsh[r0][cv] = gbh0;  *(uint4*)&Bsh[r0 + 64][cv] = gbh1;
        *(uint4*)&Bsl[r0][cv] = gbl0;  *(uint4*)&Bsl[r0 + 64][cv] = gbl1;
        __syncthreads();

        #pragma unroll
        for (int kk = 0; kk < 32; kk += 16) {
            uint32_t bh[4][2], bl[4][2];
            #pragma unroll
            for (int nt = 0; nt < 4; nt++) {
                int n = wn * 32 + nt * 8 + gr;
                bh[nt][0] = *(const uint32_t*)&Bsh[n][kk + ct * 2];
                bh[nt][1] = *(const uint32_t*)&Bsh[n][kk + ct * 2 + 8];
                bl[nt][0] = *(const uint32_t*)&Bsl[n][kk + ct * 2];
                bl[nt][1] = *(const uint32_t*)&Bsl[n][kk + ct * 2 + 8];
            }
            #pragma unroll
            for (int mt = 0; mt < 4; mt++) {
                int rA = wm * 64 + mt * 16 + gr;
                uint32_t ah0 = *(const uint32_t*)&Ash[rA][kk + ct * 2];
                uint32_t ah1 = *(const uint32_t*)&Ash[rA + 8][kk + ct * 2];
                uint32_t ah2 = *(const uint32_t*)&Ash[rA][kk + ct * 2 + 8];
                uint32_t ah3 = *(const uint32_t*)&Ash[rA + 8][kk + ct * 2 + 8];
                uint32_t al0 = *(const uint32_t*)&Asl[rA][kk + ct * 2];
                uint32_t al1 = *(const uint32_t*)&Asl[rA + 8][kk + ct * 2];
                uint32_t al2 = *(const uint32_t*)&Asl[rA][kk + ct * 2 + 8];
                uint32_t al3 = *(const uint32_t*)&Asl[rA + 8][kk + ct * 2 + 8];
                #pragma unroll
                for (int nt = 0; nt < 4; nt++) {
                    MMA_BF16(acc[mt][nt], ah0, ah1, ah2, ah3, bh[nt][0], bh[nt][1]);
                    MMA_BF16(acc[mt][nt], ah0, ah1, ah2, ah3, bl[nt][0], bl[nt][1]);
                    MMA_BF16(acc[mt][nt], al0, al1, al2, al3, bh[nt][0], bh[nt][1]);
                }
            }
        }
    }

    // ---- standard store (all modes except 5) ----
    if (MODE != 5) {
        #pragma unroll
        for (int mt = 0; mt < 4; mt++) {
            int row = bm + wm * 64 + mt * 16 + gr;
            #pragma unroll
            for (int nt = 0; nt < 4; nt++) {
                int col = bn + wn * 32 + nt * 8 + ct * 2;
                float v0 = acc[mt][nt][0], v1 = acc[mt][nt][1];
                float v2 = acc[mt][nt][2], v3 = acc[mt][nt][3];
                if (MODE == 1) {
                    float b0 = biasb[col], b1 = biasb[col + 1];
                    v0 += b0; v1 += b1; v2 += b0; v3 += b1;
                } else if (MODE == 3) {
                    float sr0 = bias[row], sr1 = bias[row + 8];
                    float sc0 = bias[col], sc1 = bias[col + 1];
                    v0 = sr0 + sc0 - 2.f * v0;
                    v1 = sr0 + sc1 - 2.f * v1;
                    v2 = sr1 + sc0 - 2.f * v2;
                    v3 = sr1 + sc1 - 2.f * v3;
                }
                *(float2*)(Cb + (size_t)row * ldc + col) = make_float2(v0, v1);
                *(float2*)(Cb + (size_t)(row + 8) * ldc + col) = make_float2(v2, v3);
            }
        }
    }

    // ---- MODE 4: fused f1/f2 row-dots (requires grid.x == 1, ldc == Dd) ----
    if (MODE == 4) {
        __shared__ float sf1[4][128];
        __shared__ float sf2[4][128];
        float a1c[4][2], a2c[4][2];
        #pragma unroll
        for (int nt = 0; nt < 4; nt++) {
            int col = bn + wn * 32 + nt * 8 + ct * 2;
            a1c[nt][0] = biasb[col];      a1c[nt][1] = biasb[col + 1];
            a2c[nt][0] = biasb[Dd + col]; a2c[nt][1] = biasb[Dd + col + 1];
        }
        float p1[8], p2[8];
        #pragma unroll
        for (int ri = 0; ri < 8; ri++) {
            int mt = ri >> 1, h2 = ri & 1;
            float s1 = 0.f, s2 = 0.f;
            #pragma unroll
            for (int nt = 0; nt < 4; nt++) {
                float v0 = acc[mt][nt][h2 * 2 + 0], v1 = acc[mt][nt][h2 * 2 + 1];
                s1 += v0 * a1c[nt][0] + v1 * a1c[nt][1];
                s2 += v0 * a2c[nt][0] + v1 * a2c[nt][1];
            }
            p1[ri] = s1; p2[ri] = s2;
        }
        #pragma unroll
        for (int ri = 0; ri < 8; ri++) {
            p1[ri] += __shfl_xor_sync(0xffffffffu, p1[ri], 1);
            p1[ri] += __shfl_xor_sync(0xffffffffu, p1[ri], 2);
            p2[ri] += __shfl_xor_sync(0xffffffffu, p2[ri], 1);
            p2[ri] += __shfl_xor_sync(0xffffffffu, p2[ri], 2);
        }
        if (ct == 0) {
            #pragma unroll
            for (int ri = 0; ri < 8; ri++) {
                int rl = wm * 64 + (ri >> 1) * 16 + gr + (ri & 1) * 8;
                sf1[wn][rl] = p1[ri];
                sf2[wn][rl] = p2[ri];
            }
        }
        __syncthreads();
        if (tid < 128) {
            float f1 = sf1[0][tid] + sf1[1][tid] + sf1[2][tid] + sf1[3][tid];
            float f2 = sf2[0][tid] + sf2[1][tid] + sf2[2][tid] + sf2[3][tid];
            g_f1[(size_t)blockIdx.z * Nn + bm + tid] = f1;
            g_f2[(size_t)blockIdx.z * Nn + bm + tid] = f2;
        }
    }

    // ---- MODE 5: bias + elu + row log_softmax, final store ----
    if (MODE == 5) {
        __shared__ float sred[4][128];
        __shared__ float srow[128];
        #pragma unroll
        for (int mt = 0; mt < 4; mt++)
            #pragma unroll
            for (int nt = 0; nt < 4; nt++) {
                int col = bn + wn * 32 + nt * 8 + ct * 2;
                float b0 = biasb[col], b1 = biasb[col + 1];
                acc[mt][nt][0] += b0; acc[mt][nt][1] += b1;
                acc[mt][nt][2] += b0; acc[mt][nt][3] += b1;
                #pragma unroll
                for (int q = 0; q < 4; q++) {
                    float v = acc[mt][nt][q];
                    acc[mt][nt][q] = (v > 0.f) ? v : expm1f(v);
                }
            }
        // row max
        float rm[8];
        #pragma unroll
        for (int ri = 0; ri < 8; ri++) {
            int mt = ri >> 1, h2 = ri & 1;
            float m = -FLT_MAX;
            #pragma unroll
            for (int nt = 0; nt < 4; nt++)
                m = fmaxf(m, fmaxf(acc[mt][nt][h2 * 2], acc[mt][nt][h2 * 2 + 1]));
            rm[ri] = m;
        }
        #pragma unroll
        for (int ri = 0; ri < 8; ri++) {
            rm[ri] = fmaxf(rm[ri], __shfl_xor_sync(0xffffffffu, rm[ri], 1));
            rm[ri] = fmaxf(rm[ri], __shfl_xor_sync(0xffffffffu, rm[ri], 2));
        }
        if (ct == 0)
            #pragma unroll
            for (int ri = 0; ri < 8; ri++)
                sred[wn][wm * 64 + (ri >> 1) * 16 + gr + (ri & 1) * 8] = rm[ri];
        __syncthreads();
        if (tid < 128)
            srow[tid] = fmaxf(fmaxf(sred[0][tid], sred[1][tid]),
                              fmaxf(sred[2][tid], sred[3][tid]));
        __syncthreads();
        // sum exp
        float se[8];
        #pragma unroll
        for (int ri = 0; ri < 8; ri++) {
            int mt = ri >> 1, h2 = ri & 1;
            int rl = wm * 64 + mt * 16 + gr + h2 * 8;
            float m = srow[rl];
            float s = 0.f;
            #pragma unroll
            for (int nt = 0; nt < 4; nt++)
                s += expf(acc[mt][nt][h2 * 2] - m) + expf(acc[mt][nt][h2 * 2 + 1] - m);
            se[ri] = s;
        }
        #pragma unroll
        for (int ri = 0; ri < 8; ri++) {
            se[ri] += __shfl_xor_sync(0xffffffffu, se[ri], 1);
            se[ri] += __shfl_xor_sync(0xffffffffu, se[ri], 2);
        }
        __syncthreads();
        if (ct == 0)
            #pragma unroll
            for (int ri = 0; ri < 8; ri++)
                sred[wn][wm * 64 + (ri >> 1) * 16 + gr + (ri & 1) * 8] = se[ri];
        __syncthreads();
        if (tid < 128)
            srow[tid] += logf(sred[0][tid] + sred[1][tid] + sred[2][tid] + sred[3][tid]);
        __syncthreads();
        #pragma unroll
        for (int mt = 0; mt < 4; mt++) {
            #pragma unroll
            for (int nt = 0; nt < 4; nt++) {
                int col = bn + wn * 32 + nt * 8 + ct * 2;
                int rl0 = wm * 64 + mt * 16 + gr;
                float l0 = srow[rl0], l1 = srow[rl0 + 8];
                *(float2*)(Cb + (size_t)(bm + rl0) * ldc + col) =
                    make_float2(acc[mt][nt][0] - l0, acc[mt][nt][1] - l0);
                *(float2*)(Cb + (size_t)(bm + rl0 + 8) * ldc + col) =
                    make_float2(acc[mt][nt][2] - l1, acc[mt][nt][3] - l1);
            }
        }
    }
}

// ---------------- per-row top-K: 4 warps per row, float4 loads, + merge ----------------
__global__ __launch_bounds__(256) void knn_kernel() {
    __shared__ float sval[8][Kk];
    __shared__ int   sidx[8][Kk];
    int tid = threadIdx.x;
    int wid = tid >> 5, lane = tid & 31;
    int row = blockIdx.x * 2 + (wid >> 2);
    int quarter = wid & 3;
    const float* dr = g_dist + (size_t)row * Nn + quarter * 512;

    // hoisted wide loads: 4 x float4 per lane (MLP=4, 512B/warp/iter)
    float4 v4[4];
    #pragma unroll
    for (int t = 0; t < 4; t++)
        v4[t] = *(const float4*)(dr + t * 128 + lane * 4);

    float val[Kk];
    int   idx[Kk];
    #pragma unroll
    for (int p = 0; p < Kk; p++) { val[p] = FLT_MAX; idx[p] = 0x7fffffff; }

    #pragma unroll
    for (int t = 0; t < 4; t++) {
        float c[4] = {v4[t].x, v4[t].y, v4[t].z, v4[t].w};
        #pragma unroll
        for (int q = 0; q < 4; q++) {
            float d = c[q];
            if (d < val[Kk - 1]) {
                int gj = quarter * 512 + t * 128 + lane * 4 + q;
                #pragma unroll
                for (int p = Kk - 1; p >= 1; p--) {
                    if (d < val[p]) {
                        bool sh = d < val[p - 1];
                        val[p] = sh ? val[p - 1] : d;
                        idx[p] = sh ? idx[p - 1] : gj;
                    }
                }
                if (d < val[0]) { val[0] = d; idx[0] = gj; }
            }
        }
    }

    // warp pop-10 -> sorted candidates in smem
    #pragma unroll 1
    for (int r = 0; r < Kk; r++) {
        float bv = val[0]; int bi = idx[0];
        #pragma unroll
        for (int o = 16; o; o >>= 1) {
            float ov = __shfl_xor_sync(0xffffffffu, bv, o);
            int   oi = __shfl_xor_sync(0xffffffffu, bi, o);
            if (ov < bv || (ov == bv && oi < bi)) { bv = ov; bi = oi; }
        }
        if (lane == 0) { sval[wid][r] = bv; sidx[wid][r] = bi; }
        if (val[0] == bv && idx[0] == bi) {
            #pragma unroll
            for (int p = 0; p < Kk - 1; p++) { val[p] = val[p + 1]; idx[p] = idx[p + 1]; }
            val[Kk - 1] = FLT_MAX; idx[Kk - 1] = 0x7fffffff;
        }
    }
    __syncthreads();

    // merge 4 x 10 candidates: warps 0 (row A) and 4 (row B)
    if ((wid & 3) == 0) {
        int wbase = wid;              // 0 or 4
        float a = FLT_MAX; int ai = 0x7fffffff;
        float b = FLT_MAX; int bi = 0x7fffffff;
        if (lane < 40) { a = sval[wbase + lane / Kk][lane % Kk]; ai = sidx[wbase + lane / Kk][lane % Kk]; }
        int l2 = lane + 32;
        if (l2 < 40) { b = sval[wbase + l2 / Kk][l2 % Kk]; bi = sidx[wbase + l2 / Kk][l2 % Kk]; }
        #pragma unroll 1
        for (int r = 0; r < Kk; r++) {
            bool useB = (b < a) || (b == a && bi < ai);
            float cv = useB ? b : a;
            int   ci = useB ? bi : ai;
            float mv = cv; int mi = ci;
            #pragma unroll
            for (int o = 16; o; o >>= 1) {
                float ov = __shfl_xor_sync(0xffffffffu, mv, o);
                int   oi = __shfl_xor_sync(0xffffffffu, mi, o);
                if (ov < mv || (ov == mv && oi < mi)) { mv = ov; mi = oi; }
            }
            if (lane == 0) g_knn[row * Kk + r] = mi;
            if (cv == mv && ci == mi) {
                if (useB) { b = FLT_MAX; bi = 0x7fffffff; }
                else      { a = FLT_MAX; ai = 0x7fffffff; }
            }
        }
    }
}

// ---------------- sparse GAT attention -> split bf16 meta ----------------
__global__ void attn_kernel(const float* __restrict__ fm) {
    int w = (blockIdx.x * blockDim.x + threadIdx.x) >> 5;
    int lane = threadIdx.x & 31;
    if (w >= VH * Nn) return;
    int i = w % Nn;
    int vh = w / Nn;
    int v = vh / Hh;

    int nb = -1;
    bool valid = false;
    if (lane < Kk) {
        nb = g_knn[i * Kk + lane];
        valid = (nb == i) || (fm[(size_t)i * Vv + v] > 0.f && fm[(size_t)nb * Vv + v] > 0.f);
    }
    unsigned hasSelf = __ballot_sync(0xffffffffu, lane < Kk && nb == i);
    if (hasSelf == 0 && lane == Kk) { nb = i; valid = true; }

    float e = -FLT_MAX;
    if (valid) {
        float x = g_f1[vh * Nn + i] + g_f2[vh * Nn + nb];
        e = (x >= 0.f) ? x : LRELU_ALPHA * x;
    }
    float m = e;
    #pragma unroll
    for (int o = 16; o; o >>= 1) m = fmaxf(m, __shfl_xor_sync(0xffffffffu, m, o));
    float wt = valid ? expf(e - m) : 0.f;
    float s = wt;
    #pragma unroll
    for (int o = 16; o; o >>= 1) s += __shfl_xor_sync(0xffffffffu, s, o);
    float att = wt / s;

    const float* base = g_Wh + (size_t)vh * Nn * Dd;
    float acc[4] = {0.f, 0.f, 0.f, 0.f};
    #pragma unroll
    for (int j = 0; j <= Kk; j++) {
        float a = __shfl_sync(0xffffffffu, att, j);
        int nj = __shfl_sync(0xffffffffu, nb, j);
        if (a != 0.f) {
            float4 wv = *(const float4*)(base + (size_t)nj * Dd + lane * 4);
            acc[0] = fmaf(a, wv.x, acc[0]);
            acc[1] = fmaf(a, wv.y, acc[1]);
            acc[2] = fmaf(a, wv.z, acc[2]);
            acc[3] = fmaf(a, wv.w, acc[3]);
        }
    }
    union { __nv_bfloat16 b[4]; uint2 u; } H, L;
    #pragma unroll
    for (int q = 0; q < 4; q++) {
        H.b[q] = __float2bfloat16(acc[q]);
        L.b[q] = __float2bfloat16(acc[q] - __bfloat162float(H.b[q]));
    }
    size_t dst = (size_t)i * (VH * Dd) + (size_t)vh * Dd + lane * 4;
    *(uint2*)(g_meta_h + dst) = H.u;
    *(uint2*)(g_meta_l + dst) = L.u;
}

// ---------------- split-K reduce for agg + bias -> sem fp32 + bf16 split ----------------
__global__ void agg_reduce_kernel(const float* __restrict__ bias, float* __restrict__ sem) {
    int i = blockIdx.x * blockDim.x + threadIdx.x;
    if (i >= Nn * Dd) return;
    float s = 0.f;
    #pragma unroll
    for (int p = 0; p < AGG_SPLITS; p++) s += g_part[(size_t)p * Nn * Dd + i];
    s += bias[i & (Dd - 1)];
    sem[i] = s;
    __nv_bfloat16 h = __float2bfloat16(s);
    g_sem_h[i] = h;
    g_sem_l[i] = __float2bfloat16(s - __bfloat162float(h));
}

// ---------------- launch ----------------
extern "C" void kernel_launch(void* const* d_in, const int* in_sizes, int n_in,
                              void* d_out, int out_size) {
    const float* fm     = (const float*)d_in[0];
    const float* latent = (const float*)d_in[1];
    const float* enc_W  = (const float*)d_in[2];
    const float* enc_b  = (const float*)d_in[3];
    const float* gat_W  = (const float*)d_in[4];
    const float* gat_a  = (const float*)d_in[5];
    const float* agg_W  = (const float*)d_in[6];
    const float* agg_b  = (const float*)d_in[7];
    const float* cls_W  = (const float*)d_in[8];
    const float* cls_b  = (const float*)d_in[9];

    float* out  = (float*)d_out;
    float* rec  = out;                                   // [V,N,VD]
    float* outp = out + (size_t)Vv * Nn * VDd;           // [N,D]
    float* sem  = outp + (size_t)Nn * Dd;                // [N,D]

    float *p_sq, *p_dist, *p_Wh, *p_part;
    cudaGetSymbolAddress((void**)&p_sq, g_sq);
    cudaGetSymbolAddress((void**)&p_dist, g_dist);
    cudaGetSymbolAddress((void**)&p_Wh, g_Wh);
    cudaGetSymbolAddress((void**)&p_part, g_part);

    __nv_bfloat16 *lat_h, *lat_l, *gwT_h, *gwT_l, *encT_h, *encT_l;
    __nv_bfloat16 *aggT_h, *aggT_l, *clsT_h, *clsT_l, *meta_h, *meta_l, *sem_h, *sem_l;
    cudaGetSymbolAddress((void**)&lat_h, g_lat_h);   cudaGetSymbolAddress((void**)&lat_l, g_lat_l);
    cudaGetSymbolAddress((void**)&gwT_h, g_gwT_h);   cudaGetSymbolAddress((void**)&gwT_l, g_gwT_l);
    cudaGetSymbolAddress((void**)&encT_h, g_encT_h); cudaGetSymbolAddress((void**)&encT_l, g_encT_l);
    cudaGetSymbolAddress((void**)&aggT_h, g_aggT_h); cudaGetSymbolAddress((void**)&aggT_l, g_aggT_l);
    cudaGetSymbolAddress((void**)&clsT_h, g_clsT_h); cudaGetSymbolAddress((void**)&clsT_l, g_clsT_l);
    cudaGetSymbolAddress((void**)&meta_h, g_meta_h); cudaGetSymbolAddress((void**)&meta_l, g_meta_l);
    cudaGetSymbolAddress((void**)&sem_h, g_sem_h);   cudaGetSymbolAddress((void**)&sem_l, g_sem_l);

    // 1. prep: weight transposes+splits + latent split/sq (one kernel)
    prep_all<<<848, 256>>>(gat_W, enc_W, agg_W, cls_W, latent);
    // 2. dist = sq_i + sq_j - 2 * latent @ latent^T
    bmma_kernel<3><<<dim3(Nn / 128, Nn / 128, 1), 256>>>(
        lat_h, lat_l, lat_h, lat_l, p_dist, p_sq, Dd, Dd, Dd, Nn, 0, 0, 0, 0);
    // 3. top-K neighbors per row (4 warps/row, float4 loads, + merge)
    knn_kernel<<<Nn / 2, 256>>>();
    // 4. Wh[v,h] = latent @ gat_W[v,h]  (+ fused f1/f2)
    bmma_kernel<4><<<dim3(1, Nn / 128, VH), 256>>>(
        lat_h, lat_l, gwT_h, gwT_l, p_Wh, gat_a, Dd, Dd, Dd, Dd,
        0, (long)Dd * Dd, (long)Nn * Dd, (long)2 * Dd);
    // 5. sparse attention -> split bf16 meta
    attn_kernel<<<VH * Nn / 8, 256>>>(fm);
    // 6. rec[v] = latent @ enc_W[v] + enc_b[v]
    bmma_kernel<1><<<dim3(VDd / 128, Nn / 128, Vv), 256>>>(
        lat_h, lat_l, encT_h, encT_l, rec, enc_b, Dd, Dd, Dd, VDd,
        0, (long)VDd * Dd, (long)Nn * VDd, (long)VDd);
    // 7. semantic partials = meta @ agg_W (split-K)
    bmma_kernel<0><<<dim3(1, Nn / 128, AGG_SPLITS), 256>>>(
        meta_h, meta_l, aggT_h, aggT_l, p_part, nullptr,
        AGG_KCHUNK, VH * Dd, VH * Dd, Dd,
        (long)AGG_KCHUNK, (long)AGG_KCHUNK, (long)Nn * Dd, 0);
    // 8. reduce partials + bias -> semantic (fp32 out + bf16 split)
    agg_reduce_kernel<<<(Nn * Dd) / 256, 256>>>(agg_b, sem);
    // 9. output = log_softmax(elu(sem @ cls_W + cls_b))  (fully fused)
    bmma_kernel<5><<<dim3(1, Nn / 128, 1), 256>>>(
        sem_h, sem_l, clsT_h, clsT_l, outp, cls_b, Dd, Dd, Dd, Dd, 0, 0, 0, 0);
}

// round 9
// speedup vs baseline: 2.4630x; 1.1262x over previous
#include <cuda_runtime.h>
#include <cuda_bf16.h>
#include <cstdint>
#include <math.h>
#include <float.h>

#define Nn 2048
#define Dd 128
#define Vv 3
#define Hh 4
#define VDd 512
#define Kk 10
#define VH (Vv*Hh)
#define LRELU_ALPHA 0.2f
#define AGG_SPLITS 8
#define AGG_KCHUNK ((VH*Dd)/AGG_SPLITS)   // 192

// ---------------- scratch (no allocations allowed) ----------------
__device__ float g_sq[Nn];
__device__ float g_dist[(size_t)Nn * Nn];
__device__ int   g_knn[Nn * Kk];
__device__ float g_Wh[(size_t)VH * Nn * Dd];
__device__ float g_f1[VH * Nn];
__device__ float g_f2[VH * Nn];
__device__ float g_part[(size_t)AGG_SPLITS * Nn * Dd];

// bf16 split operands
__device__ __nv_bfloat16 g_lat_h[Nn * Dd],  g_lat_l[Nn * Dd];
__device__ __nv_bfloat16 g_gwT_h[VH * Dd * Dd], g_gwT_l[VH * Dd * Dd];
__device__ __nv_bfloat16 g_encT_h[Vv * VDd * Dd], g_encT_l[Vv * VDd * Dd];
__device__ __nv_bfloat16 g_aggT_h[Dd * VH * Dd], g_aggT_l[Dd * VH * Dd];
__device__ __nv_bfloat16 g_clsT_h[Dd * Dd], g_clsT_l[Dd * Dd];
__device__ __nv_bfloat16 g_meta_h[(size_t)Nn * VH * Dd], g_meta_l[(size_t)Nn * VH * Dd];
__device__ __nv_bfloat16 g_sem_h[Nn * Dd], g_sem_l[Nn * Dd];

// ---------------- coalesced transpose + split (32x32 tiles) ----------------
__device__ __forceinline__ void trans_tile(
    const float* __restrict__ src, int R, int C,
    __nv_bfloat16* __restrict__ dh, __nv_bfloat16* __restrict__ dl,
    int tr, int tc, int tid)
{
    __shared__ float tile[32][33];
    int tx = tid & 31, ty = tid >> 5;
    int r0 = tr * 32, c0 = tc * 32;
    #pragma unroll
    for (int p = 0; p < 4; p++)
        tile[ty + p * 8][tx] = src[(size_t)(r0 + ty + p * 8) * C + c0 + tx];
    __syncthreads();
    #pragma unroll
    for (int p = 0; p < 4; p++) {
        int j = ty + p * 8;
        float x = tile[tx][j];
        __nv_bfloat16 h = __float2bfloat16(x);
        size_t o = (size_t)(c0 + j) * R + r0 + tx;
        dh[o] = h;
        dl[o] = __float2bfloat16(x - __bfloat162float(h));
    }
}

// combined prep: weights (blocks 0..591) + latent split/sq (blocks 592..847)
__global__ __launch_bounds__(256) void prep_all(
    const float* __restrict__ gw, const float* __restrict__ ew,
    const float* __restrict__ aw, const float* __restrict__ cw,
    const float* __restrict__ lat)
{
    int b = blockIdx.x, tid = threadIdx.x;
    if (b < 192) {
        int z = b >> 4, t = b & 15;
        trans_tile(gw + (size_t)z * Dd * Dd, Dd, Dd,
                   g_gwT_h + (size_t)z * Dd * Dd, g_gwT_l + (size_t)z * Dd * Dd,
                   t >> 2, t & 3, tid);
    } else if (b < 384) {
        int bb = b - 192; int z = bb >> 6, t = bb & 63;
        trans_tile(ew + (size_t)z * Dd * VDd, Dd, VDd,
                   g_encT_h + (size_t)z * VDd * Dd, g_encT_l + (size_t)z * VDd * Dd,
                   t >> 4, t & 15, tid);
    } else if (b < 576) {
        int t = b - 384;
        trans_tile(aw, VH * Dd, Dd, g_aggT_h, g_aggT_l, t >> 2, t & 3, tid);
    } else if (b < 592) {
        int t = b - 576;
        trans_tile(cw, Dd, Dd, g_clsT_h, g_clsT_l, t >> 2, t & 3, tid);
    } else {
        int w = (b - 592) * 8 + (tid >> 5);
        int lane = tid & 31;
        float4 r = *(const float4*)(lat + (size_t)w * Dd + lane * 4);
        union { __nv_bfloat16 bb[4]; uint2 u; } H, L;
        float c[4] = {r.x, r.y, r.z, r.w};
        #pragma unroll
        for (int q = 0; q < 4; q++) {
            H.bb[q] = __float2bfloat16(c[q]);
            L.bb[q] = __float2bfloat16(c[q] - __bfloat162float(H.bb[q]));
        }
        *(uint2*)(g_lat_h + (size_t)w * Dd + lane * 4) = H.u;
        *(uint2*)(g_lat_l + (size_t)w * Dd + lane * 4) = L.u;
        float s = c[0]*c[0] + c[1]*c[1] + c[2]*c[2] + c[3]*c[3];
        #pragma unroll
        for (int o = 16; o; o >>= 1) s += __shfl_xor_sync(0xffffffffu, s, o);
        if (lane == 0) g_sq[w] = s;
    }
}

#define MMA_BF16(c, a0, a1, a2, a3, b0, b1) \
    asm volatile("mma.sync.aligned.m16n8k16.row.col.f32.bf16.bf16.f32 " \
                 "{%0,%1,%2,%3}, {%4,%5,%6,%7}, {%8,%9}, {%0,%1,%2,%3};" \
                 : "+f"((c)[0]), "+f"((c)[1]), "+f"((c)[2]), "+f"((c)[3]) \
                 : "r"(a0), "r"(a1), "r"(a2), "r"(a3), "r"(b0), "r"(b1))

struct BmmaSmem {
    __nv_bfloat16 Ash[128][40];
    __nv_bfloat16 Asl[128][40];
    __nv_bfloat16 Bsh[128][40];
    __nv_bfloat16 Bsl[128][40];
    float red1[4][128];
    float red2[4][128];
    float srow[128];
};

// =====================================================================
// bf16 split-compensated tensor-core GEMM tile (device fn).
// MODE: 0 plain, 1 +bias[col], 3 dist epilogue,
//       4 plain + fused f1/f2 row-dots (biasb = gat_a[z], bn==0),
//       5 +biasb, elu, row log_softmax fused (bn==0, writes final output)
// =====================================================================
template <int MODE>
__device__ __forceinline__ void bmma_tile(
    BmmaSmem* sm,
    const __nv_bfloat16* __restrict__ Ahb, const __nv_bfloat16* __restrict__ Alb,
    const __nv_bfloat16* __restrict__ Bhb, const __nv_bfloat16* __restrict__ Blb,
    float* __restrict__ Cb, const float* __restrict__ bias,
    const float* __restrict__ biasb,
    int z, int bm, int bn, int Kdim, int lda, int ldb, int ldc)
{
    const int tid = threadIdx.x;
    const int wid = tid >> 5, lane = tid & 31;
    const int wm = wid >> 2, wn = wid & 3;
    const int gr = lane >> 2, ct = lane & 3;
    const int r0 = tid >> 2;
    const int cv = (tid & 3) * 8;

    float acc[4][4][4];
    #pragma unroll
    for (int mt = 0; mt < 4; mt++)
        #pragma unroll
        for (int nt = 0; nt < 4; nt++)
            #pragma unroll
            for (int q = 0; q < 4; q++) acc[mt][nt][q] = 0.f;

    const int T = Kdim >> 5;
    for (int t = 0; t < T; t++) {
        const int k0 = t * 32;
        uint4 gah0 = *(const uint4*)(Ahb + (size_t)(bm + r0) * lda + k0 + cv);
        uint4 gah1 = *(const uint4*)(Ahb + (size_t)(bm + r0 + 64) * lda + k0 + cv);
        uint4 gal0 = *(const uint4*)(Alb + (size_t)(bm + r0) * lda + k0 + cv);
        uint4 gal1 = *(const uint4*)(Alb + (size_t)(bm + r0 + 64) * lda + k0 + cv);
        uint4 gbh0 = *(const uint4*)(Bhb + (size_t)(bn + r0) * ldb + k0 + cv);
        uint4 gbh1 = *(const uint4*)(Bhb + (size_t)(bn + r0 + 64) * ldb + k0 + cv);
        uint4 gbl0 = *(const uint4*)(Blb + (size_t)(bn + r0) * ldb + k0 + cv);
        uint4 gbl1 = *(const uint4*)(Blb + (size_t)(bn + r0 + 64) * ldb + k0 + cv);

        __syncthreads();
        *(uint4*)&sm->Ash[r0][cv] = gah0;  *(uint4*)&sm->Ash[r0 + 64][cv] = gah1;
        *(uint4*)&sm->Asl[r0][cv] = gal0;  *(uint4*)&sm->Asl[r0 + 64][cv] = gal1;
        *(uint4*)&sm->Bsh[r0][cv] = gbh0;  *(uint4*)&sm->Bsh[r0 + 64][cv] = gbh1;
        *(uint4*)&sm->Bsl[r0][cv] = gbl0;  *(uint4*)&sm->Bsl[r0 + 64][cv] = gbl1;
        __syncthreads();

        #pragma unroll
        for (int kk = 0; kk < 32; kk += 16) {
            uint32_t bh[4][2], bl[4][2];
            #pragma unroll
            for (int nt = 0; nt < 4; nt++) {
                int n = wn * 32 + nt * 8 + gr;
                bh[nt][0] = *(const uint32_t*)&sm->Bsh[n][kk + ct * 2];
                bh[nt][1] = *(const uint32_t*)&sm->Bsh[n][kk + ct * 2 + 8];
                bl[nt][0] = *(const uint32_t*)&sm->Bsl[n][kk + ct * 2];
                bl[nt][1] = *(const uint32_t*)&sm->Bsl[n][kk + ct * 2 + 8];
            }
            #pragma unroll
            for (int mt = 0; mt < 4; mt++) {
                int rA = wm * 64 + mt * 16 + gr;
                uint32_t ah0 = *(const uint32_t*)&sm->Ash[rA][kk + ct * 2];
                uint32_t ah1 = *(const uint32_t*)&sm->Ash[rA + 8][kk + ct * 2];
                uint32_t ah2 = *(const uint32_t*)&sm->Ash[rA][kk + ct * 2 + 8];
                uint32_t ah3 = *(const uint32_t*)&sm->Ash[rA + 8][kk + ct * 2 + 8];
                uint32_t al0 = *(const uint32_t*)&sm->Asl[rA][kk + ct * 2];
                uint32_t al1 = *(const uint32_t*)&sm->Asl[rA + 8][kk + ct * 2];
                uint32_t al2 = *(const uint32_t*)&sm->Asl[rA][kk + ct * 2 + 8];
                uint32_t al3 = *(const uint32_t*)&sm->Asl[rA + 8][kk + ct * 2 + 8];
                #pragma unroll
                for (int nt = 0; nt < 4; nt++) {
                    MMA_BF16(acc[mt][nt], ah0, ah1, ah2, ah3, bh[nt][0], bh[nt][1]);
                    MMA_BF16(acc[mt][nt], ah0, ah1, ah2, ah3, bl[nt][0], bl[nt][1]);
                    MMA_BF16(acc[mt][nt], al0, al1, al2, al3, bh[nt][0], bh[nt][1]);
                }
            }
        }
    }

    if (MODE != 5) {
        #pragma unroll
        for (int mt = 0; mt < 4; mt++) {
            int row = bm + wm * 64 + mt * 16 + gr;
            #pragma unroll
            for (int nt = 0; nt < 4; nt++) {
                int col = bn + wn * 32 + nt * 8 + ct * 2;
                float v0 = acc[mt][nt][0], v1 = acc[mt][nt][1];
                float v2 = acc[mt][nt][2], v3 = acc[mt][nt][3];
                if (MODE == 1) {
                    float b0 = biasb[col], b1 = biasb[col + 1];
                    v0 += b0; v1 += b1; v2 += b0; v3 += b1;
                } else if (MODE == 3) {
                    float sr0 = bias[row], sr1 = bias[row + 8];
                    float sc0 = bias[col], sc1 = bias[col + 1];
                    v0 = sr0 + sc0 - 2.f * v0;
                    v1 = sr0 + sc1 - 2.f * v1;
                    v2 = sr1 + sc0 - 2.f * v2;
                    v3 = sr1 + sc1 - 2.f * v3;
                }
                *(float2*)(Cb + (size_t)row * ldc + col) = make_float2(v0, v1);
                *(float2*)(Cb + (size_t)(row + 8) * ldc + col) = make_float2(v2, v3);
            }
        }
    }

    if (MODE == 4) {
        float a1c[4][2], a2c[4][2];
        #pragma unroll
        for (int nt = 0; nt < 4; nt++) {
            int col = wn * 32 + nt * 8 + ct * 2;
            a1c[nt][0] = biasb[col];      a1c[nt][1] = biasb[col + 1];
            a2c[nt][0] = biasb[Dd + col]; a2c[nt][1] = biasb[Dd + col + 1];
        }
        float p1[8], p2[8];
        #pragma unroll
        for (int ri = 0; ri < 8; ri++) {
            int mt = ri >> 1, h2 = ri & 1;
            float s1 = 0.f, s2 = 0.f;
            #pragma unroll
            for (int nt = 0; nt < 4; nt++) {
                float v0 = acc[mt][nt][h2 * 2 + 0], v1 = acc[mt][nt][h2 * 2 + 1];
                s1 += v0 * a1c[nt][0] + v1 * a1c[nt][1];
                s2 += v0 * a2c[nt][0] + v1 * a2c[nt][1];
            }
            p1[ri] = s1; p2[ri] = s2;
        }
        #pragma unroll
        for (int ri = 0; ri < 8; ri++) {
            p1[ri] += __shfl_xor_sync(0xffffffffu, p1[ri], 1);
            p1[ri] += __shfl_xor_sync(0xffffffffu, p1[ri], 2);
            p2[ri] += __shfl_xor_sync(0xffffffffu, p2[ri], 1);
            p2[ri] += __shfl_xor_sync(0xffffffffu, p2[ri], 2);
        }
        if (ct == 0) {
            #pragma unroll
            for (int ri = 0; ri < 8; ri++) {
                int rl = wm * 64 + (ri >> 1) * 16 + gr + (ri & 1) * 8;
                sm->red1[wn][rl] = p1[ri];
                sm->red2[wn][rl] = p2[ri];
            }
        }
        __syncthreads();
        if (tid < 128) {
            float f1 = sm->red1[0][tid] + sm->red1[1][tid] + sm->red1[2][tid] + sm->red1[3][tid];
            float f2 = sm->red2[0][tid] + sm->red2[1][tid] + sm->red2[2][tid] + sm->red2[3][tid];
            g_f1[(size_t)z * Nn + bm + tid] = f1;
            g_f2[(size_t)z * Nn + bm + tid] = f2;
        }
    }

    if (MODE == 5) {
        #pragma unroll
        for (int mt = 0; mt < 4; mt++)
            #pragma unroll
            for (int nt = 0; nt < 4; nt++) {
                int col = wn * 32 + nt * 8 + ct * 2;
                float b0 = biasb[col], b1 = biasb[col + 1];
                acc[mt][nt][0] += b0; acc[mt][nt][1] += b1;
                acc[mt][nt][2] += b0; acc[mt][nt][3] += b1;
                #pragma unroll
                for (int q = 0; q < 4; q++) {
                    float v = acc[mt][nt][q];
                    acc[mt][nt][q] = (v > 0.f) ? v : expm1f(v);
                }
            }
        float rm[8];
        #pragma unroll
        for (int ri = 0; ri < 8; ri++) {
            int mt = ri >> 1, h2 = ri & 1;
            float m = -FLT_MAX;
            #pragma unroll
            for (int nt = 0; nt < 4; nt++)
                m = fmaxf(m, fmaxf(acc[mt][nt][h2 * 2], acc[mt][nt][h2 * 2 + 1]));
            rm[ri] = m;
        }
        #pragma unroll
        for (int ri = 0; ri < 8; ri++) {
            rm[ri] = fmaxf(rm[ri], __shfl_xor_sync(0xffffffffu, rm[ri], 1));
            rm[ri] = fmaxf(rm[ri], __shfl_xor_sync(0xffffffffu, rm[ri], 2));
        }
        if (ct == 0)
            #pragma unroll
            for (int ri = 0; ri < 8; ri++)
                sm->red1[wn][wm * 64 + (ri >> 1) * 16 + gr + (ri & 1) * 8] = rm[ri];
        __syncthreads();
        if (tid < 128)
            sm->srow[tid] = fmaxf(fmaxf(sm->red1[0][tid], sm->red1[1][tid]),
                                  fmaxf(sm->red1[2][tid], sm->red1[3][tid]));
        __syncthreads();
        float se[8];
        #pragma unroll
        for (int ri = 0; ri < 8; ri++) {
            int mt = ri >> 1, h2 = ri & 1;
            int rl = wm * 64 + mt * 16 + gr + h2 * 8;
            float m = sm->srow[rl];
            float s = 0.f;
            #pragma unroll
            for (int nt = 0; nt < 4; nt++)
                s += expf(acc[mt][nt][h2 * 2] - m) + expf(acc[mt][nt][h2 * 2 + 1] - m);
            se[ri] = s;
        }
        #pragma unroll
        for (int ri = 0; ri < 8; ri++) {
            se[ri] += __shfl_xor_sync(0xffffffffu, se[ri], 1);
            se[ri] += __shfl_xor_sync(0xffffffffu, se[ri], 2);
        }
        __syncthreads();
        if (ct == 0)
            #pragma unroll
            for (int ri = 0; ri < 8; ri++)
                sm->red1[wn][wm * 64 + (ri >> 1) * 16 + gr + (ri & 1) * 8] = se[ri];
        __syncthreads();
        if (tid < 128)
            sm->srow[tid] += logf(sm->red1[0][tid] + sm->red1[1][tid] +
                                  sm->red1[2][tid] + sm->red1[3][tid]);
        __syncthreads();
        #pragma unroll
        for (int mt = 0; mt < 4; mt++) {
            #pragma unroll
            for (int nt = 0; nt < 4; nt++) {
                int col = wn * 32 + nt * 8 + ct * 2;
                int rl0 = wm * 64 + mt * 16 + gr;
                float l0 = sm->srow[rl0], l1 = sm->srow[rl0 + 8];
                *(float2*)(Cb + (size_t)(bm + rl0) * ldc + col) =
                    make_float2(acc[mt][nt][0] - l0, acc[mt][nt][1] - l0);
                *(float2*)(Cb + (size_t)(bm + rl0 + 8) * ldc + col) =
                    make_float2(acc[mt][nt][2] - l1, acc[mt][nt][3] - l1);
            }
        }
    }
}

// ---------------- mega GEMM: dist (0..255) + Wh/f12 (256..447) + rec (448..639) ----------------
__global__ __launch_bounds__(256, 2) void mega_gemm(
    float* __restrict__ rec, const float* __restrict__ gat_a,
    const float* __restrict__ enc_b)
{
    __shared__ BmmaSmem sm;
    int b = blockIdx.x;
    if (b < 256) {
        bmma_tile<3>(&sm, g_lat_h, g_lat_l, g_lat_h, g_lat_l,
                     g_dist, g_sq, nullptr,
                     0, (b >> 4) * 128, (b & 15) * 128, Dd, Dd, Dd, Nn);
    } else if (b < 448) {
        int t = b - 256; int z = t >> 4; int bm = (t & 15) * 128;
        bmma_tile<4>(&sm, g_lat_h, g_lat_l,
                     g_gwT_h + (size_t)z * Dd * Dd, g_gwT_l + (size_t)z * Dd * Dd,
                     g_Wh + (size_t)z * Nn * Dd, nullptr, gat_a + (size_t)z * 2 * Dd,
                     z, bm, 0, Dd, Dd, Dd, Dd);
    } else {
        int t = b - 448; int z = t >> 6; int r = t & 63;
        bmma_tile<1>(&sm, g_lat_h, g_lat_l,
                     g_encT_h + (size_t)z * VDd * Dd, g_encT_l + (size_t)z * VDd * Dd,
                     rec + (size_t)z * Nn * VDd, nullptr, enc_b + (size_t)z * VDd,
                     z, (r >> 2) * 128, (r & 3) * 128, Dd, Dd, Dd, VDd);
    }
}

// ---------------- agg partials (split-K) ----------------
__global__ __launch_bounds__(256, 2) void agg_gemm() {
    __shared__ BmmaSmem sm;
    int z = blockIdx.z;
    bmma_tile<0>(&sm,
                 g_meta_h + (size_t)z * AGG_KCHUNK, g_meta_l + (size_t)z * AGG_KCHUNK,
                 g_aggT_h + (size_t)z * AGG_KCHUNK, g_aggT_l + (size_t)z * AGG_KCHUNK,
                 g_part + (size_t)z * Nn * Dd, nullptr, nullptr,
                 z, blockIdx.y * 128, 0, AGG_KCHUNK, VH * Dd, VH * Dd, Dd);
}

// ---------------- cls + elu + log_softmax (final output) ----------------
__global__ __launch_bounds__(256) void cls_gemm(float* __restrict__ outp,
                                                const float* __restrict__ cls_b) {
    __shared__ BmmaSmem sm;
    bmma_tile<5>(&sm, g_sem_h, g_sem_l, g_clsT_h, g_clsT_l,
                 outp, nullptr, cls_b,
                 0, blockIdx.y * 128, 0, Dd, Dd, Dd, Dd);
}

// ---------------- per-row top-K: 4 warps per row, float4 loads, + merge ----------------
__global__ __launch_bounds__(256) void knn_kernel() {
    __shared__ float sval[8][Kk];
    __shared__ int   sidx[8][Kk];
    int tid = threadIdx.x;
    int wid = tid >> 5, lane = tid & 31;
    int row = blockIdx.x * 2 + (wid >> 2);
    int quarter = wid & 3;
    const float* dr = g_dist + (size_t)row * Nn + quarter * 512;

    float4 v4[4];
    #pragma unroll
    for (int t = 0; t < 4; t++)
        v4[t] = *(const float4*)(dr + t * 128 + lane * 4);

    float val[Kk];
    int   idx[Kk];
    #pragma unroll
    for (int p = 0; p < Kk; p++) { val[p] = FLT_MAX; idx[p] = 0x7fffffff; }

    #pragma unroll
    for (int t = 0; t < 4; t++) {
        float c[4] = {v4[t].x, v4[t].y, v4[t].z, v4[t].w};
        #pragma unroll
        for (int q = 0; q < 4; q++) {
            float d = c[q];
            if (d < val[Kk - 1]) {
                int gj = quarter * 512 + t * 128 + lane * 4 + q;
                #pragma unroll
                for (int p = Kk - 1; p >= 1; p--) {
                    if (d < val[p]) {
                        bool sh = d < val[p - 1];
                        val[p] = sh ? val[p - 1] : d;
                        idx[p] = sh ? idx[p - 1] : gj;
                    }
                }
                if (d < val[0]) { val[0] = d; idx[0] = gj; }
            }
        }
    }

    #pragma unroll 1
    for (int r = 0; r < Kk; r++) {
        float bv = val[0]; int bi = idx[0];
        #pragma unroll
        for (int o = 16; o; o >>= 1) {
            float ov = __shfl_xor_sync(0xffffffffu, bv, o);
            int   oi = __shfl_xor_sync(0xffffffffu, bi, o);
            if (ov < bv || (ov == bv && oi < bi)) { bv = ov; bi = oi; }
        }
        if (lane == 0) { sval[wid][r] = bv; sidx[wid][r] = bi; }
        if (val[0] == bv && idx[0] == bi) {
            #pragma unroll
            for (int p = 0; p < Kk - 1; p++) { val[p] = val[p + 1]; idx[p] = idx[p + 1]; }
            val[Kk - 1] = FLT_MAX; idx[Kk - 1] = 0x7fffffff;
        }
    }
    __syncthreads();

    if ((wid & 3) == 0) {
        int wbase = wid;
        float a = FLT_MAX; int ai = 0x7fffffff;
        float b = FLT_MAX; int bi = 0x7fffffff;
        if (lane < 40) { a = sval[wbase + lane / Kk][lane % Kk]; ai = sidx[wbase + lane / Kk][lane % Kk]; }
        int l2 = lane + 32;
        if (l2 < 40) { b = sval[wbase + l2 / Kk][l2 % Kk]; bi = sidx[wbase + l2 / Kk][l2 % Kk]; }
        #pragma unroll 1
        for (int r = 0; r < Kk; r++) {
            bool useB = (b < a) || (b == a && bi < ai);
            float cv = useB ? b : a;
            int   ci = useB ? bi : ai;
            float mv = cv; int mi = ci;
            #pragma unroll
            for (int o = 16; o; o >>= 1) {
                float ov = __shfl_xor_sync(0xffffffffu, mv, o);
                int   oi = __shfl_xor_sync(0xffffffffu, mi, o);
                if (ov < mv || (ov == mv && oi < mi)) { mv = ov; mi = oi; }
            }
            if (lane == 0) g_knn[row * Kk + r] = mi;
            if (cv == mv && ci == mi) {
                if (useB) { b = FLT_MAX; bi = 0x7fffffff; }
                else      { a = FLT_MAX; ai = 0x7fffffff; }
            }
        }
    }
}

// ---------------- sparse GAT attention -> split bf16 meta ----------------
__global__ void attn_kernel(const float* __restrict__ fm) {
    int w = (blockIdx.x * blockDim.x + threadIdx.x) >> 5;
    int lane = threadIdx.x & 31;
    if (w >= VH * Nn) return;
    int i = w % Nn;
    int vh = w / Nn;
    int v = vh / Hh;

    int nb = -1;
    bool valid = false;
    if (lane < Kk) {
        nb = g_knn[i * Kk + lane];
        valid = (nb == i) || (fm[(size_t)i * Vv + v] > 0.f && fm[(size_t)nb * Vv + v] > 0.f);
    }
    unsigned hasSelf = __ballot_sync(0xffffffffu, lane < Kk && nb == i);
    if (hasSelf == 0 && lane == Kk) { nb = i; valid = true; }

    float e = -FLT_MAX;
    if (valid) {
        float x = g_f1[vh * Nn + i] + g_f2[vh * Nn + nb];
        e = (x >= 0.f) ? x : LRELU_ALPHA * x;
    }
    float m = e;
    #pragma unroll
    for (int o = 16; o; o >>= 1) m = fmaxf(m, __shfl_xor_sync(0xffffffffu, m, o));
    float wt = valid ? expf(e - m) : 0.f;
    float s = wt;
    #pragma unroll
    for (int o = 16; o; o >>= 1) s += __shfl_xor_sync(0xffffffffu, s, o);
    float att = wt / s;

    const float* base = g_Wh + (size_t)vh * Nn * Dd;
    float acc[4] = {0.f, 0.f, 0.f, 0.f};
    #pragma unroll
    for (int j = 0; j <= Kk; j++) {
        float a = __shfl_sync(0xffffffffu, att, j);
        int nj = __shfl_sync(0xffffffffu, nb, j);
        if (a != 0.f) {
            float4 wv = *(const float4*)(base + (size_t)nj * Dd + lane * 4);
            acc[0] = fmaf(a, wv.x, acc[0]);
            acc[1] = fmaf(a, wv.y, acc[1]);
            acc[2] = fmaf(a, wv.z, acc[2]);
            acc[3] = fmaf(a, wv.w, acc[3]);
        }
    }
    union { __nv_bfloat16 b[4]; uint2 u; } H, L;
    #pragma unroll
    for (int q = 0; q < 4; q++) {
        H.b[q] = __float2bfloat16(acc[q]);
        L.b[q] = __float2bfloat16(acc[q] - __bfloat162float(H.b[q]));
    }
    size_t dst = (size_t)i * (VH * Dd) + (size_t)vh * Dd + lane * 4;
    *(uint2*)(g_meta_h + dst) = H.u;
    *(uint2*)(g_meta_l + dst) = L.u;
}

// ---------------- split-K reduce for agg + bias -> sem fp32 + bf16 split ----------------
__global__ void agg_reduce_kernel(const float* __restrict__ bias, float* __restrict__ sem) {
    int i = blockIdx.x * blockDim.x + threadIdx.x;
    if (i >= Nn * Dd) return;
    float s = 0.f;
    #pragma unroll
    for (int p = 0; p < AGG_SPLITS; p++) s += g_part[(size_t)p * Nn * Dd + i];
    s += bias[i & (Dd - 1)];
    sem[i] = s;
    __nv_bfloat16 h = __float2bfloat16(s);
    g_sem_h[i] = h;
    g_sem_l[i] = __float2bfloat16(s - __bfloat162float(h));
}

// ---------------- launch ----------------
extern "C" void kernel_launch(void* const* d_in, const int* in_sizes, int n_in,
                              void* d_out, int out_size) {
    const float* fm     = (const float*)d_in[0];
    const float* latent = (const float*)d_in[1];
    const float* enc_W  = (const float*)d_in[2];
    const float* enc_b  = (const float*)d_in[3];
    const float* gat_W  = (const float*)d_in[4];
    const float* gat_a  = (const float*)d_in[5];
    const float* agg_W  = (const float*)d_in[6];
    const float* agg_b  = (const float*)d_in[7];
    const float* cls_W  = (const float*)d_in[8];
    const float* cls_b  = (const float*)d_in[9];

    float* out  = (float*)d_out;
    float* rec  = out;                                   // [V,N,VD]
    float* outp = out + (size_t)Vv * Nn * VDd;           // [N,D]
    float* sem  = outp + (size_t)Nn * Dd;                // [N,D]

    // 1. prep: weight transposes+splits + latent split/sq
    prep_all<<<848, 256>>>(gat_W, enc_W, agg_W, cls_W, latent);
    // 2. mega GEMM: dist + Wh/f12 + rec (all independent given prep)
    mega_gemm<<<640, 256>>>(rec, gat_a, enc_b);
    // 3. top-K neighbors per row
    knn_kernel<<<Nn / 2, 256>>>();
    // 4. sparse attention -> split bf16 meta
    attn_kernel<<<VH * Nn / 8, 256>>>(fm);
    // 5. semantic partials = meta @ agg_W (split-K)
    agg_gemm<<<dim3(1, Nn / 128, AGG_SPLITS), 256>>>();
    // 6. reduce partials + bias -> semantic (fp32 out + bf16 split)
    agg_reduce_kernel<<<(Nn * Dd) / 256, 256>>>(agg_b, sem);
    // 7. output = log_softmax(elu(sem @ cls_W + cls_b))
    cls_gemm<<<dim3(1, Nn / 128, 1), 256>>>(outp, cls_b);
}

// round 10
// speedup vs baseline: 2.4692x; 1.0026x over previous
#include <cuda_runtime.h>
#include <cuda_bf16.h>
#include <cstdint>
#include <math.h>
#include <float.h>

#define Nn 2048
#define Dd 128
#define Vv 3
#define Hh 4
#define VDd 512
#define Kk 10
#define VH (Vv*Hh)
#define LRELU_ALPHA 0.2f
#define AGG_SPLITS 8
#define AGG_KCHUNK ((VH*Dd)/AGG_SPLITS)   // 192

// ---------------- scratch (no allocations allowed) ----------------
__device__ float g_sq[Nn];
__device__ float g_dist[(size_t)Nn * Nn];
__device__ int   g_knn[Nn * Kk];
__device__ float g_Wh[(size_t)VH * Nn * Dd];
__device__ float g_f1[VH * Nn];
__device__ float g_f2[VH * Nn];
__device__ float g_part[(size_t)AGG_SPLITS * Nn * Dd];

// bf16 split operands
__device__ __nv_bfloat16 g_lat_h[Nn * Dd],  g_lat_l[Nn * Dd];
__device__ __nv_bfloat16 g_gwT_h[VH * Dd * Dd], g_gwT_l[VH * Dd * Dd];
__device__ __nv_bfloat16 g_encT_h[Vv * VDd * Dd], g_encT_l[Vv * VDd * Dd];
__device__ __nv_bfloat16 g_aggT_h[Dd * VH * Dd], g_aggT_l[Dd * VH * Dd];
__device__ __nv_bfloat16 g_clsT_h[Dd * Dd], g_clsT_l[Dd * Dd];
__device__ __nv_bfloat16 g_meta_h[(size_t)Nn * VH * Dd], g_meta_l[(size_t)Nn * VH * Dd];
__device__ __nv_bfloat16 g_sem_h[Nn * Dd], g_sem_l[Nn * Dd];

// ---------------- coalesced transpose + split (32x32 tiles) ----------------
__device__ __forceinline__ void trans_tile(
    const float* __restrict__ src, int R, int C,
    __nv_bfloat16* __restrict__ dh, __nv_bfloat16* __restrict__ dl,
    int tr, int tc, int tid)
{
    __shared__ float tile[32][33];
    int tx = tid & 31, ty = tid >> 5;
    int r0 = tr * 32, c0 = tc * 32;
    #pragma unroll
    for (int p = 0; p < 4; p++)
        tile[ty + p * 8][tx] = src[(size_t)(r0 + ty + p * 8) * C + c0 + tx];
    __syncthreads();
    #pragma unroll
    for (int p = 0; p < 4; p++) {
        int j = ty + p * 8;
        float x = tile[tx][j];
        __nv_bfloat16 h = __float2bfloat16(x);
        size_t o = (size_t)(c0 + j) * R + r0 + tx;
        dh[o] = h;
        dl[o] = __float2bfloat16(x - __bfloat162float(h));
    }
}

// combined prep: weights (blocks 0..591) + latent split/sq (blocks 592..847)
__global__ __launch_bounds__(256) void prep_all(
    const float* __restrict__ gw, const float* __restrict__ ew,
    const float* __restrict__ aw, const float* __restrict__ cw,
    const float* __restrict__ lat)
{
    int b = blockIdx.x, tid = threadIdx.x;
    if (b < 192) {
        int z = b >> 4, t = b & 15;
        trans_tile(gw + (size_t)z * Dd * Dd, Dd, Dd,
                   g_gwT_h + (size_t)z * Dd * Dd, g_gwT_l + (size_t)z * Dd * Dd,
                   t >> 2, t & 3, tid);
    } else if (b < 384) {
        int bb = b - 192; int z = bb >> 6, t = bb & 63;
        trans_tile(ew + (size_t)z * Dd * VDd, Dd, VDd,
                   g_encT_h + (size_t)z * VDd * Dd, g_encT_l + (size_t)z * VDd * Dd,
                   t >> 4, t & 15, tid);
    } else if (b < 576) {
        int t = b - 384;
        trans_tile(aw, VH * Dd, Dd, g_aggT_h, g_aggT_l, t >> 2, t & 3, tid);
    } else if (b < 592) {
        int t = b - 576;
        trans_tile(cw, Dd, Dd, g_clsT_h, g_clsT_l, t >> 2, t & 3, tid);
    } else {
        int w = (b - 592) * 8 + (tid >> 5);
        int lane = tid & 31;
        float4 r = *(const float4*)(lat + (size_t)w * Dd + lane * 4);
        union { __nv_bfloat16 bb[4]; uint2 u; } H, L;
        float c[4] = {r.x, r.y, r.z, r.w};
        #pragma unroll
        for (int q = 0; q < 4; q++) {
            H.bb[q] = __float2bfloat16(c[q]);
            L.bb[q] = __float2bfloat16(c[q] - __bfloat162float(H.bb[q]));
        }
        *(uint2*)(g_lat_h + (size_t)w * Dd + lane * 4) = H.u;
        *(uint2*)(g_lat_l + (size_t)w * Dd + lane * 4) = L.u;
        float s = c[0]*c[0] + c[1]*c[1] + c[2]*c[2] + c[3]*c[3];
        #pragma unroll
        for (int o = 16; o; o >>= 1) s += __shfl_xor_sync(0xffffffffu, s, o);
        if (lane == 0) g_sq[w] = s;
    }
}

#define MMA_BF16(c, a0, a1, a2, a3, b0, b1) \
    asm volatile("mma.sync.aligned.m16n8k16.row.col.f32.bf16.bf16.f32 " \
                 "{%0,%1,%2,%3}, {%4,%5,%6,%7}, {%8,%9}, {%0,%1,%2,%3};" \
                 : "+f"((c)[0]), "+f"((c)[1]), "+f"((c)[2]), "+f"((c)[3]) \
                 : "r"(a0), "r"(a1), "r"(a2), "r"(a3), "r"(b0), "r"(b1))

struct BmmaSmem {
    __nv_bfloat16 Ash[128][40];
    __nv_bfloat16 Asl[128][40];
    __nv_bfloat16 Bsh[128][40];
    __nv_bfloat16 Bsl[128][40];
    float red1[4][128];
    float red2[4][128];
    float srow[128];
};

// =====================================================================
// bf16 split-compensated tensor-core GEMM tile (device fn).
// MODE: 0 plain, 1 +bias[col], 3 dist epilogue,
//       4 plain + fused f1/f2 row-dots (biasb = gat_a[z], bn==0),
//       5 +biasb, elu, row log_softmax fused (bn==0, writes final output)
// =====================================================================
template <int MODE>
__device__ __forceinline__ void bmma_tile(
    BmmaSmem* sm,
    const __nv_bfloat16* __restrict__ Ahb, const __nv_bfloat16* __restrict__ Alb,
    const __nv_bfloat16* __restrict__ Bhb, const __nv_bfloat16* __restrict__ Blb,
    float* __restrict__ Cb, const float* __restrict__ bias,
    const float* __restrict__ biasb,
    int z, int bm, int bn, int Kdim, int lda, int ldb, int ldc)
{
    const int tid = threadIdx.x;
    const int wid = tid >> 5, lane = tid & 31;
    const int wm = wid >> 2, wn = wid & 3;
    const int gr = lane >> 2, ct = lane & 3;
    const int r0 = tid >> 2;
    const int cv = (tid & 3) * 8;

    float acc[4][4][4];
    #pragma unroll
    for (int mt = 0; mt < 4; mt++)
        #pragma unroll
        for (int nt = 0; nt < 4; nt++)
            #pragma unroll
            for (int q = 0; q < 4; q++) acc[mt][nt][q] = 0.f;

    const int T = Kdim >> 5;
    for (int t = 0; t < T; t++) {
        const int k0 = t * 32;
        uint4 gah0 = *(const uint4*)(Ahb + (size_t)(bm + r0) * lda + k0 + cv);
        uint4 gah1 = *(const uint4*)(Ahb + (size_t)(bm + r0 + 64) * lda + k0 + cv);
        uint4 gal0 = *(const uint4*)(Alb + (size_t)(bm + r0) * lda + k0 + cv);
        uint4 gal1 = *(const uint4*)(Alb + (size_t)(bm + r0 + 64) * lda + k0 + cv);
        uint4 gbh0 = *(const uint4*)(Bhb + (size_t)(bn + r0) * ldb + k0 + cv);
        uint4 gbh1 = *(const uint4*)(Bhb + (size_t)(bn + r0 + 64) * ldb + k0 + cv);
        uint4 gbl0 = *(const uint4*)(Blb + (size_t)(bn + r0) * ldb + k0 + cv);
        uint4 gbl1 = *(const uint4*)(Blb + (size_t)(bn + r0 + 64) * ldb + k0 + cv);

        __syncthreads();
        *(uint4*)&sm->Ash[r0][cv] = gah0;  *(uint4*)&sm->Ash[r0 + 64][cv] = gah1;
        *(uint4*)&sm->Asl[r0][cv] = gal0;  *(uint4*)&sm->Asl[r0 + 64][cv] = gal1;
        *(uint4*)&sm->Bsh[r0][cv] = gbh0;  *(uint4*)&sm->Bsh[r0 + 64][cv] = gbh1;
        *(uint4*)&sm->Bsl[r0][cv] = gbl0;  *(uint4*)&sm->Bsl[r0 + 64][cv] = gbl1;
        __syncthreads();

        #pragma unroll
        for (int kk = 0; kk < 32; kk += 16) {
            uint32_t bh[4][2], bl[4][2];
            #pragma unroll
            for (int nt = 0; nt < 4; nt++) {
                int n = wn * 32 + nt * 8 + gr;
                bh[nt][0] = *(const uint32_t*)&sm->Bsh[n][kk + ct * 2];
                bh[nt][1] = *(const uint32_t*)&sm->Bsh[n][kk + ct * 2 + 8];
                bl[nt][0] = *(const uint32_t*)&sm->Bsl[n][kk + ct * 2];
                bl[nt][1] = *(const uint32_t*)&sm->Bsl[n][kk + ct * 2 + 8];
            }
            #pragma unroll
            for (int mt = 0; mt < 4; mt++) {
                int rA = wm * 64 + mt * 16 + gr;
                uint32_t ah0 = *(const uint32_t*)&sm->Ash[rA][kk + ct * 2];
                uint32_t ah1 = *(const uint32_t*)&sm->Ash[rA + 8][kk + ct * 2];
                uint32_t ah2 = *(const uint32_t*)&sm->Ash[rA][kk + ct * 2 + 8];
                uint32_t ah3 = *(const uint32_t*)&sm->Ash[rA + 8][kk + ct * 2 + 8];
                uint32_t al0 = *(const uint32_t*)&sm->Asl[rA][kk + ct * 2];
                uint32_t al1 = *(const uint32_t*)&sm->Asl[rA + 8][kk + ct * 2];
                uint32_t al2 = *(const uint32_t*)&sm->Asl[rA][kk + ct * 2 + 8];
                uint32_t al3 = *(const uint32_t*)&sm->Asl[rA + 8][kk + ct * 2 + 8];
                #pragma unroll
                for (int nt = 0; nt < 4; nt++) {
                    MMA_BF16(acc[mt][nt], ah0, ah1, ah2, ah3, bh[nt][0], bh[nt][1]);
                    MMA_BF16(acc[mt][nt], ah0, ah1, ah2, ah3, bl[nt][0], bl[nt][1]);
                    MMA_BF16(acc[mt][nt], al0, al1, al2, al3, bh[nt][0], bh[nt][1]);
                }
            }
        }
    }

    if (MODE != 5) {
        #pragma unroll
        for (int mt = 0; mt < 4; mt++) {
            int row = bm + wm * 64 + mt * 16 + gr;
            #pragma unroll
            for (int nt = 0; nt < 4; nt++) {
                int col = bn + wn * 32 + nt * 8 + ct * 2;
                float v0 = acc[mt][nt][0], v1 = acc[mt][nt][1];
                float v2 = acc[mt][nt][2], v3 = acc[mt][nt][3];
                if (MODE == 1) {
                    float b0 = biasb[col], b1 = biasb[col + 1];
                    v0 += b0; v1 += b1; v2 += b0; v3 += b1;
                } else if (MODE == 3) {
                    float sr0 = bias[row], sr1 = bias[row + 8];
                    float sc0 = bias[col], sc1 = bias[col + 1];
                    v0 = sr0 + sc0 - 2.f * v0;
                    v1 = sr0 + sc1 - 2.f * v1;
                    v2 = sr1 + sc0 - 2.f * v2;
                    v3 = sr1 + sc1 - 2.f * v3;
                }
                *(float2*)(Cb + (size_t)row * ldc + col) = make_float2(v0, v1);
                *(float2*)(Cb + (size_t)(row + 8) * ldc + col) = make_float2(v2, v3);
            }
        }
    }

    if (MODE == 4) {
        float a1c[4][2], a2c[4][2];
        #pragma unroll
        for (int nt = 0; nt < 4; nt++) {
            int col = wn * 32 + nt * 8 + ct * 2;
            a1c[nt][0] = biasb[col];      a1c[nt][1] = biasb[col + 1];
            a2c[nt][0] = biasb[Dd + col]; a2c[nt][1] = biasb[Dd + col + 1];
        }
        float p1[8], p2[8];
        #pragma unroll
        for (int ri = 0; ri < 8; ri++) {
            int mt = ri >> 1, h2 = ri & 1;
            float s1 = 0.f, s2 = 0.f;
            #pragma unroll
            for (int nt = 0; nt < 4; nt++) {
                float v0 = acc[mt][nt][h2 * 2 + 0], v1 = acc[mt][nt][h2 * 2 + 1];
                s1 += v0 * a1c[nt][0] + v1 * a1c[nt][1];
                s2 += v0 * a2c[nt][0] + v1 * a2c[nt][1];
            }
            p1[ri] = s1; p2[ri] = s2;
        }
        #pragma unroll
        for (int ri = 0; ri < 8; ri++) {
            p1[ri] += __shfl_xor_sync(0xffffffffu, p1[ri], 1);
            p1[ri] += __shfl_xor_sync(0xffffffffu, p1[ri], 2);
            p2[ri] += __shfl_xor_sync(0xffffffffu, p2[ri], 1);
            p2[ri] += __shfl_xor_sync(0xffffffffu, p2[ri], 2);
        }
        if (ct == 0) {
            #pragma unroll
            for (int ri = 0; ri < 8; ri++) {
                int rl = wm * 64 + (ri >> 1) * 16 + gr + (ri & 1) * 8;
                sm->red1[wn][rl] = p1[ri];
                sm->red2[wn][rl] = p2[ri];
            }
        }
        __syncthreads();
        if (tid < 128) {
            float f1 = sm->red1[0][tid] + sm->red1[1][tid] + sm->red1[2][tid] + sm->red1[3][tid];
            float f2 = sm->red2[0][tid] + sm->red2[1][tid] + sm->red2[2][tid] + sm->red2[3][tid];
            g_f1[(size_t)z * Nn + bm + tid] = f1;
            g_f2[(size_t)z * Nn + bm + tid] = f2;
        }
    }

    if (MODE == 5) {
        #pragma unroll
        for (int mt = 0; mt < 4; mt++)
            #pragma unroll
            for (int nt = 0; nt < 4; nt++) {
                int col = wn * 32 + nt * 8 + ct * 2;
                float b0 = biasb[col], b1 = biasb[col + 1];
                acc[mt][nt][0] += b0; acc[mt][nt][1] += b1;
                acc[mt][nt][2] += b0; acc[mt][nt][3] += b1;
                #pragma unroll
                for (int q = 0; q < 4; q++) {
                    float v = acc[mt][nt][q];
                    acc[mt][nt][q] = (v > 0.f) ? v : expm1f(v);
                }
            }
        float rm[8];
        #pragma unroll
        for (int ri = 0; ri < 8; ri++) {
            int mt = ri >> 1, h2 = ri & 1;
            float m = -FLT_MAX;
            #pragma unroll
            for (int nt = 0; nt < 4; nt++)
                m = fmaxf(m, fmaxf(acc[mt][nt][h2 * 2], acc[mt][nt][h2 * 2 + 1]));
            rm[ri] = m;
        }
        #pragma unroll
        for (int ri = 0; ri < 8; ri++) {
            rm[ri] = fmaxf(rm[ri], __shfl_xor_sync(0xffffffffu, rm[ri], 1));
            rm[ri] = fmaxf(rm[ri], __shfl_xor_sync(0xffffffffu, rm[ri], 2));
        }
        if (ct == 0)
            #pragma unroll
            for (int ri = 0; ri < 8; ri++)
                sm->red1[wn][wm * 64 + (ri >> 1) * 16 + gr + (ri & 1) * 8] = rm[ri];
        __syncthreads();
        if (tid < 128)
            sm->srow[tid] = fmaxf(fmaxf(sm->red1[0][tid], sm->red1[1][tid]),
                                  fmaxf(sm->red1[2][tid], sm->red1[3][tid]));
        __syncthreads();
        float se[8];
        #pragma unroll
        for (int ri = 0; ri < 8; ri++) {
            int mt = ri >> 1, h2 = ri & 1;
            int rl = wm * 64 + mt * 16 + gr + h2 * 8;
            float m = sm->srow[rl];
            float s = 0.f;
            #pragma unroll
            for (int nt = 0; nt < 4; nt++)
                s += expf(acc[mt][nt][h2 * 2] - m) + expf(acc[mt][nt][h2 * 2 + 1] - m);
            se[ri] = s;
        }
        #pragma unroll
        for (int ri = 0; ri < 8; ri++) {
            se[ri] += __shfl_xor_sync(0xffffffffu, se[ri], 1);
            se[ri] += __shfl_xor_sync(0xffffffffu, se[ri], 2);
        }
        __syncthreads();
        if (ct == 0)
            #pragma unroll
            for (int ri = 0; ri < 8; ri++)
                sm->red1[wn][wm * 64 + (ri >> 1) * 16 + gr + (ri & 1) * 8] = se[ri];
        __syncthreads();
        if (tid < 128)
            sm->srow[tid] += logf(sm->red1[0][tid] + sm->red1[1][tid] +
                                  sm->red1[2][tid] + sm->red1[3][tid]);
        __syncthreads();
        #pragma unroll
        for (int mt = 0; mt < 4; mt++) {
            #pragma unroll
            for (int nt = 0; nt < 4; nt++) {
                int col = wn * 32 + nt * 8 + ct * 2;
                int rl0 = wm * 64 + mt * 16 + gr;
                float l0 = sm->srow[rl0], l1 = sm->srow[rl0 + 8];
                *(float2*)(Cb + (size_t)(bm + rl0) * ldc + col) =
                    make_float2(acc[mt][nt][0] - l0, acc[mt][nt][1] - l0);
                *(float2*)(Cb + (size_t)(bm + rl0 + 8) * ldc + col) =
                    make_float2(acc[mt][nt][2] - l1, acc[mt][nt][3] - l1);
            }
        }
    }
}

// ---------------- mega GEMM: dist (0..255) + Wh/f12 (256..447) + rec (448..639) ----------------
__global__ __launch_bounds__(256, 2) void mega_gemm(
    float* __restrict__ rec, const float* __restrict__ gat_a,
    const float* __restrict__ enc_b)
{
    __shared__ BmmaSmem sm;
    int b = blockIdx.x;
    if (b < 256) {
        bmma_tile<3>(&sm, g_lat_h, g_lat_l, g_lat_h, g_lat_l,
                     g_dist, g_sq, nullptr,
                     0, (b >> 4) * 128, (b & 15) * 128, Dd, Dd, Dd, Nn);
    } else if (b < 448) {
        int t = b - 256; int z = t >> 4; int bm = (t & 15) * 128;
        bmma_tile<4>(&sm, g_lat_h, g_lat_l,
                     g_gwT_h + (size_t)z * Dd * Dd, g_gwT_l + (size_t)z * Dd * Dd,
                     g_Wh + (size_t)z * Nn * Dd, nullptr, gat_a + (size_t)z * 2 * Dd,
                     z, bm, 0, Dd, Dd, Dd, Dd);
    } else {
        int t = b - 448; int z = t >> 6; int r = t & 63;
        bmma_tile<1>(&sm, g_lat_h, g_lat_l,
                     g_encT_h + (size_t)z * VDd * Dd, g_encT_l + (size_t)z * VDd * Dd,
                     rec + (size_t)z * Nn * VDd, nullptr, enc_b + (size_t)z * VDd,
                     z, (r >> 2) * 128, (r & 3) * 128, Dd, Dd, Dd, VDd);
    }
}

// ---------------- agg partials (split-K) ----------------
__global__ __launch_bounds__(256, 2) void agg_gemm() {
    __shared__ BmmaSmem sm;
    int z = blockIdx.z;
    bmma_tile<0>(&sm,
                 g_meta_h + (size_t)z * AGG_KCHUNK, g_meta_l + (size_t)z * AGG_KCHUNK,
                 g_aggT_h + (size_t)z * AGG_KCHUNK, g_aggT_l + (size_t)z * AGG_KCHUNK,
                 g_part + (size_t)z * Nn * Dd, nullptr, nullptr,
                 z, blockIdx.y * 128, 0, AGG_KCHUNK, VH * Dd, VH * Dd, Dd);
}

// ---------------- cls + elu + log_softmax (final output) ----------------
__global__ __launch_bounds__(256) void cls_gemm(float* __restrict__ outp,
                                                const float* __restrict__ cls_b) {
    __shared__ BmmaSmem sm;
    bmma_tile<5>(&sm, g_sem_h, g_sem_l, g_clsT_h, g_clsT_l,
                 outp, nullptr, cls_b,
                 0, blockIdx.y * 128, 0, Dd, Dd, Dd, Dd);
}

// ---------------- per-row top-K: 4 warps per row, float4 loads, + merge ----------------
__global__ __launch_bounds__(256) void knn_kernel() {
    __shared__ float sval[8][Kk];
    __shared__ int   sidx[8][Kk];
    int tid = threadIdx.x;
    int wid = tid >> 5, lane = tid & 31;
    int row = blockIdx.x * 2 + (wid >> 2);
    int quarter = wid & 3;
    const float* dr = g_dist + (size_t)row * Nn + quarter * 512;

    float4 v4[4];
    #pragma unroll
    for (int t = 0; t < 4; t++)
        v4[t] = *(const float4*)(dr + t * 128 + lane * 4);

    float val[Kk];
    int   idx[Kk];
    #pragma unroll
    for (int p = 0; p < Kk; p++) { val[p] = FLT_MAX; idx[p] = 0x7fffffff; }

    #pragma unroll
    for (int t = 0; t < 4; t++) {
        float c[4] = {v4[t].x, v4[t].y, v4[t].z, v4[t].w};
        #pragma unroll
        for (int q = 0; q < 4; q++) {
            float d = c[q];
            if (d < val[Kk - 1]) {
                int gj = quarter * 512 + t * 128 + lane * 4 + q;
                #pragma unroll
                for (int p = Kk - 1; p >= 1; p--) {
                    if (d < val[p]) {
                        bool sh = d < val[p - 1];
                        val[p] = sh ? val[p - 1] : d;
                        idx[p] = sh ? idx[p - 1] : gj;
                    }
                }
                if (d < val[0]) { val[0] = d; idx[0] = gj; }
            }
        }
    }

    #pragma unroll 1
    for (int r = 0; r < Kk; r++) {
        float bv = val[0]; int bi = idx[0];
        #pragma unroll
        for (int o = 16; o; o >>= 1) {
            float ov = __shfl_xor_sync(0xffffffffu, bv, o);
            int   oi = __shfl_xor_sync(0xffffffffu, bi, o);
            if (ov < bv || (ov == bv && oi < bi)) { bv = ov; bi = oi; }
        }
        if (lane == 0) { sval[wid][r] = bv; sidx[wid][r] = bi; }
        if (val[0] == bv && idx[0] == bi) {
            #pragma unroll
            for (int p = 0; p < Kk - 1; p++) { val[p] = val[p + 1]; idx[p] = idx[p + 1]; }
            val[Kk - 1] = FLT_MAX; idx[Kk - 1] = 0x7fffffff;
        }
    }
    __syncthreads();

    if ((wid & 3) == 0) {
        int wbase = wid;
        float a = FLT_MAX; int ai = 0x7fffffff;
        float b = FLT_MAX; int bi = 0x7fffffff;
        if (lane < 40) { a = sval[wbase + lane / Kk][lane % Kk]; ai = sidx[wbase + lane / Kk][lane % Kk]; }
        int l2 = lane + 32;
        if (l2 < 40) { b = sval[wbase + l2 / Kk][l2 % Kk]; bi = sidx[wbase + l2 / Kk][l2 % Kk]; }
        #pragma unroll 1
        for (int r = 0; r < Kk; r++) {
            bool useB = (b < a) || (b == a && bi < ai);
            float cv = useB ? b : a;
            int   ci = useB ? bi : ai;
            float mv = cv; int mi = ci;
            #pragma unroll
            for (int o = 16; o; o >>= 1) {
                float ov = __shfl_xor_sync(0xffffffffu, mv, o);
                int   oi = __shfl_xor_sync(0xffffffffu, mi, o);
                if (ov < mv || (ov == mv && oi < mi)) { mv = ov; mi = oi; }
            }
            if (lane == 0) g_knn[row * Kk + r] = mi;
            if (cv == mv && ci == mi) {
                if (useB) { b = FLT_MAX; bi = 0x7fffffff; }
                else      { a = FLT_MAX; ai = 0x7fffffff; }
            }
        }
    }
}

// ---------------- sparse GAT attention -> split bf16 meta (MLP-11 gather) ----------------
__global__ __launch_bounds__(256) void attn_kernel(const float* __restrict__ fm) {
    int w = (blockIdx.x * blockDim.x + threadIdx.x) >> 5;
    int lane = threadIdx.x & 31;
    if (w >= VH * Nn) return;
    int i = w % Nn;
    int vh = w / Nn;
    int v = vh / Hh;

    int nb = -1;
    bool valid = false;
    if (lane < Kk) {
        nb = g_knn[i * Kk + lane];
        valid = (nb == i) || (fm[(size_t)i * Vv + v] > 0.f && fm[(size_t)nb * Vv + v] > 0.f);
    }
    unsigned hasSelf = __ballot_sync(0xffffffffu, lane < Kk && nb == i);
    if (hasSelf == 0 && lane == Kk) { nb = i; valid = true; }

    float e = -FLT_MAX;
    if (valid) {
        float x = g_f1[vh * Nn + i] + g_f2[vh * Nn + nb];
        e = (x >= 0.f) ? x : LRELU_ALPHA * x;
    }
    float m = e;
    #pragma unroll
    for (int o = 16; o; o >>= 1) m = fmaxf(m, __shfl_xor_sync(0xffffffffu, m, o));
    float wt = valid ? expf(e - m) : 0.f;
    float s = wt;
    #pragma unroll
    for (int o = 16; o; o >>= 1) s += __shfl_xor_sync(0xffffffffu, s, o);
    float att = wt / s;

    // broadcast all (att, nbr) pairs up front; zero-weight entries use safe addr i
    float av[Kk + 1];
    int   nj[Kk + 1];
    #pragma unroll
    for (int j = 0; j <= Kk; j++) {
        av[j] = __shfl_sync(0xffffffffu, att, j);
        int n = __shfl_sync(0xffffffffu, nb, j);
        nj[j] = (av[j] != 0.f) ? n : i;
    }
    // issue all 11 gathers back-to-back (MLP = 11, all L2-resident)
    const float* base = g_Wh + (size_t)vh * Nn * Dd;
    float4 wv[Kk + 1];
    #pragma unroll
    for (int j = 0; j <= Kk; j++)
        wv[j] = *(const float4*)(base + (size_t)nj[j] * Dd + lane * 4);

    float acc[4] = {0.f, 0.f, 0.f, 0.f};
    #pragma unroll
    for (int j = 0; j <= Kk; j++) {
        acc[0] = fmaf(av[j], wv[j].x, acc[0]);
        acc[1] = fmaf(av[j], wv[j].y, acc[1]);
        acc[2] = fmaf(av[j], wv[j].z, acc[2]);
        acc[3] = fmaf(av[j], wv[j].w, acc[3]);
    }
    union { __nv_bfloat16 b[4]; uint2 u; } H, L;
    #pragma unroll
    for (int q = 0; q < 4; q++) {
        H.b[q] = __float2bfloat16(acc[q]);
        L.b[q] = __float2bfloat16(acc[q] - __bfloat162float(H.b[q]));
    }
    size_t dst = (size_t)i * (VH * Dd) + (size_t)vh * Dd + lane * 4;
    *(uint2*)(g_meta_h + dst) = H.u;
    *(uint2*)(g_meta_l + dst) = L.u;
}

// ---------------- split-K reduce for agg + bias -> sem fp32 + bf16 split ----------------
__global__ void agg_reduce_kernel(const float* __restrict__ bias, float* __restrict__ sem) {
    int i = blockIdx.x * blockDim.x + threadIdx.x;
    if (i >= Nn * Dd) return;
    float s = 0.f;
    #pragma unroll
    for (int p = 0; p < AGG_SPLITS; p++) s += g_part[(size_t)p * Nn * Dd + i];
    s += bias[i & (Dd - 1)];
    sem[i] = s;
    __nv_bfloat16 h = __float2bfloat16(s);
    g_sem_h[i] = h;
    g_sem_l[i] = __float2bfloat16(s - __bfloat162float(h));
}

// ---------------- launch ----------------
extern "C" void kernel_launch(void* const* d_in, const int* in_sizes, int n_in,
                              void* d_out, int out_size) {
    const float* fm     = (const float*)d_in[0];
    const float* latent = (const float*)d_in[1];
    const float* enc_W  = (const float*)d_in[2];
    const float* enc_b  = (const float*)d_in[3];
    const float* gat_W  = (const float*)d_in[4];
    const float* gat_a  = (const float*)d_in[5];
    const float* agg_W  = (const float*)d_in[6];
    const float* agg_b  = (const float*)d_in[7];
    const float* cls_W  = (const float*)d_in[8];
    const float* cls_b  = (const float*)d_in[9];

    float* out  = (float*)d_out;
    float* rec  = out;                                   // [V,N,VD]
    float* outp = out + (size_t)Vv * Nn * VDd;           // [N,D]
    float* sem  = outp + (size_t)Nn * Dd;                // [N,D]

    // 1. prep: weight transposes+splits + latent split/sq
    prep_all<<<848, 256>>>(gat_W, enc_W, agg_W, cls_W, latent);
    // 2. mega GEMM: dist + Wh/f12 + rec (all independent given prep)
    mega_gemm<<<640, 256>>>(rec, gat_a, enc_b);
    // 3. top-K neighbors per row
    knn_kernel<<<Nn / 2, 256>>>();
    // 4. sparse attention -> split bf16 meta
    attn_kernel<<<VH * Nn / 8, 256>>>(fm);
    // 5. semantic partials = meta @ agg_W (split-K)
    agg_gemm<<<dim3(1, Nn / 128, AGG_SPLITS), 256>>>();
    // 6. reduce partials + bias -> semantic (fp32 out + bf16 split)
    agg_reduce_kernel<<<(Nn * Dd) / 256, 256>>>(agg_b, sem);
    // 7. output = log_softmax(elu(sem @ cls_W + cls_b))
    cls_gemm<<<dim3(1, Nn / 128, 1), 256>>>(outp, cls_b);
}

// round 11
// speedup vs baseline: 2.5084x; 1.0159x over previous
#include <cuda_runtime.h>
#include <cuda_bf16.h>
#include <cstdint>
#include <math.h>
#include <float.h>

#define Nn 2048
#define Dd 128
#define Vv 3
#define Hh 4
#define VDd 512
#define Kk 10
#define VH (Vv*Hh)
#define LRELU_ALPHA 0.2f
#define AGG_SPLITS 8
#define AGG_KCHUNK ((VH*Dd)/AGG_SPLITS)   // 192

// ---------------- scratch (no allocations allowed) ----------------
__device__ float g_sq[Nn];
__device__ float g_dist[(size_t)Nn * Nn];
__device__ int   g_knn[Nn * Kk];
__device__ float g_f1[VH * Nn];
__device__ float g_f2[VH * Nn];
__device__ float g_part[(size_t)AGG_SPLITS * Nn * Dd];
__device__ float g_W2[(size_t)VH * Dd * Dd];          // [vh*128+d][c] fp32

// bf16 split operands
__device__ __nv_bfloat16 g_lat_h[Nn * Dd],  g_lat_l[Nn * Dd];
__device__ __nv_bfloat16 g_gwT_h[VH * Dd * Dd], g_gwT_l[VH * Dd * Dd];   // [vh][e][d]
__device__ __nv_bfloat16 g_gw_h[VH * Dd * Dd],  g_gw_l[VH * Dd * Dd];    // [vh][d][e] (plain)
__device__ __nv_bfloat16 g_encT_h[Vv * VDd * Dd], g_encT_l[Vv * VDd * Dd];
__device__ __nv_bfloat16 g_aggT_h[Dd * VH * Dd], g_aggT_l[Dd * VH * Dd]; // [c][vh*D+e]
__device__ __nv_bfloat16 g_W2T_h[Dd * VH * Dd], g_W2T_l[Dd * VH * Dd];   // [c][vh*D+d]
__device__ __nv_bfloat16 g_clsT_h[Dd * Dd], g_clsT_l[Dd * Dd];
__device__ __nv_bfloat16 g_mix_h[(size_t)Nn * VH * Dd], g_mix_l[(size_t)Nn * VH * Dd];
__device__ __nv_bfloat16 g_sem_h[Nn * Dd], g_sem_l[Nn * Dd];

// ---------------- coalesced transpose + split (32x32 tiles) ----------------
__device__ __forceinline__ void trans_tile(
    const float* __restrict__ src, int R, int C,
    __nv_bfloat16* __restrict__ dh, __nv_bfloat16* __restrict__ dl,
    int tr, int tc, int tid)
{
    __shared__ float tile[32][33];
    int tx = tid & 31, ty = tid >> 5;
    int r0 = tr * 32, c0 = tc * 32;
    #pragma unroll
    for (int p = 0; p < 4; p++)
        tile[ty + p * 8][tx] = src[(size_t)(r0 + ty + p * 8) * C + c0 + tx];
    __syncthreads();
    #pragma unroll
    for (int p = 0; p < 4; p++) {
        int j = ty + p * 8;
        float x = tile[tx][j];
        __nv_bfloat16 h = __float2bfloat16(x);
        size_t o = (size_t)(c0 + j) * R + r0 + tx;
        dh[o] = h;
        dl[o] = __float2bfloat16(x - __bfloat162float(h));
    }
}

// combined prep: transposes (0..591), cls (576..591), latent (592..847),
// gat_W plain split (848..1615)
__global__ __launch_bounds__(256) void prep_all(
    const float* __restrict__ gw, const float* __restrict__ ew,
    const float* __restrict__ aw, const float* __restrict__ cw,
    const float* __restrict__ lat)
{
    int b = blockIdx.x, tid = threadIdx.x;
    if (b < 192) {
        int z = b >> 4, t = b & 15;
        trans_tile(gw + (size_t)z * Dd * Dd, Dd, Dd,
                   g_gwT_h + (size_t)z * Dd * Dd, g_gwT_l + (size_t)z * Dd * Dd,
                   t >> 2, t & 3, tid);
    } else if (b < 384) {
        int bb = b - 192; int z = bb >> 6, t = bb & 63;
        trans_tile(ew + (size_t)z * Dd * VDd, Dd, VDd,
                   g_encT_h + (size_t)z * VDd * Dd, g_encT_l + (size_t)z * VDd * Dd,
                   t >> 4, t & 15, tid);
    } else if (b < 576) {
        int t = b - 384;
        trans_tile(aw, VH * Dd, Dd, g_aggT_h, g_aggT_l, t >> 2, t & 3, tid);
    } else if (b < 592) {
        int t = b - 576;
        trans_tile(cw, Dd, Dd, g_clsT_h, g_clsT_l, t >> 2, t & 3, tid);
    } else if (b < 848) {
        int w = (b - 592) * 8 + (tid >> 5);
        int lane = tid & 31;
        float4 r = *(const float4*)(lat + (size_t)w * Dd + lane * 4);
        union { __nv_bfloat16 bb[4]; uint2 u; } H, L;
        float c[4] = {r.x, r.y, r.z, r.w};
        #pragma unroll
        for (int q = 0; q < 4; q++) {
            H.bb[q] = __float2bfloat16(c[q]);
            L.bb[q] = __float2bfloat16(c[q] - __bfloat162float(H.bb[q]));
        }
        *(uint2*)(g_lat_h + (size_t)w * Dd + lane * 4) = H.u;
        *(uint2*)(g_lat_l + (size_t)w * Dd + lane * 4) = L.u;
        float s = c[0]*c[0] + c[1]*c[1] + c[2]*c[2] + c[3]*c[3];
        #pragma unroll
        for (int o = 16; o; o >>= 1) s += __shfl_xor_sync(0xffffffffu, s, o);
        if (lane == 0) g_sq[w] = s;
    } else {
        // gat_W plain split (element-wise): VH*Dd*Dd = 768 blocks x 256
        int i = (b - 848) * 256 + tid;
        float x = gw[i];
        __nv_bfloat16 h = __float2bfloat16(x);
        g_gw_h[i] = h;
        g_gw_l[i] = __float2bfloat16(x - __bfloat162float(h));
    }
}

#define MMA_BF16(c, a0, a1, a2, a3, b0, b1) \
    asm volatile("mma.sync.aligned.m16n8k16.row.col.f32.bf16.bf16.f32 " \
                 "{%0,%1,%2,%3}, {%4,%5,%6,%7}, {%8,%9}, {%0,%1,%2,%3};" \
                 : "+f"((c)[0]), "+f"((c)[1]), "+f"((c)[2]), "+f"((c)[3]) \
                 : "r"(a0), "r"(a1), "r"(a2), "r"(a3), "r"(b0), "r"(b1))

struct BmmaSmem {
    __nv_bfloat16 Ash[128][40];
    __nv_bfloat16 Asl[128][40];
    __nv_bfloat16 Bsh[128][40];
    __nv_bfloat16 Bsl[128][40];
    float red1[4][128];
    float red2[4][128];
    float srow[128];
};

// =====================================================================
// bf16 split-compensated tensor-core GEMM tile (device fn).
// MODE: 0 plain, 1 +bias[col], 3 dist epilogue,
//       4 f1/f2 row-dots ONLY (no C store; biasb = gat_a[z], bn==0),
//       5 +biasb, elu, row log_softmax fused (bn==0, writes final output)
// =====================================================================
template <int MODE>
__device__ __forceinline__ void bmma_tile(
    BmmaSmem* sm,
    const __nv_bfloat16* __restrict__ Ahb, const __nv_bfloat16* __restrict__ Alb,
    const __nv_bfloat16* __restrict__ Bhb, const __nv_bfloat16* __restrict__ Blb,
    float* __restrict__ Cb, const float* __restrict__ bias,
    const float* __restrict__ biasb,
    int z, int bm, int bn, int Kdim, int lda, int ldb, int ldc)
{
    const int tid = threadIdx.x;
    const int wid = tid >> 5, lane = tid & 31;
    const int wm = wid >> 2, wn = wid & 3;
    const int gr = lane >> 2, ct = lane & 3;
    const int r0 = tid >> 2;
    const int cv = (tid & 3) * 8;

    float acc[4][4][4];
    #pragma unroll
    for (int mt = 0; mt < 4; mt++)
        #pragma unroll
        for (int nt = 0; nt < 4; nt++)
            #pragma unroll
            for (int q = 0; q < 4; q++) acc[mt][nt][q] = 0.f;

    const int T = Kdim >> 5;
    for (int t = 0; t < T; t++) {
        const int k0 = t * 32;
        uint4 gah0 = *(const uint4*)(Ahb + (size_t)(bm + r0) * lda + k0 + cv);
        uint4 gah1 = *(const uint4*)(Ahb + (size_t)(bm + r0 + 64) * lda + k0 + cv);
        uint4 gal0 = *(const uint4*)(Alb + (size_t)(bm + r0) * lda + k0 + cv);
        uint4 gal1 = *(const uint4*)(Alb + (size_t)(bm + r0 + 64) * lda + k0 + cv);
        uint4 gbh0 = *(const uint4*)(Bhb + (size_t)(bn + r0) * ldb + k0 + cv);
        uint4 gbh1 = *(const uint4*)(Bhb + (size_t)(bn + r0 + 64) * ldb + k0 + cv);
        uint4 gbl0 = *(const uint4*)(Blb + (size_t)(bn + r0) * ldb + k0 + cv);
        uint4 gbl1 = *(const uint4*)(Blb + (size_t)(bn + r0 + 64) * ldb + k0 + cv);

        __syncthreads();
        *(uint4*)&sm->Ash[r0][cv] = gah0;  *(uint4*)&sm->Ash[r0 + 64][cv] = gah1;
        *(uint4*)&sm->Asl[r0][cv] = gal0;  *(uint4*)&sm->Asl[r0 + 64][cv] = gal1;
        *(uint4*)&sm->Bsh[r0][cv] = gbh0;  *(uint4*)&sm->Bsh[r0 + 64][cv] = gbh1;
        *(uint4*)&sm->Bsl[r0][cv] = gbl0;  *(uint4*)&sm->Bsl[r0 + 64][cv] = gbl1;
        __syncthreads();

        #pragma unroll
        for (int kk = 0; kk < 32; kk += 16) {
            uint32_t bh[4][2], bl[4][2];
            #pragma unroll
            for (int nt = 0; nt < 4; nt++) {
                int n = wn * 32 + nt * 8 + gr;
                bh[nt][0] = *(const uint32_t*)&sm->Bsh[n][kk + ct * 2];
                bh[nt][1] = *(const uint32_t*)&sm->Bsh[n][kk + ct * 2 + 8];
                bl[nt][0] = *(const uint32_t*)&sm->Bsl[n][kk + ct * 2];
                bl[nt][1] = *(const uint32_t*)&sm->Bsl[n][kk + ct * 2 + 8];
            }
            #pragma unroll
            for (int mt = 0; mt < 4; mt++) {
                int rA = wm * 64 + mt * 16 + gr;
                uint32_t ah0 = *(const uint32_t*)&sm->Ash[rA][kk + ct * 2];
                uint32_t ah1 = *(const uint32_t*)&sm->Ash[rA + 8][kk + ct * 2];
                uint32_t ah2 = *(const uint32_t*)&sm->Ash[rA][kk + ct * 2 + 8];
                uint32_t ah3 = *(const uint32_t*)&sm->Ash[rA + 8][kk + ct * 2 + 8];
                uint32_t al0 = *(const uint32_t*)&sm->Asl[rA][kk + ct * 2];
                uint32_t al1 = *(const uint32_t*)&sm->Asl[rA + 8][kk + ct * 2];
                uint32_t al2 = *(const uint32_t*)&sm->Asl[rA][kk + ct * 2 + 8];
                uint32_t al3 = *(const uint32_t*)&sm->Asl[rA + 8][kk + ct * 2 + 8];
                #pragma unroll
                for (int nt = 0; nt < 4; nt++) {
                    MMA_BF16(acc[mt][nt], ah0, ah1, ah2, ah3, bh[nt][0], bh[nt][1]);
                    MMA_BF16(acc[mt][nt], ah0, ah1, ah2, ah3, bl[nt][0], bl[nt][1]);
                    MMA_BF16(acc[mt][nt], al0, al1, al2, al3, bh[nt][0], bh[nt][1]);
                }
            }
        }
    }

    if (MODE != 5 && MODE != 4) {
        #pragma unroll
        for (int mt = 0; mt < 4; mt++) {
            int row = bm + wm * 64 + mt * 16 + gr;
            #pragma unroll
            for (int nt = 0; nt < 4; nt++) {
                int col = bn + wn * 32 + nt * 8 + ct * 2;
                float v0 = acc[mt][nt][0], v1 = acc[mt][nt][1];
                float v2 = acc[mt][nt][2], v3 = acc[mt][nt][3];
                if (MODE == 1) {
                    float b0 = biasb[col], b1 = biasb[col + 1];
                    v0 += b0; v1 += b1; v2 += b0; v3 += b1;
                } else if (MODE == 3) {
                    float sr0 = bias[row], sr1 = bias[row + 8];
                    float sc0 = bias[col], sc1 = bias[col + 1];
                    v0 = sr0 + sc0 - 2.f * v0;
                    v1 = sr0 + sc1 - 2.f * v1;
                    v2 = sr1 + sc0 - 2.f * v2;
                    v3 = sr1 + sc1 - 2.f * v3;
                }
                *(float2*)(Cb + (size_t)row * ldc + col) = make_float2(v0, v1);
                *(float2*)(Cb + (size_t)(row + 8) * ldc + col) = make_float2(v2, v3);
            }
        }
    }

    if (MODE == 4) {
        float a1c[4][2], a2c[4][2];
        #pragma unroll
        for (int nt = 0; nt < 4; nt++) {
            int col = wn * 32 + nt * 8 + ct * 2;
            a1c[nt][0] = biasb[col];      a1c[nt][1] = biasb[col + 1];
            a2c[nt][0] = biasb[Dd + col]; a2c[nt][1] = biasb[Dd + col + 1];
        }
        float p1[8], p2[8];
        #pragma unroll
        for (int ri = 0; ri < 8; ri++) {
            int mt = ri >> 1, h2 = ri & 1;
            float s1 = 0.f, s2 = 0.f;
            #pragma unroll
            for (int nt = 0; nt < 4; nt++) {
                float v0 = acc[mt][nt][h2 * 2 + 0], v1 = acc[mt][nt][h2 * 2 + 1];
                s1 += v0 * a1c[nt][0] + v1 * a1c[nt][1];
                s2 += v0 * a2c[nt][0] + v1 * a2c[nt][1];
            }
            p1[ri] = s1; p2[ri] = s2;
        }
        #pragma unroll
        for (int ri = 0; ri < 8; ri++) {
            p1[ri] += __shfl_xor_sync(0xffffffffu, p1[ri], 1);
            p1[ri] += __shfl_xor_sync(0xffffffffu, p1[ri], 2);
            p2[ri] += __shfl_xor_sync(0xffffffffu, p2[ri], 1);
            p2[ri] += __shfl_xor_sync(0xffffffffu, p2[ri], 2);
        }
        if (ct == 0) {
            #pragma unroll
            for (int ri = 0; ri < 8; ri++) {
                int rl = wm * 64 + (ri >> 1) * 16 + gr + (ri & 1) * 8;
                sm->red1[wn][rl] = p1[ri];
                sm->red2[wn][rl] = p2[ri];
            }
        }
        __syncthreads();
        if (tid < 128) {
            float f1 = sm->red1[0][tid] + sm->red1[1][tid] + sm->red1[2][tid] + sm->red1[3][tid];
            float f2 = sm->red2[0][tid] + sm->red2[1][tid] + sm->red2[2][tid] + sm->red2[3][tid];
            g_f1[(size_t)z * Nn + bm + tid] = f1;
            g_f2[(size_t)z * Nn + bm + tid] = f2;
        }
    }

    if (MODE == 5) {
        #pragma unroll
        for (int mt = 0; mt < 4; mt++)
            #pragma unroll
            for (int nt = 0; nt < 4; nt++) {
                int col = wn * 32 + nt * 8 + ct * 2;
                float b0 = biasb[col], b1 = biasb[col + 1];
                acc[mt][nt][0] += b0; acc[mt][nt][1] += b1;
                acc[mt][nt][2] += b0; acc[mt][nt][3] += b1;
                #pragma unroll
                for (int q = 0; q < 4; q++) {
                    float v = acc[mt][nt][q];
                    acc[mt][nt][q] = (v > 0.f) ? v : expm1f(v);
                }
            }
        float rm[8];
        #pragma unroll
        for (int ri = 0; ri < 8; ri++) {
            int mt = ri >> 1, h2 = ri & 1;
            float m = -FLT_MAX;
            #pragma unroll
            for (int nt = 0; nt < 4; nt++)
                m = fmaxf(m, fmaxf(acc[mt][nt][h2 * 2], acc[mt][nt][h2 * 2 + 1]));
            rm[ri] = m;
        }
        #pragma unroll
        for (int ri = 0; ri < 8; ri++) {
            rm[ri] = fmaxf(rm[ri], __shfl_xor_sync(0xffffffffu, rm[ri], 1));
            rm[ri] = fmaxf(rm[ri], __shfl_xor_sync(0xffffffffu, rm[ri], 2));
        }
        if (ct == 0)
            #pragma unroll
            for (int ri = 0; ri < 8; ri++)
                sm->red1[wn][wm * 64 + (ri >> 1) * 16 + gr + (ri & 1) * 8] = rm[ri];
        __syncthreads();
        if (tid < 128)
            sm->srow[tid] = fmaxf(fmaxf(sm->red1[0][tid], sm->red1[1][tid]),
                                  fmaxf(sm->red1[2][tid], sm->red1[3][tid]));
        __syncthreads();
        float se[8];
        #pragma unroll
        for (int ri = 0; ri < 8; ri++) {
            int mt = ri >> 1, h2 = ri & 1;
            int rl = wm * 64 + mt * 16 + gr + h2 * 8;
            float m = sm->srow[rl];
            float s = 0.f;
            #pragma unroll
            for (int nt = 0; nt < 4; nt++)
                s += expf(acc[mt][nt][h2 * 2] - m) + expf(acc[mt][nt][h2 * 2 + 1] - m);
            se[ri] = s;
        }
        #pragma unroll
        for (int ri = 0; ri < 8; ri++) {
            se[ri] += __shfl_xor_sync(0xffffffffu, se[ri], 1);
            se[ri] += __shfl_xor_sync(0xffffffffu, se[ri], 2);
        }
        __syncthreads();
        if (ct == 0)
            #pragma unroll
            for (int ri = 0; ri < 8; ri++)
                sm->red1[wn][wm * 64 + (ri >> 1) * 16 + gr + (ri & 1) * 8] = se[ri];
        __syncthreads();
        if (tid < 128)
            sm->srow[tid] += logf(sm->red1[0][tid] + sm->red1[1][tid] +
                                  sm->red1[2][tid] + sm->red1[3][tid]);
        __syncthreads();
        #pragma unroll
        for (int mt = 0; mt < 4; mt++) {
            #pragma unroll
            for (int nt = 0; nt < 4; nt++) {
                int col = wn * 32 + nt * 8 + ct * 2;
                int rl0 = wm * 64 + mt * 16 + gr;
                float l0 = sm->srow[rl0], l1 = sm->srow[rl0 + 8];
                *(float2*)(Cb + (size_t)(bm + rl0) * ldc + col) =
                    make_float2(acc[mt][nt][0] - l0, acc[mt][nt][1] - l0);
                *(float2*)(Cb + (size_t)(bm + rl0 + 8) * ldc + col) =
                    make_float2(acc[mt][nt][2] - l1, acc[mt][nt][3] - l1);
            }
        }
    }
}

// ---- mega GEMM: dist (0..255) + f12 (256..447) + rec (448..639) + W2 (640..651) ----
__global__ __launch_bounds__(256, 2) void mega_gemm(
    float* __restrict__ rec, const float* __restrict__ gat_a,
    const float* __restrict__ enc_b)
{
    __shared__ BmmaSmem sm;
    int b = blockIdx.x;
    if (b < 256) {
        bmma_tile<3>(&sm, g_lat_h, g_lat_l, g_lat_h, g_lat_l,
                     g_dist, g_sq, nullptr,
                     0, (b >> 4) * 128, (b & 15) * 128, Dd, Dd, Dd, Nn);
    } else if (b < 448) {
        int t = b - 256; int z = t >> 4; int bm = (t & 15) * 128;
        bmma_tile<4>(&sm, g_lat_h, g_lat_l,
                     g_gwT_h + (size_t)z * Dd * Dd, g_gwT_l + (size_t)z * Dd * Dd,
                     nullptr, nullptr, gat_a + (size_t)z * 2 * Dd,
                     z, bm, 0, Dd, Dd, Dd, Dd);
    } else if (b < 640) {
        int t = b - 448; int z = t >> 6; int r = t & 63;
        bmma_tile<1>(&sm, g_lat_h, g_lat_l,
                     g_encT_h + (size_t)z * VDd * Dd, g_encT_l + (size_t)z * VDd * Dd,
                     rec + (size_t)z * Nn * VDd, nullptr, enc_b + (size_t)z * VDd,
                     z, (r >> 2) * 128, (r & 3) * 128, Dd, Dd, Dd, VDd);
    } else {
        // W2[vh] = gat_W[vh] @ agg_W_block[vh]  (A=[d][e], B=aggT[c][vh*D+e])
        int vh = b - 640;
        bmma_tile<0>(&sm,
                     g_gw_h + (size_t)vh * Dd * Dd, g_gw_l + (size_t)vh * Dd * Dd,
                     g_aggT_h + (size_t)vh * Dd, g_aggT_l + (size_t)vh * Dd,
                     g_W2 + (size_t)vh * Dd * Dd, nullptr, nullptr,
                     vh, 0, 0, Dd, Dd, VH * Dd, Dd);
    }
}

// ---------------- semantic partials = mixed @ W2 (split-K) ----------------
__global__ __launch_bounds__(256, 2) void agg_gemm() {
    __shared__ BmmaSmem sm;
    int z = blockIdx.z;
    bmma_tile<0>(&sm,
                 g_mix_h + (size_t)z * AGG_KCHUNK, g_mix_l + (size_t)z * AGG_KCHUNK,
                 g_W2T_h + (size_t)z * AGG_KCHUNK, g_W2T_l + (size_t)z * AGG_KCHUNK,
                 g_part + (size_t)z * Nn * Dd, nullptr, nullptr,
                 z, blockIdx.y * 128, 0, AGG_KCHUNK, VH * Dd, VH * Dd, Dd);
}

// ---------------- cls + elu + log_softmax (final output) ----------------
__global__ __launch_bounds__(256) void cls_gemm(float* __restrict__ outp,
                                                const float* __restrict__ cls_b) {
    __shared__ BmmaSmem sm;
    bmma_tile<5>(&sm, g_sem_h, g_sem_l, g_clsT_h, g_clsT_l,
                 outp, nullptr, cls_b,
                 0, blockIdx.y * 128, 0, Dd, Dd, Dd, Dd);
}

// ---- knn (blocks 0..1023) + W2 transpose/split (blocks 1024..1215) ----
__global__ __launch_bounds__(256) void knn_kernel() {
    if (blockIdx.x >= Nn / 2) {
        int t = blockIdx.x - Nn / 2;    // 0..191: W2 [1536][128] -> W2T [128][1536]
        trans_tile(g_W2, VH * Dd, Dd, g_W2T_h, g_W2T_l, t >> 2, t & 3, threadIdx.x);
        return;
    }
    __shared__ float sval[8][Kk];
    __shared__ int   sidx[8][Kk];
    int tid = threadIdx.x;
    int wid = tid >> 5, lane = tid & 31;
    int row = blockIdx.x * 2 + (wid >> 2);
    int quarter = wid & 3;
    const float* dr = g_dist + (size_t)row * Nn + quarter * 512;

    float4 v4[4];
    #pragma unroll
    for (int t = 0; t < 4; t++)
        v4[t] = *(const float4*)(dr + t * 128 + lane * 4);

    float val[Kk];
    int   idx[Kk];
    #pragma unroll
    for (int p = 0; p < Kk; p++) { val[p] = FLT_MAX; idx[p] = 0x7fffffff; }

    #pragma unroll
    for (int t = 0; t < 4; t++) {
        float c[4] = {v4[t].x, v4[t].y, v4[t].z, v4[t].w};
        #pragma unroll
        for (int q = 0; q < 4; q++) {
            float d = c[q];
            if (d < val[Kk - 1]) {
                int gj = quarter * 512 + t * 128 + lane * 4 + q;
                #pragma unroll
                for (int p = Kk - 1; p >= 1; p--) {
                    if (d < val[p]) {
                        bool sh = d < val[p - 1];
                        val[p] = sh ? val[p - 1] : d;
                        idx[p] = sh ? idx[p - 1] : gj;
                    }
                }
                if (d < val[0]) { val[0] = d; idx[0] = gj; }
            }
        }
    }

    #pragma unroll 1
    for (int r = 0; r < Kk; r++) {
        float bv = val[0]; int bi = idx[0];
        #pragma unroll
        for (int o = 16; o; o >>= 1) {
            float ov = __shfl_xor_sync(0xffffffffu, bv, o);
            int   oi = __shfl_xor_sync(0xffffffffu, bi, o);
            if (ov < bv || (ov == bv && oi < bi)) { bv = ov; bi = oi; }
        }
        if (lane == 0) { sval[wid][r] = bv; sidx[wid][r] = bi; }
        if (val[0] == bv && idx[0] == bi) {
            #pragma unroll
            for (int p = 0; p < Kk - 1; p++) { val[p] = val[p + 1]; idx[p] = idx[p + 1]; }
            val[Kk - 1] = FLT_MAX; idx[Kk - 1] = 0x7fffffff;
        }
    }
    __syncthreads();

    if ((wid & 3) == 0) {
        int wbase = wid;
        float a = FLT_MAX; int ai = 0x7fffffff;
        float b = FLT_MAX; int bi = 0x7fffffff;
        if (lane < 40) { a = sval[wbase + lane / Kk][lane % Kk]; ai = sidx[wbase + lane / Kk][lane % Kk]; }
        int l2 = lane + 32;
        if (l2 < 40) { b = sval[wbase + l2 / Kk][l2 % Kk]; bi = sidx[wbase + l2 / Kk][l2 % Kk]; }
        #pragma unroll 1
        for (int r = 0; r < Kk; r++) {
            bool useB = (b < a) || (b == a && bi < ai);
            float cv = useB ? b : a;
            int   ci = useB ? bi : ai;
            float mv = cv; int mi = ci;
            #pragma unroll
            for (int o = 16; o; o >>= 1) {
                float ov = __shfl_xor_sync(0xffffffffu, mv, o);
                int   oi = __shfl_xor_sync(0xffffffffu, mi, o);
                if (ov < mv || (ov == mv && oi < mi)) { mv = ov; mi = oi; }
            }
            if (lane == 0) g_knn[row * Kk + r] = mi;
            if (cv == mv && ci == mi) {
                if (useB) { b = FLT_MAX; bi = 0x7fffffff; }
                else      { a = FLT_MAX; ai = 0x7fffffff; }
            }
        }
    }
}

// ---- sparse attention over LATENT (mixed = att @ latent) -> split bf16 ----
// warp w: i = w / VH, vh = w % VH (12 consecutive warps share gather rows -> L1 hits)
__global__ __launch_bounds__(256) void attn_kernel(const float* __restrict__ fm,
                                                   const float* __restrict__ latent) {
    int w = (blockIdx.x * blockDim.x + threadIdx.x) >> 5;
    int lane = threadIdx.x & 31;
    if (w >= VH * Nn) return;
    int i = w / VH;
    int vh = w - i * VH;
    int v = vh / Hh;

    int nb = -1;
    bool valid = false;
    if (lane < Kk) {
        nb = g_knn[i * Kk + lane];
        valid = (nb == i) || (fm[(size_t)i * Vv + v] > 0.f && fm[(size_t)nb * Vv + v] > 0.f);
    }
    unsigned hasSelf = __ballot_sync(0xffffffffu, lane < Kk && nb == i);
    if (hasSelf == 0 && lane == Kk) { nb = i; valid = true; }

    float e = -FLT_MAX;
    if (valid) {
        float x = g_f1[vh * Nn + i] + g_f2[vh * Nn + nb];
        e = (x >= 0.f) ? x : LRELU_ALPHA * x;
    }
    float m = e;
    #pragma unroll
    for (int o = 16; o; o >>= 1) m = fmaxf(m, __shfl_xor_sync(0xffffffffu, m, o));
    float wt = valid ? expf(e - m) : 0.f;
    float s = wt;
    #pragma unroll
    for (int o = 16; o; o >>= 1) s += __shfl_xor_sync(0xffffffffu, s, o);
    float att = wt / s;

    float av[Kk + 1];
    int   nj[Kk + 1];
    #pragma unroll
    for (int j = 0; j <= Kk; j++) {
        av[j] = __shfl_sync(0xffffffffu, att, j);
        int n = __shfl_sync(0xffffffffu, nb, j);
        nj[j] = (av[j] != 0.f) ? n : i;
    }
    float4 wv[Kk + 1];
    #pragma unroll
    for (int j = 0; j <= Kk; j++)
        wv[j] = *(const float4*)(latent + (size_t)nj[j] * Dd + lane * 4);

    float acc[4] = {0.f, 0.f, 0.f, 0.f};
    #pragma unroll
    for (int j = 0; j <= Kk; j++) {
        acc[0] = fmaf(av[j], wv[j].x, acc[0]);
        acc[1] = fmaf(av[j], wv[j].y, acc[1]);
        acc[2] = fmaf(av[j], wv[j].z, acc[2]);
        acc[3] = fmaf(av[j], wv[j].w, acc[3]);
    }
    union { __nv_bfloat16 b[4]; uint2 u; } H, L;
    #pragma unroll
    for (int q = 0; q < 4; q++) {
        H.b[q] = __float2bfloat16(acc[q]);
        L.b[q] = __float2bfloat16(acc[q] - __bfloat162float(H.b[q]));
    }
    size_t dst = (size_t)i * (VH * Dd) + (size_t)vh * Dd + lane * 4;
    *(uint2*)(g_mix_h + dst) = H.u;
    *(uint2*)(g_mix_l + dst) = L.u;
}

// ---------------- split-K reduce for semantic + bias -> sem fp32 + bf16 split ----------------
__global__ void agg_reduce_kernel(const float* __restrict__ bias, float* __restrict__ sem) {
    int i = blockIdx.x * blockDim.x + threadIdx.x;
    if (i >= Nn * Dd) return;
    float s = 0.f;
    #pragma unroll
    for (int p = 0; p < AGG_SPLITS; p++) s += g_part[(size_t)p * Nn * Dd + i];
    s += bias[i & (Dd - 1)];
    sem[i] = s;
    __nv_bfloat16 h = __float2bfloat16(s);
    g_sem_h[i] = h;
    g_sem_l[i] = __float2bfloat16(s - __bfloat162float(h));
}

// ---------------- launch ----------------
extern "C" void kernel_launch(void* const* d_in, const int* in_sizes, int n_in,
                              void* d_out, int out_size) {
    const float* fm     = (const float*)d_in[0];
    const float* latent = (const float*)d_in[1];
    const float* enc_W  = (const float*)d_in[2];
    const float* enc_b  = (const float*)d_in[3];
    const float* gat_W  = (const float*)d_in[4];
    const float* gat_a  = (const float*)d_in[5];
    const float* agg_W  = (const float*)d_in[6];
    const float* agg_b  = (const float*)d_in[7];
    const float* cls_W  = (const float*)d_in[8];
    const float* cls_b  = (const float*)d_in[9];

    float* out  = (float*)d_out;
    float* rec  = out;                                   // [V,N,VD]
    float* outp = out + (size_t)Vv * Nn * VDd;           // [N,D]
    float* sem  = outp + (size_t)Nn * Dd;                // [N,D]

    // 1. prep: transposes/splits + latent + plain gat_W split
    prep_all<<<1616, 256>>>(gat_W, enc_W, agg_W, cls_W, latent);
    // 2. mega GEMM: dist + f12 + rec + W2 (all independent given prep)
    mega_gemm<<<652, 256>>>(rec, gat_a, enc_b);
    // 3. top-K neighbors + W2 transpose/split
    knn_kernel<<<Nn / 2 + 192, 256>>>();
    // 4. sparse attention over latent -> mixed (split bf16)
    attn_kernel<<<VH * Nn / 8, 256>>>(fm, latent);
    // 5. semantic partials = mixed @ W2 (split-K)
    agg_gemm<<<dim3(1, Nn / 128, AGG_SPLITS), 256>>>();
    // 6. reduce partials + bias -> semantic (fp32 out + bf16 split)
    agg_reduce_kernel<<<(Nn * Dd) / 256, 256>>>(agg_b, sem);
    // 7. output = log_softmax(elu(sem @ cls_W + cls_b))
    cls_gemm<<<dim3(1, Nn / 128, 1), 256>>>(outp, cls_b);
}